// round 1
// baseline (speedup 1.0000x reference)
#include <cuda_runtime.h>

// Shapes (fixed)
#define TT  4
#define SS  1024
#define DD  768
#define FFD 3072
#define TS  4096          // TT*SS
#define EPSf 1e-5f

// ---------------- scratch (device globals; no allocs allowed) ----------------
__device__ float g_tmp[TS*DD];
__device__ float g_q  [TS*DD];
__device__ float g_k  [TS*DD];
__device__ float g_v  [TS*DD];
__device__ float g_qkp[8*TT*DD];   // 8 s-chunks of partial QK sums
__device__ float g_qks[TT*DD];     // IF(QK) spikes, [T,D]
__device__ float g_go [TS*DD];
__device__ float g_h  [TS*DD];
__device__ float g_f  [TS*DD];
__device__ float g_g1 [TS*FFD];
__device__ float g_g2 [TS*DD];

// ---------------- kernel 1: IF neuron on raw input -> binary tmp -------------
__global__ void k_if_input(const float* __restrict__ x)
{
    int idx = blockIdx.x * 256 + threadIdx.x;   // s*DD + d, grid exactly covers
    float v = 0.f;
    #pragma unroll
    for (int t = 0; t < TT; t++) {
        v += x[t*SS*DD + idx];
        float sp = (v >= 1.f) ? 1.f : 0.f;
        g_tmp[t*SS*DD + idx] = sp;
        v *= (1.f - sp);
    }
}

// ---------------- SGEMM: C[4096,N] = A[4096,K] @ B[K,N] (+bias) (*mask) ------
// 128x128 block tile, BK=8, 8x8 per-thread micro tile, 256 threads.
// mask (if present) is [T,K], multiplied into A rows: t = row>>10.
template<bool HAS_BIAS, bool HAS_MASK>
__global__ void __launch_bounds__(256) k_sgemm(
    const float* __restrict__ A, const float* __restrict__ B,
    const float* __restrict__ bias, const float* __restrict__ Mk,
    float* __restrict__ C, int N, int K)
{
    __shared__ float As[8][132];
    __shared__ float Bs[8][132];
    const int tid     = threadIdx.x;
    const int rowBase = blockIdx.y * 128;
    const int colBase = blockIdx.x * 128;
    const int am  = tid >> 1;            // 0..127
    const int ak  = (tid & 1) * 4;       // 0 or 4
    const int bkr = tid >> 5;            // 0..7
    const int bn  = (tid & 31) * 4;      // 0..124
    const int ty  = tid >> 4;            // 0..15
    const int tx  = tid & 15;

    const float* Ap = A + (rowBase + am) * K + ak;
    const float* Mp = HAS_MASK ? (Mk + ((rowBase + am) >> 10) * K + ak) : (const float*)0;
    const float* Bp = B + bkr * N + colBase + bn;

    float acc[8][8];
    #pragma unroll
    for (int i = 0; i < 8; i++)
        #pragma unroll
        for (int j = 0; j < 8; j++) acc[i][j] = 0.f;

    for (int k0 = 0; k0 < K; k0 += 8) {
        float4 av = *(const float4*)(Ap + k0);
        if (HAS_MASK) {
            float4 mv = *(const float4*)(Mp + k0);
            av.x *= mv.x; av.y *= mv.y; av.z *= mv.z; av.w *= mv.w;
        }
        As[ak+0][am] = av.x; As[ak+1][am] = av.y;
        As[ak+2][am] = av.z; As[ak+3][am] = av.w;
        *(float4*)&Bs[bkr][bn] = *(const float4*)(Bp + k0 * N);
        __syncthreads();
        #pragma unroll
        for (int k = 0; k < 8; k++) {
            float a[8], b[8];
            *(float4*)&a[0] = *(const float4*)&As[k][ty*8];
            *(float4*)&a[4] = *(const float4*)&As[k][ty*8 + 4];
            *(float4*)&b[0] = *(const float4*)&Bs[k][tx*8];
            *(float4*)&b[4] = *(const float4*)&Bs[k][tx*8 + 4];
            #pragma unroll
            for (int i = 0; i < 8; i++)
                #pragma unroll
                for (int j = 0; j < 8; j++)
                    acc[i][j] += a[i] * b[j];
        }
        __syncthreads();
    }

    #pragma unroll
    for (int i = 0; i < 8; i++) {
        int row = rowBase + ty*8 + i;
        #pragma unroll
        for (int j = 0; j < 8; j += 4) {
            int col = colBase + tx*8 + j;
            float4 o;
            o.x = acc[i][j+0]; o.y = acc[i][j+1];
            o.z = acc[i][j+2]; o.w = acc[i][j+3];
            if (HAS_BIAS) {
                o.x += bias[col+0]; o.y += bias[col+1];
                o.z += bias[col+2]; o.w += bias[col+3];
            }
            *(float4*)(C + row * N + col) = o;
        }
    }
}

// ---------------- fused BatchNorm (per-s over T,DIM) + IF ---------------------
// MODE 0: o1 = IF(BN(y))                       (in-place safe)
// MODE 1: o1 = h = res + BN(y); o2 = IF(h)
// MODE 2: o1 = res + BN(y)
template<int MODE, int DIM>
__global__ void __launch_bounds__(256) k_bn_if(
    const float* __restrict__ y, const float* __restrict__ res,
    float* __restrict__ o1, float* __restrict__ o2)
{
    constexpr int CPT = DIM / 256;
    const int s   = blockIdx.x;
    const int tid = threadIdx.x;
    float vals[TT][CPT];
    float sum = 0.f, sq = 0.f;
    #pragma unroll
    for (int c = 0; c < CPT; c++) {
        int d = tid + c * 256;
        #pragma unroll
        for (int t = 0; t < TT; t++) {
            float val = y[(t*SS + s)*DIM + d];
            vals[t][c] = val;
            sum += val; sq += val * val;
        }
    }
    __shared__ float s1[256], s2[256];
    s1[tid] = sum; s2[tid] = sq;
    __syncthreads();
    for (int o = 128; o > 0; o >>= 1) {
        if (tid < o) { s1[tid] += s1[tid+o]; s2[tid] += s2[tid+o]; }
        __syncthreads();
    }
    const float invn = 1.f / (float)(TT * DIM);
    float mean = s1[0] * invn;
    float inv  = rsqrtf(s2[0] * invn - mean * mean + EPSf);
    #pragma unroll
    for (int c = 0; c < CPT; c++) {
        int d = tid + c * 256;
        float v = 0.f;
        #pragma unroll
        for (int t = 0; t < TT; t++) {
            int idx = (t*SS + s)*DIM + d;
            float nv = (vals[t][c] - mean) * inv;
            if (MODE == 0) {
                v += nv;
                float sp = (v >= 1.f) ? 1.f : 0.f;
                o1[idx] = sp;
                v *= (1.f - sp);
            } else if (MODE == 1) {
                float hh = res[idx] + nv;
                o1[idx] = hh;
                v += hh;
                float sp = (v >= 1.f) ? 1.f : 0.f;
                o2[idx] = sp;
                v *= (1.f - sp);
            } else {
                o1[idx] = res[idx] + nv;
            }
        }
    }
}

// ---------------- QK = sum_s Q*K (deterministic 2-phase), then IF over T -----
__global__ void k_qk_partial()
{
    int d = blockIdx.x * 256 + threadIdx.x;   // 3 blocks * 256 = 768
    int t = blockIdx.z;
    int chunk = blockIdx.y;                   // 8 chunks of 128 s
    int base = (t*SS + chunk*128)*DD + d;
    float acc = 0.f;
    #pragma unroll 4
    for (int i = 0; i < 128; i++)
        acc += g_q[base + i*DD] * g_k[base + i*DD];
    g_qkp[(chunk*TT + t)*DD + d] = acc;
}

__global__ void k_qk_if()
{
    int d = blockIdx.x * 256 + threadIdx.x;
    float v = 0.f;
    #pragma unroll
    for (int t = 0; t < TT; t++) {
        float s = 0.f;
        #pragma unroll
        for (int c = 0; c < 8; c++) s += g_qkp[(c*TT + t)*DD + d];
        v += s;
        float sp = (v >= 1.f) ? 1.f : 0.f;
        g_qks[t*DD + d] = sp;
        v *= (1.f - sp);
    }
}

// ---------------- launch ------------------------------------------------------
extern "C" void kernel_launch(void* const* d_in, const int* in_sizes, int n_in,
                              void* d_out, int out_size)
{
    const float* x  = (const float*)d_in[0];
    const float* wq = (const float*)d_in[1];
    const float* wk = (const float*)d_in[2];
    const float* wv = (const float*)d_in[3];
    const float* wo = (const float*)d_in[4];
    const float* w1 = (const float*)d_in[5];
    const float* b1 = (const float*)d_in[6];
    const float* w2 = (const float*)d_in[7];
    const float* b2 = (const float*)d_in[8];
    float* out = (float*)d_out;

    float *tmp, *q, *k, *v, *qks, *go, *h, *f, *g1, *g2;
    cudaGetSymbolAddress((void**)&tmp, g_tmp);
    cudaGetSymbolAddress((void**)&q,   g_q);
    cudaGetSymbolAddress((void**)&k,   g_k);
    cudaGetSymbolAddress((void**)&v,   g_v);
    cudaGetSymbolAddress((void**)&qks, g_qks);
    cudaGetSymbolAddress((void**)&go,  g_go);
    cudaGetSymbolAddress((void**)&h,   g_h);
    cudaGetSymbolAddress((void**)&f,   g_f);
    cudaGetSymbolAddress((void**)&g1,  g_g1);
    cudaGetSymbolAddress((void**)&g2,  g_g2);

    const dim3 gD(DD/128, TS/128);    // (6, 32)  N=768 GEMMs
    const dim3 gF(FFD/128, TS/128);   // (24, 32) N=3072 GEMM

    // 1) tmp = IF(x)
    k_if_input<<<SS*DD/256, 256>>>(x);
    // 2) pre-BN activations for Q, K, V
    k_sgemm<false,false><<<gD, 256>>>(tmp, wq, nullptr, nullptr, q, DD, DD);
    k_sgemm<false,false><<<gD, 256>>>(tmp, wk, nullptr, nullptr, k, DD, DD);
    k_sgemm<false,false><<<gD, 256>>>(tmp, wv, nullptr, nullptr, v, DD, DD);
    // 3) BN + IF (in-place -> spikes)
    k_bn_if<0, DD><<<SS, 256>>>(q, nullptr, q, nullptr);
    k_bn_if<0, DD><<<SS, 256>>>(k, nullptr, k, nullptr);
    k_bn_if<0, DD><<<SS, 256>>>(v, nullptr, v, nullptr);
    // 4) QK column-sums (deterministic) + talking-heads IF
    k_qk_partial<<<dim3(3, 8, 4), 256>>>();
    k_qk_if<<<3, 256>>>();
    // 5) attn GEMM with A = V * broadcast(QK spikes)
    k_sgemm<false,true><<<gD, 256>>>(v, wo, nullptr, qks, go, DD, DD);
    // 6) h = x + BN(go); f = IF(h)
    k_bn_if<1, DD><<<SS, 256>>>(go, x, h, f);
    // 7) FFN up: g1 = f @ w1 + b1
    k_sgemm<true,false><<<gF, 256>>>(f, w1, b1, nullptr, g1, FFD, DD);
    // 8) BN + IF (in-place on g1)
    k_bn_if<0, FFD><<<SS, 256>>>(g1, nullptr, g1, nullptr);
    // 9) FFN down: g2 = g1 @ w2 + b2
    k_sgemm<true,false><<<gD, 256>>>(g1, w2, b2, nullptr, g2, DD, FFD);
    // 10) out = h + BN(g2)
    k_bn_if<2, DD><<<SS, 256>>>(g2, h, out, nullptr);
}

// round 5
// speedup vs baseline: 1.3319x; 1.3319x over previous
#include <cuda_runtime.h>
#include <cuda_bf16.h>
#include <cstdint>

// Shapes (fixed)
#define TT  4
#define SS  1024
#define DD  768
#define FFD 3072
#define TS  4096          // TT*SS
#define EPSf 1e-5f
#define NSPLIT 3          // bf16 hi/mid/lo split of fp32 weights (exact to 2^-27)

// ---------------- scratch (device globals; no allocs allowed) ----------------
__device__ float g_q  [TS*DD];
__device__ float g_k  [TS*DD];
__device__ float g_v  [TS*DD];
__device__ float g_go [TS*DD];
__device__ float g_h  [TS*DD];
__device__ float g_g1 [TS*FFD];
__device__ float g_g2 [TS*DD];
__device__ float g_qkp[8*TT*DD];
__device__ float g_qks[TT*DD];
// fp32 spikes (bitwise-R1 path)
__device__ float g_qs [TS*DD];
__device__ float g_ks [TS*DD];
__device__ float g_vs [TS*DD];
// column-major fp32 A operands for SGEMM: [K][TS]
__device__ __align__(128) float g_tmpsT[DD*TS];
__device__ __align__(128) float g_vmT  [DD*TS];
// bf16 spikes for tensor FFN path
__device__ __align__(128) __nv_bfloat16 g_fs [TS*DD];
__device__ __align__(128) __nv_bfloat16 g_g1s[TS*FFD];
// bf16 split-transposed FFN weights: Wt[n, 0:K]=hi, [K:2K]=mid, [2K:3K]=lo
__device__ __align__(128) __nv_bfloat16 g_w1T[FFD*NSPLIT*DD];
__device__ __align__(128) __nv_bfloat16 g_w2T[DD*NSPLIT*FFD];

// ---------------- PTX helpers ------------------------------------------------
__device__ __forceinline__ uint32_t smem_u32(const void* p) {
    uint32_t a;
    asm("{ .reg .u64 t; cvta.to.shared.u64 t, %1; cvt.u32.u64 %0, t; }" : "=r"(a) : "l"(p));
    return a;
}
__device__ __forceinline__ void cp16(uint32_t dst, const void* src) {
    asm volatile("cp.async.cg.shared.global [%0], [%1], 16;" :: "r"(dst), "l"(src));
}
__device__ __forceinline__ void cp_commit() {
    asm volatile("cp.async.commit_group;" ::: "memory");
}
template<int N> __device__ __forceinline__ void cp_wait() {
    asm volatile("cp.async.wait_group %0;" :: "n"(N) : "memory");
}
__device__ __forceinline__ void ldm_x4(uint32_t& r0, uint32_t& r1, uint32_t& r2, uint32_t& r3,
                                       uint32_t addr) {
    asm volatile("ldmatrix.sync.aligned.m8n8.x4.shared.b16 {%0,%1,%2,%3}, [%4];"
                 : "=r"(r0), "=r"(r1), "=r"(r2), "=r"(r3) : "r"(addr));
}
__device__ __forceinline__ void mma_bf16(float* d, uint32_t a0, uint32_t a1, uint32_t a2,
                                         uint32_t a3, uint32_t b0, uint32_t b1) {
    asm volatile(
        "mma.sync.aligned.m16n8k16.row.col.f32.bf16.bf16.f32 "
        "{%0,%1,%2,%3}, {%4,%5,%6,%7}, {%8,%9}, {%0,%1,%2,%3};"
        : "+f"(d[0]), "+f"(d[1]), "+f"(d[2]), "+f"(d[3])
        : "r"(a0), "r"(a1), "r"(a2), "r"(a3), "r"(b0), "r"(b1));
}

// =============================================================================
// fp32 SGEMM, bitwise-identical accumulation to R1 (ascending-k FFMA chain).
// C[4096,N] = A[4096,K] @ W[K,N], A given column-major AT[K][4096].
// 64x128 tile, BK=16, 3-stage cp.async, 256 threads, 4x8 microtile.
// =============================================================================
#define AS_F 1152              // 16*72 floats per A stage
#define BS_F 2112              // 16*132 floats per B stage
#define STG_F (AS_F + BS_F)    // 3264 floats (13056 B) per stage

__global__ void __launch_bounds__(256, 3) k_sgemm_f32(
    const float* __restrict__ AT, const float* __restrict__ W,
    float* __restrict__ C, int N, int K)
{
    __shared__ __align__(16) float smem[3 * STG_F];   // 39168 B
    const int tid = threadIdx.x;
    const int ty = tid >> 4, tx = tid & 15;
    const int rowBase = blockIdx.y * 64;
    const int colBase = blockIdx.x * 128;
    const int NC = K >> 4;
    const uint32_t sb = smem_u32(smem);

    const int lr = tid >> 4;     // k-row 0..15
    const int lg = tid & 15;     // granule 0..15

    // prefetch helper (issued inline below)
#define PREFETCH(c) do {                                                     \
        const int st_ = (c) % 3;                                             \
        const uint32_t sa_ = sb + (st_ * STG_F + lr * 72 + lg * 4) * 4;      \
        const uint32_t sbB_ = sb + (st_ * STG_F + AS_F + lr * 132 + lg * 4) * 4; \
        const float* asrc_ = AT + (size_t)((c) * 16 + lr) * TS + rowBase + lg * 4; \
        const float* bsrc_ = W + (size_t)((c) * 16 + lr) * N + colBase + lg * 4;   \
        cp16(sa_, asrc_);                                                    \
        cp16(sbB_, bsrc_);                                                   \
        cp16(sbB_ + 256, bsrc_ + 64);                                        \
        cp_commit();                                                         \
    } while (0)

    float acc[4][8];
    #pragma unroll
    for (int i = 0; i < 4; i++)
        #pragma unroll
        for (int j = 0; j < 8; j++) acc[i][j] = 0.f;

    PREFETCH(0);
    PREFETCH(1);

    for (int c = 0; c < NC; c++) {
        cp_wait<1>();
        __syncthreads();
        if (c + 2 < NC) PREFETCH(c + 2); else cp_commit();
        const float* As = smem + (c % 3) * STG_F;
        const float* Bs = As + AS_F;
        #pragma unroll
        for (int kk = 0; kk < 16; kk++) {
            float4 av = *(const float4*)&As[kk * 72 + ty * 4];
            float4 b0 = *(const float4*)&Bs[kk * 132 + tx * 8];
            float4 b1 = *(const float4*)&Bs[kk * 132 + tx * 8 + 4];
            float a[4] = { av.x, av.y, av.z, av.w };
            float b[8] = { b0.x, b0.y, b0.z, b0.w, b1.x, b1.y, b1.z, b1.w };
            #pragma unroll
            for (int i = 0; i < 4; i++)
                #pragma unroll
                for (int j = 0; j < 8; j++)
                    acc[i][j] += a[i] * b[j];   // FFMA, ascending-k chain
        }
    }
#undef PREFETCH

    const int row0 = rowBase + ty * 4;
    const int col0 = colBase + tx * 8;
    #pragma unroll
    for (int i = 0; i < 4; i++) {
        float4 o0 = { acc[i][0], acc[i][1], acc[i][2], acc[i][3] };
        float4 o1 = { acc[i][4], acc[i][5], acc[i][6], acc[i][7] };
        *(float4*)(C + (size_t)(row0 + i) * N + col0) = o0;
        *(float4*)(C + (size_t)(row0 + i) * N + col0 + 4) = o1;
    }
}

// =============================================================================
// HMMA GEMM (tensor cores) for FFN only: C = A @ Wt^T (+bias)
// A: bf16 [4096, KA] binary spikes. Wt: bf16 [N, NSPLIT*KA] (hi|mid|lo).
// =============================================================================
#define BK      32
#define STRIDE  80
#define TILE_B  (128 * STRIDE)
#define STAGE_B (2 * TILE_B)

__global__ void __launch_bounds__(256, 2) k_mma_gemm(
    const __nv_bfloat16* __restrict__ A, const __nv_bfloat16* __restrict__ Wt,
    const float* __restrict__ bias, float* __restrict__ C, int N, int KA)
{
    __shared__ __align__(16) char smem[2 * STAGE_B];   // 40 KB
    const int tid = threadIdx.x, lane = tid & 31, wid = tid >> 5;
    const int wm = wid >> 2, wn = wid & 3;
    const int rowBase = blockIdx.y * 128, colBase = blockIdx.x * 128;
    const int NC_A = KA >> 5, NC = NC_A * NSPLIT;
    const uint32_t sb = smem_u32(smem);

    const int lr = tid >> 1;
    const int lcb = (tid & 1) * 32;
    const __nv_bfloat16* Ag = A + (size_t)(rowBase + lr) * KA + (lcb >> 1);
    const __nv_bfloat16* Bg = Wt + (size_t)(colBase + lr) * (NSPLIT * KA) + (lcb >> 1);
    const uint32_t sdA = sb + lr * STRIDE + lcb;
    const uint32_t sdB = sb + TILE_B + lr * STRIDE + lcb;

    const uint32_t aBase = sb + (wm * 64 + (lane & 15)) * STRIDE + (lane >> 4) * 16;
    const int bn_local = (lane & 7) + ((lane >> 4) & 1) * 8;
    const uint32_t bBase = sb + TILE_B + (wn * 32 + bn_local) * STRIDE + ((lane >> 3) & 1) * 16;

    float acc[4][4][4];
    #pragma unroll
    for (int i = 0; i < 4; i++)
        #pragma unroll
        for (int j = 0; j < 4; j++)
            #pragma unroll
            for (int r = 0; r < 4; r++) acc[i][j][r] = 0.f;

    #pragma unroll
    for (int c = 0; c < 2; c++) {
        const uint32_t so = c * STAGE_B;
        const __nv_bfloat16* as = Ag + (size_t)(c % NC_A) * BK;
        const __nv_bfloat16* bs = Bg + (size_t)c * BK;
        cp16(sdA + so, as);      cp16(sdA + so + 16, as + 8);
        cp16(sdB + so, bs);      cp16(sdB + so + 16, bs + 8);
        cp_commit();
    }

    for (int c = 0; c < NC; c++) {
        cp_wait<1>();
        __syncthreads();
        const uint32_t so = (c & 1) * STAGE_B;
        #pragma unroll
        for (int ks = 0; ks < 2; ks++) {
            uint32_t a[4][4], b[2][4];
            #pragma unroll
            for (int mi = 0; mi < 4; mi++)
                ldm_x4(a[mi][0], a[mi][1], a[mi][2], a[mi][3],
                       aBase + so + mi * 16 * STRIDE + ks * 32);
            #pragma unroll
            for (int nj = 0; nj < 2; nj++)
                ldm_x4(b[nj][0], b[nj][1], b[nj][2], b[nj][3],
                       bBase + so + nj * 16 * STRIDE + ks * 32);
            #pragma unroll
            for (int mi = 0; mi < 4; mi++)
                #pragma unroll
                for (int ni = 0; ni < 4; ni++)
                    mma_bf16(acc[mi][ni], a[mi][0], a[mi][1], a[mi][2], a[mi][3],
                             b[ni >> 1][(ni & 1) * 2], b[ni >> 1][(ni & 1) * 2 + 1]);
        }
        __syncthreads();
        const int cn = c + 2;
        if (cn < NC) {
            const uint32_t sn = (cn & 1) * STAGE_B;
            const __nv_bfloat16* as = Ag + (size_t)(cn % NC_A) * BK;
            const __nv_bfloat16* bs = Bg + (size_t)cn * BK;
            cp16(sdA + sn, as);      cp16(sdA + sn + 16, as + 8);
            cp16(sdB + sn, bs);      cp16(sdB + sn + 16, bs + 8);
        }
        cp_commit();
    }

    const int row0 = rowBase + wm * 64 + (lane >> 2);
    const int col0 = colBase + wn * 32 + (lane & 3) * 2;
    #pragma unroll
    for (int mi = 0; mi < 4; mi++) {
        #pragma unroll
        for (int ni = 0; ni < 4; ni++) {
            const int r = row0 + mi * 16;
            const int cc = col0 + ni * 8;
            float b0 = 0.f, b1 = 0.f;
            if (bias) { b0 = bias[cc]; b1 = bias[cc + 1]; }
            float2 v0 = { acc[mi][ni][0] + b0, acc[mi][ni][1] + b1 };
            float2 v1 = { acc[mi][ni][2] + b0, acc[mi][ni][3] + b1 };
            *(float2*)(C + (size_t)r * N + cc) = v0;
            *(float2*)(C + (size_t)(r + 8) * N + cc) = v1;
        }
    }
}

// ------------ weight prep: w[K,N] fp32 -> Wt[N,3K] bf16 (hi|mid|lo) ----------
__global__ void k_prep_w(const float* __restrict__ w, __nv_bfloat16* __restrict__ wt,
                         int K, int N)
{
    int idx = blockIdx.x * 256 + threadIdx.x;
    if (idx >= N * K) return;
    int n = idx / K, k = idx - n * K;
    float v = w[(size_t)k * N + n];
    __nv_bfloat16 hi = __float2bfloat16(v);
    float r1 = v - __bfloat162float(hi);
    __nv_bfloat16 mid = __float2bfloat16(r1);
    float r2 = r1 - __bfloat162float(mid);
    __nv_bfloat16* base = wt + (size_t)n * NSPLIT * K + k;
    base[0]     = hi;
    base[K]     = mid;
    base[2 * K] = __float2bfloat16(r2);
}

// ------- IF on input + transpose to column-major fp32 spikes (bitwise R1) ----
// grid (DD/32, SS/32), block (32, 8). Each thread: 4 (s,d) pairs.
__global__ void k_if_input_T(const float* __restrict__ x)
{
    __shared__ float sm[TT][32][33];
    const int d0 = blockIdx.x * 32, s0 = blockIdx.y * 32;
    const int tx = threadIdx.x, tyy = threadIdx.y;
    #pragma unroll
    for (int i = 0; i < 4; i++) {
        const int sl = tyy + i * 8;
        const int s = s0 + sl;
        float v = 0.f;
        #pragma unroll
        for (int t = 0; t < TT; t++) {
            v += x[(size_t)(t * SS + s) * DD + d0 + tx];
            float sp = (v >= 1.f) ? 1.f : 0.f;
            sm[t][sl][tx] = sp;
            v *= (1.f - sp);
        }
    }
    __syncthreads();
    #pragma unroll
    for (int i = 0; i < 4; i++) {
        const int d = d0 + tyy + i * 8;
        #pragma unroll
        for (int t = 0; t < TT; t++)
            g_tmpsT[(size_t)d * TS + t * SS + s0 + tx] = sm[t][tx][tyy + i * 8];
    }
}

// ---------------- fused BatchNorm (per-s over T,DIM) + IF (R1-exact) ---------
// MODE 0: ob = IF(BN(y));  MODE 1: of = h = res + BN(y), ob = IF(h);
// MODE 2: of = res + BN(y)
template<int MODE, int DIM, typename OBT>
__global__ void __launch_bounds__(256) k_bn_if(
    const float* __restrict__ y, const float* __restrict__ res,
    float* __restrict__ of, OBT* __restrict__ ob)
{
    constexpr int CPT = DIM / 256;
    const int s = blockIdx.x, tid = threadIdx.x;
    float vals[TT][CPT];
    float sum = 0.f, sq = 0.f;
    #pragma unroll
    for (int c = 0; c < CPT; c++) {
        int d = tid + c * 256;
        #pragma unroll
        for (int t = 0; t < TT; t++) {
            float val = y[(size_t)(t * SS + s) * DIM + d];
            vals[t][c] = val;
            sum += val; sq += val * val;
        }
    }
    __shared__ float s1[256], s2[256];
    s1[tid] = sum; s2[tid] = sq;
    __syncthreads();
    for (int o = 128; o > 0; o >>= 1) {
        if (tid < o) { s1[tid] += s1[tid + o]; s2[tid] += s2[tid + o]; }
        __syncthreads();
    }
    const float invn = 1.f / (float)(TT * DIM);
    float mean = s1[0] * invn;
    float inv  = rsqrtf(s2[0] * invn - mean * mean + EPSf);
    #pragma unroll
    for (int c = 0; c < CPT; c++) {
        int d = tid + c * 256;
        float v = 0.f;
        #pragma unroll
        for (int t = 0; t < TT; t++) {
            size_t idx = (size_t)(t * SS + s) * DIM + d;
            float nv = (vals[t][c] - mean) * inv;
            if (MODE == 0) {
                v += nv;
                float sp = (v >= 1.f) ? 1.f : 0.f;
                ob[idx] = (OBT)sp;
                v *= (1.f - sp);
            } else if (MODE == 1) {
                float hh = res[idx] + nv;
                of[idx] = hh;
                v += hh;
                float sp = (v >= 1.f) ? 1.f : 0.f;
                ob[idx] = (OBT)sp;
                v *= (1.f - sp);
            } else {
                of[idx] = res[idx] + nv;
            }
        }
    }
}

// ---------------- QK column-sum (deterministic 2-phase) + IF over T ----------
__global__ void k_qk_partial()
{
    int d = blockIdx.x * 256 + threadIdx.x;
    int t = blockIdx.z;
    int chunk = blockIdx.y;
    size_t base = (size_t)(t * SS + chunk * 128) * DD + d;
    float acc = 0.f;
    #pragma unroll 4
    for (int i = 0; i < 128; i++)
        acc += g_qs[base + (size_t)i * DD] * g_ks[base + (size_t)i * DD];
    g_qkp[(chunk * TT + t) * DD + d] = acc;
}

__global__ void k_qk_if()
{
    int d = blockIdx.x * 256 + threadIdx.x;
    float v = 0.f;
    #pragma unroll
    for (int t = 0; t < TT; t++) {
        float s = 0.f;
        #pragma unroll
        for (int c = 0; c < 8; c++) s += g_qkp[(c * TT + t) * DD + d];
        v += s;
        float sp = (v >= 1.f) ? 1.f : 0.f;
        g_qks[t * DD + d] = sp;
        v *= (1.f - sp);
    }
}

// -------- vm = V_spike * QK_spike, transposed to column-major fp32 -----------
// grid (DD/32, SS/32), block (32, 8)
__global__ void k_vmask_T()
{
    __shared__ float sm[TT][32][33];
    const int d0 = blockIdx.x * 32, s0 = blockIdx.y * 32;
    const int tx = threadIdx.x, tyy = threadIdx.y;
    #pragma unroll
    for (int i = 0; i < 4; i++) {
        const int sl = tyy + i * 8;
        const int s = s0 + sl;
        #pragma unroll
        for (int t = 0; t < TT; t++) {
            float m = g_qks[t * DD + d0 + tx];
            sm[t][sl][tx] = g_vs[(size_t)(t * SS + s) * DD + d0 + tx] * m;
        }
    }
    __syncthreads();
    #pragma unroll
    for (int i = 0; i < 4; i++) {
        const int d = d0 + tyy + i * 8;
        #pragma unroll
        for (int t = 0; t < TT; t++)
            g_vmT[(size_t)d * TS + t * SS + s0 + tx] = sm[t][tx][tyy + i * 8];
    }
}

// ---------------- launch ------------------------------------------------------
extern "C" void kernel_launch(void* const* d_in, const int* in_sizes, int n_in,
                              void* d_out, int out_size)
{
    const float* x  = (const float*)d_in[0];
    const float* wq = (const float*)d_in[1];
    const float* wk = (const float*)d_in[2];
    const float* wv = (const float*)d_in[3];
    const float* wo = (const float*)d_in[4];
    const float* w1 = (const float*)d_in[5];
    const float* b1 = (const float*)d_in[6];
    const float* w2 = (const float*)d_in[7];
    const float* b2 = (const float*)d_in[8];
    float* out = (float*)d_out;

    float *q, *k, *v, *go, *h, *g1, *g2, *qs, *ks, *vs, *tmpsT, *vmT;
    __nv_bfloat16 *fs, *g1s, *w1T, *w2T;
    cudaGetSymbolAddress((void**)&q, g_q);       cudaGetSymbolAddress((void**)&k, g_k);
    cudaGetSymbolAddress((void**)&v, g_v);       cudaGetSymbolAddress((void**)&go, g_go);
    cudaGetSymbolAddress((void**)&h, g_h);       cudaGetSymbolAddress((void**)&g1, g_g1);
    cudaGetSymbolAddress((void**)&g2, g_g2);
    cudaGetSymbolAddress((void**)&qs, g_qs);     cudaGetSymbolAddress((void**)&ks, g_ks);
    cudaGetSymbolAddress((void**)&vs, g_vs);
    cudaGetSymbolAddress((void**)&tmpsT, g_tmpsT);
    cudaGetSymbolAddress((void**)&vmT, g_vmT);
    cudaGetSymbolAddress((void**)&fs, g_fs);     cudaGetSymbolAddress((void**)&g1s, g_g1s);
    cudaGetSymbolAddress((void**)&w1T, g_w1T);   cudaGetSymbolAddress((void**)&w2T, g_w2T);

    const dim3 gS(DD / 128, TS / 64);       // (6, 64) SGEMM grid
    const dim3 gUp(FFD / 128, TS / 128);    // (24, 32)
    const dim3 gDn(DD / 128, TS / 128);     // (6, 32)
    const dim3 gT(DD / 32, SS / 32);        // (24, 32) transpose grids
    const dim3 bT(32, 8);

    // 0) FFN weight prep (hi/mid/lo split + transpose)
    k_prep_w<<<(DD * FFD + 255) / 256, 256>>>(w1, w1T, DD, FFD);
    k_prep_w<<<(DD * FFD + 255) / 256, 256>>>(w2, w2T, FFD, DD);

    // 1) tmp = IF(x), column-major fp32 spikes
    k_if_input_T<<<gT, bT>>>(x);
    // 2) Q/K/V pre-BN GEMMs (bitwise-R1 fp32 chain)
    k_sgemm_f32<<<gS, 256>>>(tmpsT, wq, q, DD, DD);
    k_sgemm_f32<<<gS, 256>>>(tmpsT, wk, k, DD, DD);
    k_sgemm_f32<<<gS, 256>>>(tmpsT, wv, v, DD, DD);
    // 3) BN + IF -> fp32 spikes
    k_bn_if<0, DD, float><<<SS, 256>>>(q, nullptr, nullptr, qs);
    k_bn_if<0, DD, float><<<SS, 256>>>(k, nullptr, nullptr, ks);
    k_bn_if<0, DD, float><<<SS, 256>>>(v, nullptr, nullptr, vs);
    // 4) QK column-sums (exact integers) + talking-heads IF; masked-V transpose
    k_qk_partial<<<dim3(3, 8, 4), 256>>>();
    k_qk_if<<<3, 256>>>();
    k_vmask_T<<<gT, bT>>>();
    // 5) attn GEMM (bitwise-R1 fp32 chain)
    k_sgemm_f32<<<gS, 256>>>(vmT, wo, go, DD, DD);
    // 6) h = x + BN(go); f = IF(h) -> bf16 spikes
    k_bn_if<1, DD, __nv_bfloat16><<<SS, 256>>>(go, x, h, fs);
    // 7) FFN up (tensor cores; downstream flips are benign)
    k_mma_gemm<<<gUp, 256>>>(fs, w1T, b1, g1, FFD, DD);
    // 8) BN + IF -> bf16 spikes
    k_bn_if<0, FFD, __nv_bfloat16><<<SS, 256>>>(g1, nullptr, nullptr, g1s);
    // 9) FFN down (tensor cores; no downstream IF at all)
    k_mma_gemm<<<gDn, 256>>>(g1s, w2T, b2, g2, DD, FFD);
    // 10) out = h + BN(g2)
    k_bn_if<2, DD, float><<<SS, 256>>>(g2, h, out, nullptr);
}

// round 6
// speedup vs baseline: 1.6292x; 1.2232x over previous
#include <cuda_runtime.h>
#include <cuda_bf16.h>
#include <cstdint>

// Shapes (fixed)
#define TT  4
#define SS  1024
#define DD  768
#define FFD 3072
#define TS  4096          // TT*SS
#define EPSf 1e-5f

// ---------------- scratch (device globals; no allocs allowed) ----------------
__device__ float g_q  [TS*DD];
__device__ float g_k  [TS*DD];
__device__ float g_v  [TS*DD];
__device__ float g_go [TS*DD];
__device__ float g_h  [TS*DD];
__device__ float g_g1 [TS*FFD];
__device__ float g_g2 [TS*DD];
__device__ float g_qkp[8*TT*DD];
__device__ float g_qks[TT*DD];
// fp32 spikes (bitwise path)
__device__ float g_qs [TS*DD];
__device__ float g_ks [TS*DD];
__device__ float g_vs [TS*DD];
// column-major fp32 A operands for SGEMM: [K][TS]
__device__ __align__(128) float g_tmpsT[DD*TS];
__device__ __align__(128) float g_vmT  [DD*TS];
// bf16 spikes for tensor FFN path
__device__ __align__(128) __nv_bfloat16 g_fs [TS*DD];
__device__ __align__(128) __nv_bfloat16 g_g1s[TS*FFD];
// bf16 split-transposed FFN weights (hi|mid|lo planes)
__device__ __align__(128) __nv_bfloat16 g_w1T[FFD*3*DD];
__device__ __align__(128) __nv_bfloat16 g_w2T[DD*3*FFD];

// ---------------- PTX helpers ------------------------------------------------
__device__ __forceinline__ uint32_t smem_u32(const void* p) {
    uint32_t a;
    asm("{ .reg .u64 t; cvta.to.shared.u64 t, %1; cvt.u32.u64 %0, t; }" : "=r"(a) : "l"(p));
    return a;
}
__device__ __forceinline__ void cp16(uint32_t dst, const void* src) {
    asm volatile("cp.async.cg.shared.global [%0], [%1], 16;" :: "r"(dst), "l"(src));
}
__device__ __forceinline__ void cp_commit() {
    asm volatile("cp.async.commit_group;" ::: "memory");
}
template<int N> __device__ __forceinline__ void cp_wait() {
    asm volatile("cp.async.wait_group %0;" :: "n"(N) : "memory");
}
__device__ __forceinline__ void ldm_x4(uint32_t& r0, uint32_t& r1, uint32_t& r2, uint32_t& r3,
                                       uint32_t addr) {
    asm volatile("ldmatrix.sync.aligned.m8n8.x4.shared.b16 {%0,%1,%2,%3}, [%4];"
                 : "=r"(r0), "=r"(r1), "=r"(r2), "=r"(r3) : "r"(addr));
}
__device__ __forceinline__ void mma_bf16(float* d, uint32_t a0, uint32_t a1, uint32_t a2,
                                         uint32_t a3, uint32_t b0, uint32_t b1) {
    asm volatile(
        "mma.sync.aligned.m16n8k16.row.col.f32.bf16.bf16.f32 "
        "{%0,%1,%2,%3}, {%4,%5,%6,%7}, {%8,%9}, {%0,%1,%2,%3};"
        : "+f"(d[0]), "+f"(d[1]), "+f"(d[2]), "+f"(d[3])
        : "r"(a0), "r"(a1), "r"(a2), "r"(a3), "r"(b0), "r"(b1));
}
// packed fp32x2 (Blackwell base ISA); lane-wise fma.rn == scalar FFMA bitwise
__device__ __forceinline__ unsigned long long pk2(float lo, float hi) {
    unsigned long long r;
    asm("mov.b64 %0, {%1, %2};" : "=l"(r) : "f"(lo), "f"(hi));
    return r;
}
__device__ __forceinline__ void upk2(unsigned long long v, float& lo, float& hi) {
    asm("mov.b64 {%0, %1}, %2;" : "=f"(lo), "=f"(hi) : "l"(v));
}
__device__ __forceinline__ void fma2(unsigned long long& d, unsigned long long a,
                                     unsigned long long b) {
    asm("fma.rn.f32x2 %0, %1, %2, %0;" : "+l"(d) : "l"(a), "l"(b));
}

// =============================================================================
// fp32 SGEMM, bitwise ascending-k FFMA chain per output, packed f32x2 math.
// C[4096,N] = A[4096,K] @ W[K,N], A column-major AT[K][4096].
// 128x128 tile, BK=16, 3-stage cp.async, 256 threads, 8x8 microtile
// (rows {ty*4+i, 64+ty*4+i}, cols {tx*4+j, 64+tx*4+j}).
// =============================================================================
#define AS_F (16*132)          // floats per operand stage
#define STG_F (2*AS_F)         // A+B per stage
#define SGEMM_SMEM (3*STG_F*4) // 50688 B

__global__ void __launch_bounds__(256, 2) k_sgemm_f32(
    const float* __restrict__ AT, const float* __restrict__ W,
    float* __restrict__ C, int N, int K)
{
    extern __shared__ float smem[];
    const int tid = threadIdx.x;
    const int ty = tid >> 4, tx = tid & 15;
    const int rowBase = blockIdx.y * 128;
    const int colBase = blockIdx.x * 128;
    const int NC = K >> 4;
    const uint32_t sb = smem_u32(smem);
    const int kr = tid >> 4;     // k-row 0..15 (loader role)
    const int lg = tid & 15;     // 8-float granule 0..15

#define PREFETCH(c) do {                                                       \
        const int st_ = (c) % 3;                                               \
        const uint32_t sa_  = sb + (st_ * STG_F + kr * 132 + lg * 8) * 4;      \
        const uint32_t sbB_ = sb + (st_ * STG_F + AS_F + kr * 132 + lg * 8) * 4; \
        const float* as_ = AT + (size_t)((c) * 16 + kr) * TS + rowBase + lg * 8; \
        const float* bs_ = W + (size_t)((c) * 16 + kr) * N + colBase + lg * 8;   \
        cp16(sa_, as_);        cp16(sa_ + 16, as_ + 4);                        \
        cp16(sbB_, bs_);       cp16(sbB_ + 16, bs_ + 4);                       \
        cp_commit();                                                           \
    } while (0)

    unsigned long long acc2[4][8];   // [row-pair][col]: pair=(row 2i, row 2i+1)
    #pragma unroll
    for (int i = 0; i < 4; i++)
        #pragma unroll
        for (int j = 0; j < 8; j++) acc2[i][j] = 0ull;

    PREFETCH(0);
    PREFETCH(1);

    for (int c = 0; c < NC; c++) {
        cp_wait<1>();
        __syncthreads();
        if (c + 2 < NC) PREFETCH(c + 2); else cp_commit();
        const float* As = smem + (c % 3) * STG_F;
        const float* Bs = As + AS_F;
        #pragma unroll
        for (int kk = 0; kk < 16; kk++) {
            float4 a0 = *(const float4*)&As[kk * 132 + ty * 4];
            float4 a1 = *(const float4*)&As[kk * 132 + 64 + ty * 4];
            float4 b0 = *(const float4*)&Bs[kk * 132 + tx * 4];
            float4 b1 = *(const float4*)&Bs[kk * 132 + 64 + tx * 4];
            unsigned long long ap[4] = { pk2(a0.x, a0.y), pk2(a0.z, a0.w),
                                         pk2(a1.x, a1.y), pk2(a1.z, a1.w) };
            unsigned long long bd[8] = { pk2(b0.x, b0.x), pk2(b0.y, b0.y),
                                         pk2(b0.z, b0.z), pk2(b0.w, b0.w),
                                         pk2(b1.x, b1.x), pk2(b1.y, b1.y),
                                         pk2(b1.z, b1.z), pk2(b1.w, b1.w) };
            #pragma unroll
            for (int i = 0; i < 4; i++)
                #pragma unroll
                for (int j = 0; j < 8; j++)
                    fma2(acc2[i][j], ap[i], bd[j]);
        }
    }
#undef PREFETCH

    // epilogue: unpack row pairs, write float4 per col-half
    #pragma unroll
    for (int p = 0; p < 4; p++) {
        const int rbase = rowBase + ((p >> 1) ? 64 : 0) + ty * 4 + (p & 1) * 2;
        float lo[8], hi[8];
        #pragma unroll
        for (int j = 0; j < 8; j++) upk2(acc2[p][j], lo[j], hi[j]);
        float4 l0 = { lo[0], lo[1], lo[2], lo[3] }, l1 = { lo[4], lo[5], lo[6], lo[7] };
        float4 h0 = { hi[0], hi[1], hi[2], hi[3] }, h1 = { hi[4], hi[5], hi[6], hi[7] };
        *(float4*)(C + (size_t)rbase * N + colBase + tx * 4) = l0;
        *(float4*)(C + (size_t)rbase * N + colBase + 64 + tx * 4) = l1;
        *(float4*)(C + (size_t)(rbase + 1) * N + colBase + tx * 4) = h0;
        *(float4*)(C + (size_t)(rbase + 1) * N + colBase + 64 + tx * 4) = h1;
    }
}

// =============================================================================
// HMMA GEMM (tensor cores) for FFN: C = A @ Wt^T (+bias), ns split planes
// =============================================================================
#define BK      32
#define STRIDE  80
#define TILE_B  (128 * STRIDE)
#define STAGE_B (2 * TILE_B)

__global__ void __launch_bounds__(256, 2) k_mma_gemm(
    const __nv_bfloat16* __restrict__ A, const __nv_bfloat16* __restrict__ Wt,
    const float* __restrict__ bias, float* __restrict__ C, int N, int KA, int ns)
{
    __shared__ __align__(16) char smem[2 * STAGE_B];   // 40 KB
    const int tid = threadIdx.x, lane = tid & 31, wid = tid >> 5;
    const int wm = wid >> 2, wn = wid & 3;
    const int rowBase = blockIdx.y * 128, colBase = blockIdx.x * 128;
    const int NC_A = KA >> 5, NC = NC_A * ns;
    const uint32_t sb = smem_u32(smem);

    const int lr = tid >> 1;
    const int lcb = (tid & 1) * 32;
    const __nv_bfloat16* Ag = A + (size_t)(rowBase + lr) * KA + (lcb >> 1);
    const __nv_bfloat16* Bg = Wt + (size_t)(colBase + lr) * (ns * KA) + (lcb >> 1);
    const uint32_t sdA = sb + lr * STRIDE + lcb;
    const uint32_t sdB = sb + TILE_B + lr * STRIDE + lcb;

    const uint32_t aBase = sb + (wm * 64 + (lane & 15)) * STRIDE + (lane >> 4) * 16;
    const int bn_local = (lane & 7) + ((lane >> 4) & 1) * 8;
    const uint32_t bBase = sb + TILE_B + (wn * 32 + bn_local) * STRIDE + ((lane >> 3) & 1) * 16;

    float acc[4][4][4];
    #pragma unroll
    for (int i = 0; i < 4; i++)
        #pragma unroll
        for (int j = 0; j < 4; j++)
            #pragma unroll
            for (int r = 0; r < 4; r++) acc[i][j][r] = 0.f;

    #pragma unroll
    for (int c = 0; c < 2; c++) {
        const uint32_t so = c * STAGE_B;
        const __nv_bfloat16* as = Ag + (size_t)(c % NC_A) * BK;
        const __nv_bfloat16* bs = Bg + (size_t)c * BK;
        cp16(sdA + so, as);      cp16(sdA + so + 16, as + 8);
        cp16(sdB + so, bs);      cp16(sdB + so + 16, bs + 8);
        cp_commit();
    }

    for (int c = 0; c < NC; c++) {
        cp_wait<1>();
        __syncthreads();
        const uint32_t so = (c & 1) * STAGE_B;
        #pragma unroll
        for (int ks = 0; ks < 2; ks++) {
            uint32_t a[4][4], b[2][4];
            #pragma unroll
            for (int mi = 0; mi < 4; mi++)
                ldm_x4(a[mi][0], a[mi][1], a[mi][2], a[mi][3],
                       aBase + so + mi * 16 * STRIDE + ks * 32);
            #pragma unroll
            for (int nj = 0; nj < 2; nj++)
                ldm_x4(b[nj][0], b[nj][1], b[nj][2], b[nj][3],
                       bBase + so + nj * 16 * STRIDE + ks * 32);
            #pragma unroll
            for (int mi = 0; mi < 4; mi++)
                #pragma unroll
                for (int ni = 0; ni < 4; ni++)
                    mma_bf16(acc[mi][ni], a[mi][0], a[mi][1], a[mi][2], a[mi][3],
                             b[ni >> 1][(ni & 1) * 2], b[ni >> 1][(ni & 1) * 2 + 1]);
        }
        __syncthreads();
        const int cn = c + 2;
        if (cn < NC) {
            const uint32_t sn = (cn & 1) * STAGE_B;
            const __nv_bfloat16* as = Ag + (size_t)(cn % NC_A) * BK;
            const __nv_bfloat16* bs = Bg + (size_t)cn * BK;
            cp16(sdA + sn, as);      cp16(sdA + sn + 16, as + 8);
            cp16(sdB + sn, bs);      cp16(sdB + sn + 16, bs + 8);
        }
        cp_commit();
    }

    const int row0 = rowBase + wm * 64 + (lane >> 2);
    const int col0 = colBase + wn * 32 + (lane & 3) * 2;
    #pragma unroll
    for (int mi = 0; mi < 4; mi++) {
        #pragma unroll
        for (int ni = 0; ni < 4; ni++) {
            const int r = row0 + mi * 16;
            const int cc = col0 + ni * 8;
            float b0 = 0.f, b1 = 0.f;
            if (bias) { b0 = bias[cc]; b1 = bias[cc + 1]; }
            float2 v0 = { acc[mi][ni][0] + b0, acc[mi][ni][1] + b1 };
            float2 v1 = { acc[mi][ni][2] + b0, acc[mi][ni][3] + b1 };
            *(float2*)(C + (size_t)r * N + cc) = v0;
            *(float2*)(C + (size_t)(r + 8) * N + cc) = v1;
        }
    }
}

// ---- weight prep: w[K,N] fp32 -> Wt[N,ns*K] bf16 (hi|mid|lo planes) ---------
__global__ void k_prep_w(const float* __restrict__ w, __nv_bfloat16* __restrict__ wt,
                         int K, int N, int ns)
{
    int idx = blockIdx.x * 256 + threadIdx.x;
    if (idx >= N * K) return;
    int n = idx / K, k = idx - n * K;
    float v = w[(size_t)k * N + n];
    __nv_bfloat16 hi = __float2bfloat16(v);
    float r1 = v - __bfloat162float(hi);
    __nv_bfloat16 mid = __float2bfloat16(r1);
    __nv_bfloat16* base = wt + (size_t)n * ns * K + k;
    base[0] = hi;
    base[K] = mid;
    if (ns == 3) {
        float r2 = r1 - __bfloat162float(mid);
        base[2 * K] = __float2bfloat16(r2);
    }
}

// ------- IF on input + transpose to column-major fp32 spikes -----------------
__global__ void k_if_input_T(const float* __restrict__ x)
{
    __shared__ float sm[TT][32][33];
    const int d0 = blockIdx.x * 32, s0 = blockIdx.y * 32;
    const int tx = threadIdx.x, tyy = threadIdx.y;
    #pragma unroll
    for (int i = 0; i < 4; i++) {
        const int sl = tyy + i * 8;
        const int s = s0 + sl;
        float v = 0.f;
        #pragma unroll
        for (int t = 0; t < TT; t++) {
            v += x[(size_t)(t * SS + s) * DD + d0 + tx];
            float sp = (v >= 1.f) ? 1.f : 0.f;
            sm[t][sl][tx] = sp;
            v *= (1.f - sp);
        }
    }
    __syncthreads();
    #pragma unroll
    for (int i = 0; i < 4; i++) {
        const int d = d0 + tyy + i * 8;
        #pragma unroll
        for (int t = 0; t < TT; t++)
            g_tmpsT[(size_t)d * TS + t * SS + s0 + tx] = sm[t][tx][tyy + i * 8];
    }
}

// ---------------- fused BatchNorm (per-s over T,DIM) + IF --------------------
template<int MODE, int DIM, typename OBT>
__global__ void __launch_bounds__(256) k_bn_if(
    const float* __restrict__ y, const float* __restrict__ res,
    float* __restrict__ of, OBT* __restrict__ ob)
{
    constexpr int CPT = DIM / 256;
    const int s = blockIdx.x, tid = threadIdx.x;
    float vals[TT][CPT];
    float sum = 0.f, sq = 0.f;
    #pragma unroll
    for (int c = 0; c < CPT; c++) {
        int d = tid + c * 256;
        #pragma unroll
        for (int t = 0; t < TT; t++) {
            float val = y[(size_t)(t * SS + s) * DIM + d];
            vals[t][c] = val;
            sum += val; sq += val * val;
        }
    }
    __shared__ float s1[256], s2[256];
    s1[tid] = sum; s2[tid] = sq;
    __syncthreads();
    for (int o = 128; o > 0; o >>= 1) {
        if (tid < o) { s1[tid] += s1[tid + o]; s2[tid] += s2[tid + o]; }
        __syncthreads();
    }
    const float invn = 1.f / (float)(TT * DIM);
    float mean = s1[0] * invn;
    float inv  = rsqrtf(s2[0] * invn - mean * mean + EPSf);
    #pragma unroll
    for (int c = 0; c < CPT; c++) {
        int d = tid + c * 256;
        float v = 0.f;
        #pragma unroll
        for (int t = 0; t < TT; t++) {
            size_t idx = (size_t)(t * SS + s) * DIM + d;
            float nv = (vals[t][c] - mean) * inv;
            if (MODE == 0) {
                v += nv;
                float sp = (v >= 1.f) ? 1.f : 0.f;
                ob[idx] = (OBT)sp;
                v *= (1.f - sp);
            } else if (MODE == 1) {
                float hh = res[idx] + nv;
                of[idx] = hh;
                v += hh;
                float sp = (v >= 1.f) ? 1.f : 0.f;
                ob[idx] = (OBT)sp;
                v *= (1.f - sp);
            } else {
                of[idx] = res[idx] + nv;
            }
        }
    }
}

// ---------------- QK column-sum (deterministic 2-phase) + IF over T ----------
__global__ void k_qk_partial()
{
    int d = blockIdx.x * 256 + threadIdx.x;
    int t = blockIdx.z;
    int chunk = blockIdx.y;
    size_t base = (size_t)(t * SS + chunk * 128) * DD + d;
    float acc = 0.f;
    #pragma unroll 4
    for (int i = 0; i < 128; i++)
        acc += g_qs[base + (size_t)i * DD] * g_ks[base + (size_t)i * DD];
    g_qkp[(chunk * TT + t) * DD + d] = acc;
}

__global__ void k_qk_if()
{
    int d = blockIdx.x * 256 + threadIdx.x;
    float v = 0.f;
    #pragma unroll
    for (int t = 0; t < TT; t++) {
        float s = 0.f;
        #pragma unroll
        for (int c = 0; c < 8; c++) s += g_qkp[(c * TT + t) * DD + d];
        v += s;
        float sp = (v >= 1.f) ? 1.f : 0.f;
        g_qks[t * DD + d] = sp;
        v *= (1.f - sp);
    }
}

// -------- vm = V_spike * QK_spike, transposed to column-major fp32 -----------
__global__ void k_vmask_T()
{
    __shared__ float sm[TT][32][33];
    const int d0 = blockIdx.x * 32, s0 = blockIdx.y * 32;
    const int tx = threadIdx.x, tyy = threadIdx.y;
    #pragma unroll
    for (int i = 0; i < 4; i++) {
        const int sl = tyy + i * 8;
        const int s = s0 + sl;
        #pragma unroll
        for (int t = 0; t < TT; t++) {
            float m = g_qks[t * DD + d0 + tx];
            sm[t][sl][tx] = g_vs[(size_t)(t * SS + s) * DD + d0 + tx] * m;
        }
    }
    __syncthreads();
    #pragma unroll
    for (int i = 0; i < 4; i++) {
        const int d = d0 + tyy + i * 8;
        #pragma unroll
        for (int t = 0; t < TT; t++)
            g_vmT[(size_t)d * TS + t * SS + s0 + tx] = sm[t][tx][tyy + i * 8];
    }
}

// ---------------- launch ------------------------------------------------------
extern "C" void kernel_launch(void* const* d_in, const int* in_sizes, int n_in,
                              void* d_out, int out_size)
{
    const float* x  = (const float*)d_in[0];
    const float* wq = (const float*)d_in[1];
    const float* wk = (const float*)d_in[2];
    const float* wv = (const float*)d_in[3];
    const float* wo = (const float*)d_in[4];
    const float* w1 = (const float*)d_in[5];
    const float* b1 = (const float*)d_in[6];
    const float* w2 = (const float*)d_in[7];
    const float* b2 = (const float*)d_in[8];
    float* out = (float*)d_out;

    float *q, *k, *v, *go, *h, *g1, *g2, *qs, *ks, *vs, *tmpsT, *vmT;
    __nv_bfloat16 *fs, *g1s, *w1T, *w2T;
    cudaGetSymbolAddress((void**)&q, g_q);       cudaGetSymbolAddress((void**)&k, g_k);
    cudaGetSymbolAddress((void**)&v, g_v);       cudaGetSymbolAddress((void**)&go, g_go);
    cudaGetSymbolAddress((void**)&h, g_h);       cudaGetSymbolAddress((void**)&g1, g_g1);
    cudaGetSymbolAddress((void**)&g2, g_g2);
    cudaGetSymbolAddress((void**)&qs, g_qs);     cudaGetSymbolAddress((void**)&ks, g_ks);
    cudaGetSymbolAddress((void**)&vs, g_vs);
    cudaGetSymbolAddress((void**)&tmpsT, g_tmpsT);
    cudaGetSymbolAddress((void**)&vmT, g_vmT);
    cudaGetSymbolAddress((void**)&fs, g_fs);     cudaGetSymbolAddress((void**)&g1s, g_g1s);
    cudaGetSymbolAddress((void**)&w1T, g_w1T);   cudaGetSymbolAddress((void**)&w2T, g_w2T);

    cudaFuncSetAttribute(k_sgemm_f32, cudaFuncAttributeMaxDynamicSharedMemorySize, SGEMM_SMEM);

    const dim3 gS(DD / 128, TS / 128);      // (6, 32) SGEMM grid
    const dim3 gUp(FFD / 128, TS / 128);    // (24, 32)
    const dim3 gDn(DD / 128, TS / 128);     // (6, 32)
    const dim3 gT(DD / 32, SS / 32);        // (24, 32) transpose grids
    const dim3 bT(32, 8);

    // 0) FFN weight prep (w1: 3-split feeds IF; w2: 2-split, value-only)
    k_prep_w<<<(DD * FFD + 255) / 256, 256>>>(w1, w1T, DD, FFD, 3);
    k_prep_w<<<(DD * FFD + 255) / 256, 256>>>(w2, w2T, FFD, DD, 2);

    // 1) tmp = IF(x), column-major fp32 spikes
    k_if_input_T<<<gT, bT>>>(x);
    // 2) Q/K/V pre-BN GEMMs (bitwise ascending-k fp32 chain, f32x2 packed)
    k_sgemm_f32<<<gS, 256, SGEMM_SMEM>>>(tmpsT, wq, q, DD, DD);
    k_sgemm_f32<<<gS, 256, SGEMM_SMEM>>>(tmpsT, wk, k, DD, DD);
    k_sgemm_f32<<<gS, 256, SGEMM_SMEM>>>(tmpsT, wv, v, DD, DD);
    // 3) BN + IF -> fp32 spikes
    k_bn_if<0, DD, float><<<SS, 256>>>(q, nullptr, nullptr, qs);
    k_bn_if<0, DD, float><<<SS, 256>>>(k, nullptr, nullptr, ks);
    k_bn_if<0, DD, float><<<SS, 256>>>(v, nullptr, nullptr, vs);
    // 4) QK column-sums + talking-heads IF; masked-V transpose
    k_qk_partial<<<dim3(3, 8, 4), 256>>>();
    k_qk_if<<<3, 256>>>();
    k_vmask_T<<<gT, bT>>>();
    // 5) attn GEMM
    k_sgemm_f32<<<gS, 256, SGEMM_SMEM>>>(vmT, wo, go, DD, DD);
    // 6) h = x + BN(go); f = IF(h) -> bf16 spikes
    k_bn_if<1, DD, __nv_bfloat16><<<SS, 256>>>(go, x, h, fs);
    // 7) FFN up (tensor cores, 3-split)
    k_mma_gemm<<<gUp, 256>>>(fs, w1T, b1, g1, FFD, DD, 3);
    // 8) BN + IF -> bf16 spikes
    k_bn_if<0, FFD, __nv_bfloat16><<<SS, 256>>>(g1, nullptr, nullptr, g1s);
    // 9) FFN down (tensor cores, 2-split; no downstream IF)
    k_mma_gemm<<<gDn, 256>>>(g1s, w2T, b2, g2, DD, FFD, 2);
    // 10) out = h + BN(g2)
    k_bn_if<2, DD, float><<<SS, 256>>>(g2, h, out, nullptr);
}

// round 7
// speedup vs baseline: 1.7333x; 1.0639x over previous
#include <cuda_runtime.h>
#include <cuda_bf16.h>
#include <cstdint>

// Shapes (fixed)
#define TT  4
#define SS  1024
#define DD  768
#define FFD 3072
#define TS  4096          // TT*SS
#define EPSf 1e-5f

// ---------------- scratch (device globals; no allocs allowed) ----------------
__device__ float g_q  [TS*DD];
__device__ float g_k  [TS*DD];
__device__ float g_v  [TS*DD];
__device__ float g_go [TS*DD];
__device__ float g_h  [TS*DD];
__device__ float g_g1 [TS*FFD];
__device__ float g_g2 [TS*DD];
__device__ float g_qkp[8*TT*DD];
__device__ float g_qks[TT*DD];
// fp32 spikes (bitwise path)
__device__ float g_qs [TS*DD];
__device__ float g_ks [TS*DD];
__device__ float g_vs [TS*DD];
// column-major fp32 A operands for SGEMM: [K][TS]
__device__ __align__(128) float g_tmpsT[DD*TS];
__device__ __align__(128) float g_vmT  [DD*TS];
// bf16 spikes for tensor FFN path
__device__ __align__(128) __nv_bfloat16 g_fs [TS*DD];
__device__ __align__(128) __nv_bfloat16 g_g1s[TS*FFD];
// bf16 split-transposed FFN weights (hi|mid|lo planes)
__device__ __align__(128) __nv_bfloat16 g_w1T[FFD*3*DD];
__device__ __align__(128) __nv_bfloat16 g_w2T[DD*3*FFD];

// ---------------- PTX helpers ------------------------------------------------
__device__ __forceinline__ uint32_t smem_u32(const void* p) {
    uint32_t a;
    asm("{ .reg .u64 t; cvta.to.shared.u64 t, %1; cvt.u32.u64 %0, t; }" : "=r"(a) : "l"(p));
    return a;
}
__device__ __forceinline__ void cp16(uint32_t dst, const void* src) {
    asm volatile("cp.async.cg.shared.global [%0], [%1], 16;" :: "r"(dst), "l"(src));
}
__device__ __forceinline__ void cp_commit() {
    asm volatile("cp.async.commit_group;" ::: "memory");
}
template<int N> __device__ __forceinline__ void cp_wait() {
    asm volatile("cp.async.wait_group %0;" :: "n"(N) : "memory");
}
__device__ __forceinline__ void ldm_x4(uint32_t& r0, uint32_t& r1, uint32_t& r2, uint32_t& r3,
                                       uint32_t addr) {
    asm volatile("ldmatrix.sync.aligned.m8n8.x4.shared.b16 {%0,%1,%2,%3}, [%4];"
                 : "=r"(r0), "=r"(r1), "=r"(r2), "=r"(r3) : "r"(addr));
}
__device__ __forceinline__ void mma_bf16(float* d, uint32_t a0, uint32_t a1, uint32_t a2,
                                         uint32_t a3, uint32_t b0, uint32_t b1) {
    asm volatile(
        "mma.sync.aligned.m16n8k16.row.col.f32.bf16.bf16.f32 "
        "{%0,%1,%2,%3}, {%4,%5,%6,%7}, {%8,%9}, {%0,%1,%2,%3};"
        : "+f"(d[0]), "+f"(d[1]), "+f"(d[2]), "+f"(d[3])
        : "r"(a0), "r"(a1), "r"(a2), "r"(a3), "r"(b0), "r"(b1));
}
// packed fp32x2 (Blackwell base ISA); lane-wise fma.rn == scalar FFMA bitwise
__device__ __forceinline__ unsigned long long pk2(float lo, float hi) {
    unsigned long long r;
    asm("mov.b64 %0, {%1, %2};" : "=l"(r) : "f"(lo), "f"(hi));
    return r;
}
__device__ __forceinline__ void upk2(unsigned long long v, float& lo, float& hi) {
    asm("mov.b64 {%0, %1}, %2;" : "=f"(lo), "=f"(hi) : "l"(v));
}
__device__ __forceinline__ void fma2(unsigned long long& d, unsigned long long a,
                                     unsigned long long b) {
    asm("fma.rn.f32x2 %0, %1, %2, %0;" : "+l"(d) : "l"(a), "l"(b));
}

// =============================================================================
// fp32 SGEMM, bitwise ascending-k FFMA chain per output, packed f32x2 math.
// C[4096,N] = A[4096,K] @ W[K,N], A column-major AT[K][4096].
// 64x128 tile, BK=16, 3-stage cp.async, 256 threads, 4x8 microtile.
// grid = 384 CTAs -> single wave at 3 CTAs/SM.
// =============================================================================
#define A_F   (16*68)            // A floats per stage (16 k-rows x 64 + pad)
#define B_F   (16*132)           // B floats per stage
#define STG_F (A_F + B_F)        // 3200 floats = 12800 B per stage
#define SGEMM_SMEM (3*STG_F*4)   // 38400 B

__global__ void __launch_bounds__(256, 3) k_sgemm_f32(
    const float* __restrict__ AT, const float* __restrict__ W,
    float* __restrict__ C, int N, int K)
{
    extern __shared__ float smem[];
    const int tid = threadIdx.x;
    const int ty = tid >> 4, tx = tid & 15;
    const int rowBase = blockIdx.y * 64;
    const int colBase = blockIdx.x * 128;
    const int NC = K >> 4;
    const uint32_t sb = smem_u32(smem);
    const int kr = tid >> 4;     // k-row 0..15 (loader role)
    const int lg = tid & 15;     // granule

#define PREFETCH(c) do {                                                       \
        const int st_ = (c) % 3;                                               \
        const uint32_t sa_  = sb + (st_ * STG_F + kr * 68 + lg * 4) * 4;       \
        const uint32_t sbB_ = sb + (st_ * STG_F + A_F + kr * 132 + lg * 8) * 4; \
        const float* as_ = AT + (size_t)((c) * 16 + kr) * TS + rowBase + lg * 4; \
        const float* bs_ = W + (size_t)((c) * 16 + kr) * N + colBase + lg * 8;   \
        cp16(sa_, as_);                                                        \
        cp16(sbB_, bs_);       cp16(sbB_ + 16, bs_ + 4);                       \
        cp_commit();                                                           \
    } while (0)

    unsigned long long acc2[2][8];   // [row-pair][col]
    #pragma unroll
    for (int i = 0; i < 2; i++)
        #pragma unroll
        for (int j = 0; j < 8; j++) acc2[i][j] = 0ull;

    PREFETCH(0);
    PREFETCH(1);

    for (int c = 0; c < NC; c++) {
        cp_wait<1>();
        __syncthreads();
        if (c + 2 < NC) PREFETCH(c + 2); else cp_commit();
        const float* As = smem + (c % 3) * STG_F;
        const float* Bs = As + A_F;
        #pragma unroll
        for (int kk = 0; kk < 16; kk++) {
            float4 av = *(const float4*)&As[kk * 68 + ty * 4];
            float4 b0 = *(const float4*)&Bs[kk * 132 + tx * 4];
            float4 b1 = *(const float4*)&Bs[kk * 132 + 64 + tx * 4];
            unsigned long long ap[2] = { pk2(av.x, av.y), pk2(av.z, av.w) };
            unsigned long long bd[8] = { pk2(b0.x, b0.x), pk2(b0.y, b0.y),
                                         pk2(b0.z, b0.z), pk2(b0.w, b0.w),
                                         pk2(b1.x, b1.x), pk2(b1.y, b1.y),
                                         pk2(b1.z, b1.z), pk2(b1.w, b1.w) };
            #pragma unroll
            for (int i = 0; i < 2; i++)
                #pragma unroll
                for (int j = 0; j < 8; j++)
                    fma2(acc2[i][j], ap[i], bd[j]);
        }
    }
#undef PREFETCH

    // epilogue: unpack row pairs (rows ty*4+2p, ty*4+2p+1), cols tx*4 / 64+tx*4
    #pragma unroll
    for (int p = 0; p < 2; p++) {
        const int rbase = rowBase + ty * 4 + p * 2;
        float lo[8], hi[8];
        #pragma unroll
        for (int j = 0; j < 8; j++) upk2(acc2[p][j], lo[j], hi[j]);
        float4 l0 = { lo[0], lo[1], lo[2], lo[3] }, l1 = { lo[4], lo[5], lo[6], lo[7] };
        float4 h0 = { hi[0], hi[1], hi[2], hi[3] }, h1 = { hi[4], hi[5], hi[6], hi[7] };
        *(float4*)(C + (size_t)rbase * N + colBase + tx * 4) = l0;
        *(float4*)(C + (size_t)rbase * N + colBase + 64 + tx * 4) = l1;
        *(float4*)(C + (size_t)(rbase + 1) * N + colBase + tx * 4) = h0;
        *(float4*)(C + (size_t)(rbase + 1) * N + colBase + 64 + tx * 4) = h1;
    }
}

// =============================================================================
// HMMA GEMM (tensor cores) for FFN: C = A @ Wt^T (+bias), ns split planes
// =============================================================================
#define BK      32
#define STRIDE  80
#define TILE_B  (128 * STRIDE)
#define STAGE_B (2 * TILE_B)

__global__ void __launch_bounds__(256, 2) k_mma_gemm(
    const __nv_bfloat16* __restrict__ A, const __nv_bfloat16* __restrict__ Wt,
    const float* __restrict__ bias, float* __restrict__ C, int N, int KA, int ns)
{
    __shared__ __align__(16) char smem[2 * STAGE_B];   // 40 KB
    const int tid = threadIdx.x, lane = tid & 31, wid = tid >> 5;
    const int wm = wid >> 2, wn = wid & 3;
    const int rowBase = blockIdx.y * 128, colBase = blockIdx.x * 128;
    const int NC_A = KA >> 5, NC = NC_A * ns;
    const uint32_t sb = smem_u32(smem);

    const int lr = tid >> 1;
    const int lcb = (tid & 1) * 32;
    const __nv_bfloat16* Ag = A + (size_t)(rowBase + lr) * KA + (lcb >> 1);
    const __nv_bfloat16* Bg = Wt + (size_t)(colBase + lr) * (ns * KA) + (lcb >> 1);
    const uint32_t sdA = sb + lr * STRIDE + lcb;
    const uint32_t sdB = sb + TILE_B + lr * STRIDE + lcb;

    const uint32_t aBase = sb + (wm * 64 + (lane & 15)) * STRIDE + (lane >> 4) * 16;
    const int bn_local = (lane & 7) + ((lane >> 4) & 1) * 8;
    const uint32_t bBase = sb + TILE_B + (wn * 32 + bn_local) * STRIDE + ((lane >> 3) & 1) * 16;

    float acc[4][4][4];
    #pragma unroll
    for (int i = 0; i < 4; i++)
        #pragma unroll
        for (int j = 0; j < 4; j++)
            #pragma unroll
            for (int r = 0; r < 4; r++) acc[i][j][r] = 0.f;

    #pragma unroll
    for (int c = 0; c < 2; c++) {
        const uint32_t so = c * STAGE_B;
        const __nv_bfloat16* as = Ag + (size_t)(c % NC_A) * BK;
        const __nv_bfloat16* bs = Bg + (size_t)c * BK;
        cp16(sdA + so, as);      cp16(sdA + so + 16, as + 8);
        cp16(sdB + so, bs);      cp16(sdB + so + 16, bs + 8);
        cp_commit();
    }

    for (int c = 0; c < NC; c++) {
        cp_wait<1>();
        __syncthreads();
        const uint32_t so = (c & 1) * STAGE_B;
        #pragma unroll
        for (int ks = 0; ks < 2; ks++) {
            uint32_t a[4][4], b[2][4];
            #pragma unroll
            for (int mi = 0; mi < 4; mi++)
                ldm_x4(a[mi][0], a[mi][1], a[mi][2], a[mi][3],
                       aBase + so + mi * 16 * STRIDE + ks * 32);
            #pragma unroll
            for (int nj = 0; nj < 2; nj++)
                ldm_x4(b[nj][0], b[nj][1], b[nj][2], b[nj][3],
                       bBase + so + nj * 16 * STRIDE + ks * 32);
            #pragma unroll
            for (int mi = 0; mi < 4; mi++)
                #pragma unroll
                for (int ni = 0; ni < 4; ni++)
                    mma_bf16(acc[mi][ni], a[mi][0], a[mi][1], a[mi][2], a[mi][3],
                             b[ni >> 1][(ni & 1) * 2], b[ni >> 1][(ni & 1) * 2 + 1]);
        }
        __syncthreads();
        const int cn = c + 2;
        if (cn < NC) {
            const uint32_t sn = (cn & 1) * STAGE_B;
            const __nv_bfloat16* as = Ag + (size_t)(cn % NC_A) * BK;
            const __nv_bfloat16* bs = Bg + (size_t)cn * BK;
            cp16(sdA + sn, as);      cp16(sdA + sn + 16, as + 8);
            cp16(sdB + sn, bs);      cp16(sdB + sn + 16, bs + 8);
        }
        cp_commit();
    }

    const int row0 = rowBase + wm * 64 + (lane >> 2);
    const int col0 = colBase + wn * 32 + (lane & 3) * 2;
    #pragma unroll
    for (int mi = 0; mi < 4; mi++) {
        #pragma unroll
        for (int ni = 0; ni < 4; ni++) {
            const int r = row0 + mi * 16;
            const int cc = col0 + ni * 8;
            float b0 = 0.f, b1 = 0.f;
            if (bias) { b0 = bias[cc]; b1 = bias[cc + 1]; }
            float2 v0 = { acc[mi][ni][0] + b0, acc[mi][ni][1] + b1 };
            float2 v1 = { acc[mi][ni][2] + b0, acc[mi][ni][3] + b1 };
            *(float2*)(C + (size_t)r * N + cc) = v0;
            *(float2*)(C + (size_t)(r + 8) * N + cc) = v1;
        }
    }
}

// ---- weight prep: w[K,N] fp32 -> Wt[N,ns*K] bf16 (hi|mid|lo planes) ---------
__global__ void k_prep_w(const float* __restrict__ w, __nv_bfloat16* __restrict__ wt,
                         int K, int N, int ns)
{
    int idx = blockIdx.x * 256 + threadIdx.x;
    if (idx >= N * K) return;
    int n = idx / K, k = idx - n * K;
    float v = w[(size_t)k * N + n];
    __nv_bfloat16 hi = __float2bfloat16(v);
    float r1 = v - __bfloat162float(hi);
    __nv_bfloat16 mid = __float2bfloat16(r1);
    __nv_bfloat16* base = wt + (size_t)n * ns * K + k;
    base[0] = hi;
    base[K] = mid;
    if (ns == 3) {
        float r2 = r1 - __bfloat162float(mid);
        base[2 * K] = __float2bfloat16(r2);
    }
}

// ------- IF on input + transpose to column-major fp32 spikes -----------------
__global__ void k_if_input_T(const float* __restrict__ x)
{
    __shared__ float sm[TT][32][33];
    const int d0 = blockIdx.x * 32, s0 = blockIdx.y * 32;
    const int tx = threadIdx.x, tyy = threadIdx.y;
    #pragma unroll
    for (int i = 0; i < 4; i++) {
        const int sl = tyy + i * 8;
        const int s = s0 + sl;
        float v = 0.f;
        #pragma unroll
        for (int t = 0; t < TT; t++) {
            v += x[(size_t)(t * SS + s) * DD + d0 + tx];
            float sp = (v >= 1.f) ? 1.f : 0.f;
            sm[t][sl][tx] = sp;
            v *= (1.f - sp);
        }
    }
    __syncthreads();
    #pragma unroll
    for (int i = 0; i < 4; i++) {
        const int d = d0 + tyy + i * 8;
        #pragma unroll
        for (int t = 0; t < TT; t++)
            g_tmpsT[(size_t)d * TS + t * SS + s0 + tx] = sm[t][tx][tyy + i * 8];
    }
}

// ---------------- fused BatchNorm (per-s over T,DIM) + IF --------------------
template<int MODE, int DIM, typename OBT>
__global__ void __launch_bounds__(256) k_bn_if(
    const float* __restrict__ y, const float* __restrict__ res,
    float* __restrict__ of, OBT* __restrict__ ob)
{
    constexpr int CPT = DIM / 256;
    const int s = blockIdx.x, tid = threadIdx.x;
    float vals[TT][CPT];
    float sum = 0.f, sq = 0.f;
    #pragma unroll
    for (int c = 0; c < CPT; c++) {
        int d = tid + c * 256;
        #pragma unroll
        for (int t = 0; t < TT; t++) {
            float val = y[(size_t)(t * SS + s) * DIM + d];
            vals[t][c] = val;
            sum += val; sq += val * val;
        }
    }
    __shared__ float s1[256], s2[256];
    s1[tid] = sum; s2[tid] = sq;
    __syncthreads();
    for (int o = 128; o > 0; o >>= 1) {
        if (tid < o) { s1[tid] += s1[tid + o]; s2[tid] += s2[tid + o]; }
        __syncthreads();
    }
    const float invn = 1.f / (float)(TT * DIM);
    float mean = s1[0] * invn;
    float inv  = rsqrtf(s2[0] * invn - mean * mean + EPSf);
    #pragma unroll
    for (int c = 0; c < CPT; c++) {
        int d = tid + c * 256;
        float v = 0.f;
        #pragma unroll
        for (int t = 0; t < TT; t++) {
            size_t idx = (size_t)(t * SS + s) * DIM + d;
            float nv = (vals[t][c] - mean) * inv;
            if (MODE == 0) {
                v += nv;
                float sp = (v >= 1.f) ? 1.f : 0.f;
                ob[idx] = (OBT)sp;
                v *= (1.f - sp);
            } else if (MODE == 1) {
                float hh = res[idx] + nv;
                of[idx] = hh;
                v += hh;
                float sp = (v >= 1.f) ? 1.f : 0.f;
                ob[idx] = (OBT)sp;
                v *= (1.f - sp);
            } else {
                of[idx] = res[idx] + nv;
            }
        }
    }
}

// ---------------- QK column-sum (deterministic 2-phase) + IF over T ----------
__global__ void k_qk_partial()
{
    int d = blockIdx.x * 256 + threadIdx.x;
    int t = blockIdx.z;
    int chunk = blockIdx.y;
    size_t base = (size_t)(t * SS + chunk * 128) * DD + d;
    float acc = 0.f;
    #pragma unroll 4
    for (int i = 0; i < 128; i++)
        acc += g_qs[base + (size_t)i * DD] * g_ks[base + (size_t)i * DD];
    g_qkp[(chunk * TT + t) * DD + d] = acc;
}

__global__ void k_qk_if()
{
    int d = blockIdx.x * 256 + threadIdx.x;
    float v = 0.f;
    #pragma unroll
    for (int t = 0; t < TT; t++) {
        float s = 0.f;
        #pragma unroll
        for (int c = 0; c < 8; c++) s += g_qkp[(c * TT + t) * DD + d];
        v += s;
        float sp = (v >= 1.f) ? 1.f : 0.f;
        g_qks[t * DD + d] = sp;
        v *= (1.f - sp);
    }
}

// -------- vm = V_spike * QK_spike, transposed to column-major fp32 -----------
__global__ void k_vmask_T()
{
    __shared__ float sm[TT][32][33];
    const int d0 = blockIdx.x * 32, s0 = blockIdx.y * 32;
    const int tx = threadIdx.x, tyy = threadIdx.y;
    #pragma unroll
    for (int i = 0; i < 4; i++) {
        const int sl = tyy + i * 8;
        const int s = s0 + sl;
        #pragma unroll
        for (int t = 0; t < TT; t++) {
            float m = g_qks[t * DD + d0 + tx];
            sm[t][sl][tx] = g_vs[(size_t)(t * SS + s) * DD + d0 + tx] * m;
        }
    }
    __syncthreads();
    #pragma unroll
    for (int i = 0; i < 4; i++) {
        const int d = d0 + tyy + i * 8;
        #pragma unroll
        for (int t = 0; t < TT; t++)
            g_vmT[(size_t)d * TS + t * SS + s0 + tx] = sm[t][tx][tyy + i * 8];
    }
}

// ---------------- launch ------------------------------------------------------
extern "C" void kernel_launch(void* const* d_in, const int* in_sizes, int n_in,
                              void* d_out, int out_size)
{
    const float* x  = (const float*)d_in[0];
    const float* wq = (const float*)d_in[1];
    const float* wk = (const float*)d_in[2];
    const float* wv = (const float*)d_in[3];
    const float* wo = (const float*)d_in[4];
    const float* w1 = (const float*)d_in[5];
    const float* b1 = (const float*)d_in[6];
    const float* w2 = (const float*)d_in[7];
    const float* b2 = (const float*)d_in[8];
    float* out = (float*)d_out;

    float *q, *k, *v, *go, *h, *g1, *g2, *qs, *ks, *vs, *tmpsT, *vmT;
    __nv_bfloat16 *fs, *g1s, *w1T, *w2T;
    cudaGetSymbolAddress((void**)&q, g_q);       cudaGetSymbolAddress((void**)&k, g_k);
    cudaGetSymbolAddress((void**)&v, g_v);       cudaGetSymbolAddress((void**)&go, g_go);
    cudaGetSymbolAddress((void**)&h, g_h);       cudaGetSymbolAddress((void**)&g1, g_g1);
    cudaGetSymbolAddress((void**)&g2, g_g2);
    cudaGetSymbolAddress((void**)&qs, g_qs);     cudaGetSymbolAddress((void**)&ks, g_ks);
    cudaGetSymbolAddress((void**)&vs, g_vs);
    cudaGetSymbolAddress((void**)&tmpsT, g_tmpsT);
    cudaGetSymbolAddress((void**)&vmT, g_vmT);
    cudaGetSymbolAddress((void**)&fs, g_fs);     cudaGetSymbolAddress((void**)&g1s, g_g1s);
    cudaGetSymbolAddress((void**)&w1T, g_w1T);   cudaGetSymbolAddress((void**)&w2T, g_w2T);

    cudaFuncSetAttribute(k_sgemm_f32, cudaFuncAttributeMaxDynamicSharedMemorySize, SGEMM_SMEM);

    const dim3 gS(DD / 128, TS / 64);       // (6, 64) = 384 CTAs, single wave
    const dim3 gUp(FFD / 128, TS / 128);    // (24, 32)
    const dim3 gDn(DD / 128, TS / 128);     // (6, 32)
    const dim3 gT(DD / 32, SS / 32);        // (24, 32) transpose grids
    const dim3 bT(32, 8);

    // 0) FFN weight prep (w1: 3-split feeds IF; w2: 2-split, value-only)
    k_prep_w<<<(DD * FFD + 255) / 256, 256>>>(w1, w1T, DD, FFD, 3);
    k_prep_w<<<(DD * FFD + 255) / 256, 256>>>(w2, w2T, FFD, DD, 2);

    // 1) tmp = IF(x), column-major fp32 spikes
    k_if_input_T<<<gT, bT>>>(x);
    // 2) Q/K/V pre-BN GEMMs (bitwise ascending-k fp32 chain, f32x2 packed)
    k_sgemm_f32<<<gS, 256, SGEMM_SMEM>>>(tmpsT, wq, q, DD, DD);
    k_sgemm_f32<<<gS, 256, SGEMM_SMEM>>>(tmpsT, wk, k, DD, DD);
    k_sgemm_f32<<<gS, 256, SGEMM_SMEM>>>(tmpsT, wv, v, DD, DD);
    // 3) BN + IF -> fp32 spikes
    k_bn_if<0, DD, float><<<SS, 256>>>(q, nullptr, nullptr, qs);
    k_bn_if<0, DD, float><<<SS, 256>>>(k, nullptr, nullptr, ks);
    k_bn_if<0, DD, float><<<SS, 256>>>(v, nullptr, nullptr, vs);
    // 4) QK column-sums + talking-heads IF; masked-V transpose
    k_qk_partial<<<dim3(3, 8, 4), 256>>>();
    k_qk_if<<<3, 256>>>();
    k_vmask_T<<<gT, bT>>>();
    // 5) attn GEMM
    k_sgemm_f32<<<gS, 256, SGEMM_SMEM>>>(vmT, wo, go, DD, DD);
    // 6) h = x + BN(go); f = IF(h) -> bf16 spikes
    k_bn_if<1, DD, __nv_bfloat16><<<SS, 256>>>(go, x, h, fs);
    // 7) FFN up (tensor cores, 3-split)
    k_mma_gemm<<<gUp, 256>>>(fs, w1T, b1, g1, FFD, DD, 3);
    // 8) BN + IF -> bf16 spikes
    k_bn_if<0, FFD, __nv_bfloat16><<<SS, 256>>>(g1, nullptr, nullptr, g1s);
    // 9) FFN down (tensor cores, 2-split; no downstream IF)
    k_mma_gemm<<<gDn, 256>>>(g1s, w2T, b2, g2, DD, FFD, 2);
    // 10) out = h + BN(g2)
    k_bn_if<2, DD, float><<<SS, 256>>>(g2, h, out, nullptr);
}

// round 8
// speedup vs baseline: 1.8698x; 1.0788x over previous
#include <cuda_runtime.h>
#include <cuda_bf16.h>
#include <cstdint>

// Shapes (fixed)
#define TT  4
#define SS  1024
#define DD  768
#define FFD 3072
#define TS  4096          // TT*SS
#define EPSf 1e-5f

// ---------------- scratch (device globals; no allocs allowed) ----------------
__device__ float g_q  [TS*DD];
__device__ float g_k  [TS*DD];
__device__ float g_v  [TS*DD];
__device__ float g_go [TS*DD];
__device__ float g_h  [TS*DD];
__device__ float g_g1 [TS*FFD];
__device__ float g_g2 [TS*DD];
__device__ float g_qkp[8*TT*DD];
__device__ float g_qks[TT*DD];
// fp32 spikes (bitwise path)
__device__ float g_qs [TS*DD];
__device__ float g_ks [TS*DD];
__device__ float g_vs [TS*DD];
// column-major fp32 A operands for SGEMM: [K][TS]
__device__ __align__(128) float g_tmpsT[DD*TS];
__device__ __align__(128) float g_vmT  [DD*TS];
// bf16 spikes for tensor FFN path
__device__ __align__(128) __nv_bfloat16 g_fs [TS*DD];
__device__ __align__(128) __nv_bfloat16 g_g1s[TS*FFD];
// bf16 split-transposed FFN weights (hi|mid|lo planes)
__device__ __align__(128) __nv_bfloat16 g_w1T[FFD*3*DD];
__device__ __align__(128) __nv_bfloat16 g_w2T[DD*3*FFD];

// ---------------- PTX helpers ------------------------------------------------
__device__ __forceinline__ uint32_t smem_u32(const void* p) {
    uint32_t a;
    asm("{ .reg .u64 t; cvta.to.shared.u64 t, %1; cvt.u32.u64 %0, t; }" : "=r"(a) : "l"(p));
    return a;
}
__device__ __forceinline__ void cp16(uint32_t dst, const void* src) {
    asm volatile("cp.async.cg.shared.global [%0], [%1], 16;" :: "r"(dst), "l"(src));
}
__device__ __forceinline__ void cp_commit() {
    asm volatile("cp.async.commit_group;" ::: "memory");
}
template<int N> __device__ __forceinline__ void cp_wait() {
    asm volatile("cp.async.wait_group %0;" :: "n"(N) : "memory");
}
__device__ __forceinline__ void ldm_x4(uint32_t& r0, uint32_t& r1, uint32_t& r2, uint32_t& r3,
                                       uint32_t addr) {
    asm volatile("ldmatrix.sync.aligned.m8n8.x4.shared.b16 {%0,%1,%2,%3}, [%4];"
                 : "=r"(r0), "=r"(r1), "=r"(r2), "=r"(r3) : "r"(addr));
}
__device__ __forceinline__ void mma_bf16(float* d, uint32_t a0, uint32_t a1, uint32_t a2,
                                         uint32_t a3, uint32_t b0, uint32_t b1) {
    asm volatile(
        "mma.sync.aligned.m16n8k16.row.col.f32.bf16.bf16.f32 "
        "{%0,%1,%2,%3}, {%4,%5,%6,%7}, {%8,%9}, {%0,%1,%2,%3};"
        : "+f"(d[0]), "+f"(d[1]), "+f"(d[2]), "+f"(d[3])
        : "r"(a0), "r"(a1), "r"(a2), "r"(a3), "r"(b0), "r"(b1));
}
// packed fp32x2 (Blackwell base ISA); lane-wise fma.rn == scalar FFMA bitwise
__device__ __forceinline__ unsigned long long pk2(float lo, float hi) {
    unsigned long long r;
    asm("mov.b64 %0, {%1, %2};" : "=l"(r) : "f"(lo), "f"(hi));
    return r;
}
__device__ __forceinline__ void fma2(unsigned long long& d, unsigned long long a,
                                     unsigned long long b) {
    asm("fma.rn.f32x2 %0, %1, %2, %0;" : "+l"(d) : "l"(a), "l"(b));
}

// =============================================================================
// fp32 SGEMM, bitwise ascending-k FFMA chain per output, packed f32x2 math.
// C[4096,N] = A[4096,K] @ W[K,N], A column-major AT[K][4096].
// 64x128 tile, BK=16, 3-stage cp.async, 256 threads, 4x8 microtile.
// f32x2 pairs = adjacent COLUMNS (B pairs free from LDS.128 register quads;
// only 4 A broadcasts per k). grid = 384 CTAs -> single wave at 3 CTAs/SM.
// =============================================================================
#define A_F   (16*68)            // A floats per stage
#define B_F   (16*132)           // B floats per stage
#define STG_F (A_F + B_F)        // 3200 floats = 12800 B per stage
#define SGEMM_SMEM (3*STG_F*4)   // 38400 B

__global__ void __launch_bounds__(256, 3) k_sgemm_f32(
    const float* __restrict__ AT, const float* __restrict__ W,
    float* __restrict__ C, int N, int K)
{
    extern __shared__ float smem[];
    const int tid = threadIdx.x;
    const int ty = tid >> 4, tx = tid & 15;
    const int rowBase = blockIdx.y * 64;
    const int colBase = blockIdx.x * 128;
    const int NC = K >> 4;
    const uint32_t sb = smem_u32(smem);
    const int kr = tid >> 4;     // k-row 0..15 (loader role)
    const int lg = tid & 15;     // granule

#define PREFETCH(c) do {                                                       \
        const int st_ = (c) % 3;                                               \
        const uint32_t sa_  = sb + (st_ * STG_F + kr * 68 + lg * 4) * 4;       \
        const uint32_t sbB_ = sb + (st_ * STG_F + A_F + kr * 132 + lg * 8) * 4; \
        const float* as_ = AT + (size_t)((c) * 16 + kr) * TS + rowBase + lg * 4; \
        const float* bs_ = W + (size_t)((c) * 16 + kr) * N + colBase + lg * 8;   \
        cp16(sa_, as_);                                                        \
        cp16(sbB_, bs_);       cp16(sbB_ + 16, bs_ + 4);                       \
        cp_commit();                                                           \
    } while (0)

    unsigned long long acc2[4][4];   // [row][col-pair]
    #pragma unroll
    for (int i = 0; i < 4; i++)
        #pragma unroll
        for (int j = 0; j < 4; j++) acc2[i][j] = 0ull;

    PREFETCH(0);
    PREFETCH(1);

    for (int c = 0; c < NC; c++) {
        cp_wait<1>();
        __syncthreads();
        if (c + 2 < NC) PREFETCH(c + 2); else cp_commit();
        const float* As = smem + (c % 3) * STG_F;
        const float* Bs = As + A_F;
        #pragma unroll
        for (int kk = 0; kk < 16; kk++) {
            float4 av = *(const float4*)&As[kk * 68 + ty * 4];
            float4 b0 = *(const float4*)&Bs[kk * 132 + tx * 4];
            float4 b1 = *(const float4*)&Bs[kk * 132 + 64 + tx * 4];
            unsigned long long bp[4] = { pk2(b0.x, b0.y), pk2(b0.z, b0.w),
                                         pk2(b1.x, b1.y), pk2(b1.z, b1.w) };
            unsigned long long ad[4] = { pk2(av.x, av.x), pk2(av.y, av.y),
                                         pk2(av.z, av.z), pk2(av.w, av.w) };
            #pragma unroll
            for (int i = 0; i < 4; i++)
                #pragma unroll
                for (int j = 0; j < 4; j++)
                    fma2(acc2[i][j], ad[i], bp[j]);
        }
    }
#undef PREFETCH

    // epilogue: acc2[i][j] = (col even, col odd) -> direct 128-bit stores
    #pragma unroll
    for (int i = 0; i < 4; i++) {
        const int row = rowBase + ty * 4 + i;
        ulonglong2 u0 = { acc2[i][0], acc2[i][1] };
        ulonglong2 u1 = { acc2[i][2], acc2[i][3] };
        *(ulonglong2*)(C + (size_t)row * N + colBase + tx * 4) = u0;
        *(ulonglong2*)(C + (size_t)row * N + colBase + 64 + tx * 4) = u1;
    }
}

// =============================================================================
// HMMA GEMM (tensor cores) for FFN: C = A @ Wt^T (+bias), ns split planes.
// 128x128 tile, BK=32, 3-stage cp.async, ONE barrier per K-iteration.
// =============================================================================
#define BK      32
#define STRIDE  80
#define TILE_B  (128 * STRIDE)
#define STAGE_B (2 * TILE_B)      // 20480 B per stage (A+B)
#define MMA_SMEM (3 * STAGE_B)    // 61440 B

__global__ void __launch_bounds__(256, 2) k_mma_gemm(
    const __nv_bfloat16* __restrict__ A, const __nv_bfloat16* __restrict__ Wt,
    const float* __restrict__ bias, float* __restrict__ C, int N, int KA, int ns)
{
    extern __shared__ __align__(16) char smem_mma[];
    const int tid = threadIdx.x, lane = tid & 31, wid = tid >> 5;
    const int wm = wid >> 2, wn = wid & 3;
    const int rowBase = blockIdx.y * 128, colBase = blockIdx.x * 128;
    const int NC_A = KA >> 5, NC = NC_A * ns;
    const uint32_t sb = smem_u32(smem_mma);

    const int lr = tid >> 1;
    const int lcb = (tid & 1) * 32;
    const __nv_bfloat16* Ag = A + (size_t)(rowBase + lr) * KA + (lcb >> 1);
    const __nv_bfloat16* Bg = Wt + (size_t)(colBase + lr) * (ns * KA) + (lcb >> 1);
    const uint32_t sdA = sb + lr * STRIDE + lcb;
    const uint32_t sdB = sb + TILE_B + lr * STRIDE + lcb;

    const uint32_t aBase = sb + (wm * 64 + (lane & 15)) * STRIDE + (lane >> 4) * 16;
    const int bn_local = (lane & 7) + ((lane >> 4) & 1) * 8;
    const uint32_t bBase = sb + TILE_B + (wn * 32 + bn_local) * STRIDE + ((lane >> 3) & 1) * 16;

#define MPRE(c) do {                                                           \
        const uint32_t so_ = ((c) % 3) * STAGE_B;                              \
        const __nv_bfloat16* as_ = Ag + (size_t)((c) % NC_A) * BK;             \
        const __nv_bfloat16* bs_ = Bg + (size_t)(c) * BK;                      \
        cp16(sdA + so_, as_);      cp16(sdA + so_ + 16, as_ + 8);              \
        cp16(sdB + so_, bs_);      cp16(sdB + so_ + 16, bs_ + 8);              \
        cp_commit();                                                           \
    } while (0)

    float acc[4][4][4];
    #pragma unroll
    for (int i = 0; i < 4; i++)
        #pragma unroll
        for (int j = 0; j < 4; j++)
            #pragma unroll
            for (int r = 0; r < 4; r++) acc[i][j][r] = 0.f;

    MPRE(0);
    MPRE(1);

    for (int c = 0; c < NC; c++) {
        cp_wait<1>();
        __syncthreads();
        if (c + 2 < NC) MPRE(c + 2); else cp_commit();
        const uint32_t so = (c % 3) * STAGE_B;
        #pragma unroll
        for (int ks = 0; ks < 2; ks++) {
            uint32_t a[4][4], b[2][4];
            #pragma unroll
            for (int mi = 0; mi < 4; mi++)
                ldm_x4(a[mi][0], a[mi][1], a[mi][2], a[mi][3],
                       aBase + so + mi * 16 * STRIDE + ks * 32);
            #pragma unroll
            for (int nj = 0; nj < 2; nj++)
                ldm_x4(b[nj][0], b[nj][1], b[nj][2], b[nj][3],
                       bBase + so + nj * 16 * STRIDE + ks * 32);
            #pragma unroll
            for (int mi = 0; mi < 4; mi++)
                #pragma unroll
                for (int ni = 0; ni < 4; ni++)
                    mma_bf16(acc[mi][ni], a[mi][0], a[mi][1], a[mi][2], a[mi][3],
                             b[ni >> 1][(ni & 1) * 2], b[ni >> 1][(ni & 1) * 2 + 1]);
        }
    }
#undef MPRE

    const int row0 = rowBase + wm * 64 + (lane >> 2);
    const int col0 = colBase + wn * 32 + (lane & 3) * 2;
    #pragma unroll
    for (int mi = 0; mi < 4; mi++) {
        #pragma unroll
        for (int ni = 0; ni < 4; ni++) {
            const int r = row0 + mi * 16;
            const int cc = col0 + ni * 8;
            float b0 = 0.f, b1 = 0.f;
            if (bias) { b0 = bias[cc]; b1 = bias[cc + 1]; }
            float2 v0 = { acc[mi][ni][0] + b0, acc[mi][ni][1] + b1 };
            float2 v1 = { acc[mi][ni][2] + b0, acc[mi][ni][3] + b1 };
            *(float2*)(C + (size_t)r * N + cc) = v0;
            *(float2*)(C + (size_t)(r + 8) * N + cc) = v1;
        }
    }
}

// ---- weight prep: w[K,N] fp32 -> Wt[N,ns*K] bf16 (hi|mid|lo planes) ---------
__global__ void k_prep_w(const float* __restrict__ w, __nv_bfloat16* __restrict__ wt,
                         int K, int N, int ns)
{
    int idx = blockIdx.x * 256 + threadIdx.x;
    if (idx >= N * K) return;
    int n = idx / K, k = idx - n * K;
    float v = w[(size_t)k * N + n];
    __nv_bfloat16 hi = __float2bfloat16(v);
    float r1 = v - __bfloat162float(hi);
    __nv_bfloat16 mid = __float2bfloat16(r1);
    __nv_bfloat16* base = wt + (size_t)n * ns * K + k;
    base[0] = hi;
    base[K] = mid;
    if (ns == 3) {
        float r2 = r1 - __bfloat162float(mid);
        base[2 * K] = __float2bfloat16(r2);
    }
}

// ------- IF on input + transpose to column-major fp32 spikes -----------------
__global__ void k_if_input_T(const float* __restrict__ x)
{
    __shared__ float sm[TT][32][33];
    const int d0 = blockIdx.x * 32, s0 = blockIdx.y * 32;
    const int tx = threadIdx.x, tyy = threadIdx.y;
    #pragma unroll
    for (int i = 0; i < 4; i++) {
        const int sl = tyy + i * 8;
        const int s = s0 + sl;
        float v = 0.f;
        #pragma unroll
        for (int t = 0; t < TT; t++) {
            v += x[(size_t)(t * SS + s) * DD + d0 + tx];
            float sp = (v >= 1.f) ? 1.f : 0.f;
            sm[t][sl][tx] = sp;
            v *= (1.f - sp);
        }
    }
    __syncthreads();
    #pragma unroll
    for (int i = 0; i < 4; i++) {
        const int d = d0 + tyy + i * 8;
        #pragma unroll
        for (int t = 0; t < TT; t++)
            g_tmpsT[(size_t)d * TS + t * SS + s0 + tx] = sm[t][tx][tyy + i * 8];
    }
}

// ---------------- fused BatchNorm (per-s over T,DIM) + IF --------------------
template<int MODE, int DIM, typename OBT>
__global__ void __launch_bounds__(256) k_bn_if(
    const float* __restrict__ y, const float* __restrict__ res,
    float* __restrict__ of, OBT* __restrict__ ob)
{
    constexpr int CPT = DIM / 256;
    const int s = blockIdx.x, tid = threadIdx.x;
    float vals[TT][CPT];
    float sum = 0.f, sq = 0.f;
    #pragma unroll
    for (int c = 0; c < CPT; c++) {
        int d = tid + c * 256;
        #pragma unroll
        for (int t = 0; t < TT; t++) {
            float val = y[(size_t)(t * SS + s) * DIM + d];
            vals[t][c] = val;
            sum += val; sq += val * val;
        }
    }
    __shared__ float s1[256], s2[256];
    s1[tid] = sum; s2[tid] = sq;
    __syncthreads();
    for (int o = 128; o > 0; o >>= 1) {
        if (tid < o) { s1[tid] += s1[tid + o]; s2[tid] += s2[tid + o]; }
        __syncthreads();
    }
    const float invn = 1.f / (float)(TT * DIM);
    float mean = s1[0] * invn;
    float inv  = rsqrtf(s2[0] * invn - mean * mean + EPSf);
    #pragma unroll
    for (int c = 0; c < CPT; c++) {
        int d = tid + c * 256;
        float v = 0.f;
        #pragma unroll
        for (int t = 0; t < TT; t++) {
            size_t idx = (size_t)(t * SS + s) * DIM + d;
            float nv = (vals[t][c] - mean) * inv;
            if (MODE == 0) {
                v += nv;
                float sp = (v >= 1.f) ? 1.f : 0.f;
                ob[idx] = (OBT)sp;
                v *= (1.f - sp);
            } else if (MODE == 1) {
                float hh = res[idx] + nv;
                of[idx] = hh;
                v += hh;
                float sp = (v >= 1.f) ? 1.f : 0.f;
                ob[idx] = (OBT)sp;
                v *= (1.f - sp);
            } else {
                of[idx] = res[idx] + nv;
            }
        }
    }
}

// ---------------- QK column-sum (deterministic 2-phase) + IF over T ----------
__global__ void k_qk_partial()
{
    int d = blockIdx.x * 256 + threadIdx.x;
    int t = blockIdx.z;
    int chunk = blockIdx.y;
    size_t base = (size_t)(t * SS + chunk * 128) * DD + d;
    float acc = 0.f;
    #pragma unroll 4
    for (int i = 0; i < 128; i++)
        acc += g_qs[base + (size_t)i * DD] * g_ks[base + (size_t)i * DD];
    g_qkp[(chunk * TT + t) * DD + d] = acc;
}

__global__ void k_qk_if()
{
    int d = blockIdx.x * 256 + threadIdx.x;
    float v = 0.f;
    #pragma unroll
    for (int t = 0; t < TT; t++) {
        float s = 0.f;
        #pragma unroll
        for (int c = 0; c < 8; c++) s += g_qkp[(c * TT + t) * DD + d];
        v += s;
        float sp = (v >= 1.f) ? 1.f : 0.f;
        g_qks[t * DD + d] = sp;
        v *= (1.f - sp);
    }
}

// -------- vm = V_spike * QK_spike, transposed to column-major fp32 -----------
__global__ void k_vmask_T()
{
    __shared__ float sm[TT][32][33];
    const int d0 = blockIdx.x * 32, s0 = blockIdx.y * 32;
    const int tx = threadIdx.x, tyy = threadIdx.y;
    #pragma unroll
    for (int i = 0; i < 4; i++) {
        const int sl = tyy + i * 8;
        const int s = s0 + sl;
        #pragma unroll
        for (int t = 0; t < TT; t++) {
            float m = g_qks[t * DD + d0 + tx];
            sm[t][sl][tx] = g_vs[(size_t)(t * SS + s) * DD + d0 + tx] * m;
        }
    }
    __syncthreads();
    #pragma unroll
    for (int i = 0; i < 4; i++) {
        const int d = d0 + tyy + i * 8;
        #pragma unroll
        for (int t = 0; t < TT; t++)
            g_vmT[(size_t)d * TS + t * SS + s0 + tx] = sm[t][tx][tyy + i * 8];
    }
}

// ---------------- launch ------------------------------------------------------
extern "C" void kernel_launch(void* const* d_in, const int* in_sizes, int n_in,
                              void* d_out, int out_size)
{
    const float* x  = (const float*)d_in[0];
    const float* wq = (const float*)d_in[1];
    const float* wk = (const float*)d_in[2];
    const float* wv = (const float*)d_in[3];
    const float* wo = (const float*)d_in[4];
    const float* w1 = (const float*)d_in[5];
    const float* b1 = (const float*)d_in[6];
    const float* w2 = (const float*)d_in[7];
    const float* b2 = (const float*)d_in[8];
    float* out = (float*)d_out;

    float *q, *k, *v, *go, *h, *g1, *g2, *qs, *ks, *vs, *tmpsT, *vmT;
    __nv_bfloat16 *fs, *g1s, *w1T, *w2T;
    cudaGetSymbolAddress((void**)&q, g_q);       cudaGetSymbolAddress((void**)&k, g_k);
    cudaGetSymbolAddress((void**)&v, g_v);       cudaGetSymbolAddress((void**)&go, g_go);
    cudaGetSymbolAddress((void**)&h, g_h);       cudaGetSymbolAddress((void**)&g1, g_g1);
    cudaGetSymbolAddress((void**)&g2, g_g2);
    cudaGetSymbolAddress((void**)&qs, g_qs);     cudaGetSymbolAddress((void**)&ks, g_ks);
    cudaGetSymbolAddress((void**)&vs, g_vs);
    cudaGetSymbolAddress((void**)&tmpsT, g_tmpsT);
    cudaGetSymbolAddress((void**)&vmT, g_vmT);
    cudaGetSymbolAddress((void**)&fs, g_fs);     cudaGetSymbolAddress((void**)&g1s, g_g1s);
    cudaGetSymbolAddress((void**)&w1T, g_w1T);   cudaGetSymbolAddress((void**)&w2T, g_w2T);

    cudaFuncSetAttribute(k_sgemm_f32, cudaFuncAttributeMaxDynamicSharedMemorySize, SGEMM_SMEM);
    cudaFuncSetAttribute(k_mma_gemm, cudaFuncAttributeMaxDynamicSharedMemorySize, MMA_SMEM);

    const dim3 gS(DD / 128, TS / 64);       // (6, 64) = 384 CTAs, single wave
    const dim3 gUp(FFD / 128, TS / 128);    // (24, 32)
    const dim3 gDn(DD / 128, TS / 128);     // (6, 32)
    const dim3 gT(DD / 32, SS / 32);        // (24, 32) transpose grids
    const dim3 bT(32, 8);

    // 0) FFN weight prep (w1: 3-split feeds IF; w2: 2-split, value-only)
    k_prep_w<<<(DD * FFD + 255) / 256, 256>>>(w1, w1T, DD, FFD, 3);
    k_prep_w<<<(DD * FFD + 255) / 256, 256>>>(w2, w2T, FFD, DD, 2);

    // 1) tmp = IF(x), column-major fp32 spikes
    k_if_input_T<<<gT, bT>>>(x);
    // 2) Q/K/V pre-BN GEMMs (bitwise ascending-k fp32 chain, f32x2 packed)
    k_sgemm_f32<<<gS, 256, SGEMM_SMEM>>>(tmpsT, wq, q, DD, DD);
    k_sgemm_f32<<<gS, 256, SGEMM_SMEM>>>(tmpsT, wk, k, DD, DD);
    k_sgemm_f32<<<gS, 256, SGEMM_SMEM>>>(tmpsT, wv, v, DD, DD);
    // 3) BN + IF -> fp32 spikes
    k_bn_if<0, DD, float><<<SS, 256>>>(q, nullptr, nullptr, qs);
    k_bn_if<0, DD, float><<<SS, 256>>>(k, nullptr, nullptr, ks);
    k_bn_if<0, DD, float><<<SS, 256>>>(v, nullptr, nullptr, vs);
    // 4) QK column-sums + talking-heads IF; masked-V transpose
    k_qk_partial<<<dim3(3, 8, 4), 256>>>();
    k_qk_if<<<3, 256>>>();
    k_vmask_T<<<gT, bT>>>();
    // 5) attn GEMM
    k_sgemm_f32<<<gS, 256, SGEMM_SMEM>>>(vmT, wo, go, DD, DD);
    // 6) h = x + BN(go); f = IF(h) -> bf16 spikes
    k_bn_if<1, DD, __nv_bfloat16><<<SS, 256>>>(go, x, h, fs);
    // 7) FFN up (tensor cores, 3-split)
    k_mma_gemm<<<gUp, 256, MMA_SMEM>>>(fs, w1T, b1, g1, FFD, DD, 3);
    // 8) BN + IF -> bf16 spikes
    k_bn_if<0, FFD, __nv_bfloat16><<<SS, 256>>>(g1, nullptr, nullptr, g1s);
    // 9) FFN down (tensor cores, 2-split; no downstream IF)
    k_mma_gemm<<<gDn, 256, MMA_SMEM>>>(g1s, w2T, b2, g2, DD, FFD, 2);
    // 10) out = h + BN(g2)
    k_bn_if<2, DD, float><<<SS, 256>>>(g2, h, out, nullptr);
}

// round 9
// speedup vs baseline: 2.2149x; 1.1845x over previous
#include <cuda_runtime.h>
#include <cuda_bf16.h>
#include <cstdint>

// Shapes (fixed)
#define TT  4
#define SS  1024
#define DD  768
#define FFD 3072
#define TS  4096          // TT*SS
#define EPSf 1e-5f

// ---------------- scratch (device globals; no allocs allowed) ----------------
__device__ float g_q  [TS*DD];
__device__ float g_k  [TS*DD];
__device__ float g_v  [TS*DD];
__device__ float g_go [TS*DD];
__device__ float g_h  [TS*DD];
__device__ float g_g1 [TS*FFD];
__device__ float g_g2 [TS*DD];
__device__ float g_qkp[8*TT*DD];
__device__ float g_qks[TT*DD];
// fp32 spikes (bitwise path)
__device__ float g_qs [TS*DD];
__device__ float g_ks [TS*DD];
__device__ float g_vs [TS*DD];
// column-major fp32 A operands for SGEMM: [K][TS]
__device__ __align__(128) float g_tmpsT[DD*TS];
__device__ __align__(128) float g_vmT  [DD*TS];
// s8 spikes for IMMA FFN path
__device__ __align__(128) int8_t g_fs [TS*DD];
__device__ __align__(128) int8_t g_g1s[TS*FFD];
// s8 digit-plane weights: Wt[n][plane*K + k], msb plane first
__device__ __align__(128) int8_t g_w1T[(size_t)FFD*4*DD];
__device__ __align__(128) int8_t g_w2T[(size_t)DD*2*FFD];

// ---------------- PTX helpers ------------------------------------------------
__device__ __forceinline__ uint32_t smem_u32(const void* p) {
    uint32_t a;
    asm("{ .reg .u64 t; cvta.to.shared.u64 t, %1; cvt.u32.u64 %0, t; }" : "=r"(a) : "l"(p));
    return a;
}
__device__ __forceinline__ void cp16(uint32_t dst, const void* src) {
    asm volatile("cp.async.cg.shared.global [%0], [%1], 16;" :: "r"(dst), "l"(src));
}
__device__ __forceinline__ void cp_commit() {
    asm volatile("cp.async.commit_group;" ::: "memory");
}
template<int N> __device__ __forceinline__ void cp_wait() {
    asm volatile("cp.async.wait_group %0;" :: "n"(N) : "memory");
}
__device__ __forceinline__ void ldm_x4(uint32_t& r0, uint32_t& r1, uint32_t& r2, uint32_t& r3,
                                       uint32_t addr) {
    asm volatile("ldmatrix.sync.aligned.m8n8.x4.shared.b16 {%0,%1,%2,%3}, [%4];"
                 : "=r"(r0), "=r"(r1), "=r"(r2), "=r"(r3) : "r"(addr));
}
__device__ __forceinline__ void mma_s8(int* d, uint32_t a0, uint32_t a1, uint32_t a2,
                                       uint32_t a3, uint32_t b0, uint32_t b1) {
    asm volatile(
        "mma.sync.aligned.m16n8k32.row.col.s32.s8.s8.s32 "
        "{%0,%1,%2,%3}, {%4,%5,%6,%7}, {%8,%9}, {%0,%1,%2,%3};"
        : "+r"(d[0]), "+r"(d[1]), "+r"(d[2]), "+r"(d[3])
        : "r"(a0), "r"(a1), "r"(a2), "r"(a3), "r"(b0), "r"(b1));
}
// packed fp32x2 (Blackwell base ISA); lane-wise fma.rn == scalar FFMA bitwise
__device__ __forceinline__ unsigned long long pk2(float lo, float hi) {
    unsigned long long r;
    asm("mov.b64 %0, {%1, %2};" : "=l"(r) : "f"(lo), "f"(hi));
    return r;
}
__device__ __forceinline__ void fma2(unsigned long long& d, unsigned long long a,
                                     unsigned long long b) {
    asm("fma.rn.f32x2 %0, %1, %2, %0;" : "+l"(d) : "l"(a), "l"(b));
}

// =============================================================================
// fp32 SGEMM, bitwise ascending-k FFMA chain per output, packed f32x2 math.
// (QKV + attn path: spike decisions depend on this exact accumulation order.)
// =============================================================================
#define A_F   (16*68)
#define B_F   (16*132)
#define STG_F (A_F + B_F)
#define SGEMM_SMEM (3*STG_F*4)

__global__ void __launch_bounds__(256, 3) k_sgemm_f32(
    const float* __restrict__ AT, const float* __restrict__ W,
    float* __restrict__ C, int N, int K)
{
    extern __shared__ float smem[];
    const int tid = threadIdx.x;
    const int ty = tid >> 4, tx = tid & 15;
    const int rowBase = blockIdx.y * 64;
    const int colBase = blockIdx.x * 128;
    const int NC = K >> 4;
    const uint32_t sb = smem_u32(smem);
    const int kr = tid >> 4;
    const int lg = tid & 15;

#define PREFETCH(c) do {                                                       \
        const int st_ = (c) % 3;                                               \
        const uint32_t sa_  = sb + (st_ * STG_F + kr * 68 + lg * 4) * 4;       \
        const uint32_t sbB_ = sb + (st_ * STG_F + A_F + kr * 132 + lg * 8) * 4; \
        const float* as_ = AT + (size_t)((c) * 16 + kr) * TS + rowBase + lg * 4; \
        const float* bs_ = W + (size_t)((c) * 16 + kr) * N + colBase + lg * 8;   \
        cp16(sa_, as_);                                                        \
        cp16(sbB_, bs_);       cp16(sbB_ + 16, bs_ + 4);                       \
        cp_commit();                                                           \
    } while (0)

    unsigned long long acc2[4][4];
    #pragma unroll
    for (int i = 0; i < 4; i++)
        #pragma unroll
        for (int j = 0; j < 4; j++) acc2[i][j] = 0ull;

    PREFETCH(0);
    PREFETCH(1);

    for (int c = 0; c < NC; c++) {
        cp_wait<1>();
        __syncthreads();
        if (c + 2 < NC) PREFETCH(c + 2); else cp_commit();
        const float* As = smem + (c % 3) * STG_F;
        const float* Bs = As + A_F;
        #pragma unroll
        for (int kk = 0; kk < 16; kk++) {
            float4 av = *(const float4*)&As[kk * 68 + ty * 4];
            float4 b0 = *(const float4*)&Bs[kk * 132 + tx * 4];
            float4 b1 = *(const float4*)&Bs[kk * 132 + 64 + tx * 4];
            unsigned long long bp[4] = { pk2(b0.x, b0.y), pk2(b0.z, b0.w),
                                         pk2(b1.x, b1.y), pk2(b1.z, b1.w) };
            unsigned long long ad[4] = { pk2(av.x, av.x), pk2(av.y, av.y),
                                         pk2(av.z, av.z), pk2(av.w, av.w) };
            #pragma unroll
            for (int i = 0; i < 4; i++)
                #pragma unroll
                for (int j = 0; j < 4; j++)
                    fma2(acc2[i][j], ad[i], bp[j]);
        }
    }
#undef PREFETCH

    #pragma unroll
    for (int i = 0; i < 4; i++) {
        const int row = rowBase + ty * 4 + i;
        ulonglong2 u0 = { acc2[i][0], acc2[i][1] };
        ulonglong2 u1 = { acc2[i][2], acc2[i][3] };
        *(ulonglong2*)(C + (size_t)row * N + colBase + tx * 4) = u0;
        *(ulonglong2*)(C + (size_t)row * N + colBase + 64 + tx * 4) = u1;
    }
}

// =============================================================================
// IMMA s8 GEMM for FFN: C = (A @ digit-planes of W) folded, + bias.
// A: s8 binary spikes [4096, KA]. Wt: s8 [N][NP*KA] (msb digit plane first).
// CTA tile 128x64, warp 32x32, BK=64 s8, 3-stage cp.async.
// Per-plane s32 accumulation is EXACT; fold facc = facc*256 + iacc per plane.
// =============================================================================
#define ISTRIDE 80
#define IA_TILE (128*ISTRIDE)          // 10240 B
#define IB_TILE (64*ISTRIDE)           // 5120 B
#define ISTG    (IA_TILE + IB_TILE)    // 15360 B
#define IMMA_SMEM (3*ISTG)             // 46080 B

template<int KA, int NP>
__global__ void __launch_bounds__(256, 2) k_imma_gemm(
    const int8_t* __restrict__ A, const int8_t* __restrict__ Wt,
    const float* __restrict__ bias, float* __restrict__ C, int N, float invSF)
{
    constexpr int NCA = KA / 64;
    constexpr int NC = NCA * NP;
    extern __shared__ __align__(16) char smem_i[];
    const int tid = threadIdx.x, lane = tid & 31, wid = tid >> 5;
    const int wm = wid >> 1, wn = wid & 1;        // 4 x 2 warps, 32x32 each
    const int rowBase = blockIdx.y * 128, colBase = blockIdx.x * 64;
    const uint32_t sb = smem_u32(smem_i);

    // A loader: 128 rows x 64B, 2 threads/row x 32B
    const int lrA = tid >> 1, lcA = (tid & 1) * 32;
    const int8_t* Ag = A + (size_t)(rowBase + lrA) * KA + lcA;
    const uint32_t sdA = sb + lrA * ISTRIDE + lcA;
    // B loader: 64 rows x 64B, 4 threads/row x 16B
    const int lrB = tid >> 2, lcB = (tid & 3) * 16;
    const int8_t* Bg = Wt + (size_t)(colBase + lrB) * (NP * KA) + lcB;
    const uint32_t sdB = sb + IA_TILE + lrB * ISTRIDE + lcB;

#define IPRE(c) do {                                                           \
        const uint32_t so_ = ((c) % 3) * ISTG;                                 \
        const int8_t* as_ = Ag + ((c) % NCA) * 64;                             \
        const int8_t* bs_ = Bg + (size_t)(c) * 64;                             \
        cp16(sdA + so_, as_);      cp16(sdA + so_ + 16, as_ + 16);             \
        cp16(sdB + so_, bs_);                                                  \
        cp_commit();                                                           \
    } while (0)

    const uint32_t aBase = sb + (wm * 32 + (lane & 15)) * ISTRIDE + (lane >> 4) * 16;
    const int bn_local = (lane & 7) + ((lane >> 4) & 1) * 8;
    const uint32_t bBase = sb + IA_TILE + (wn * 32 + bn_local) * ISTRIDE + ((lane >> 3) & 1) * 16;

    int   iacc[2][4][4];
    float facc[2][4][4];
    #pragma unroll
    for (int i = 0; i < 2; i++)
        #pragma unroll
        for (int j = 0; j < 4; j++)
            #pragma unroll
            for (int r = 0; r < 4; r++) { iacc[i][j][r] = 0; facc[i][j][r] = 0.f; }

    IPRE(0);
    IPRE(1);

    for (int c = 0; c < NC; c++) {
        cp_wait<1>();
        __syncthreads();
        if (c + 2 < NC) IPRE(c + 2); else cp_commit();
        const uint32_t so = (c % 3) * ISTG;
        #pragma unroll
        for (int ks = 0; ks < 2; ks++) {
            uint32_t a[2][4], b[2][4];
            #pragma unroll
            for (int mi = 0; mi < 2; mi++)
                ldm_x4(a[mi][0], a[mi][1], a[mi][2], a[mi][3],
                       aBase + so + mi * 16 * ISTRIDE + ks * 32);
            #pragma unroll
            for (int nj = 0; nj < 2; nj++)
                ldm_x4(b[nj][0], b[nj][1], b[nj][2], b[nj][3],
                       bBase + so + nj * 16 * ISTRIDE + ks * 32);
            #pragma unroll
            for (int mi = 0; mi < 2; mi++)
                #pragma unroll
                for (int ni = 0; ni < 4; ni++)
                    mma_s8(iacc[mi][ni], a[mi][0], a[mi][1], a[mi][2], a[mi][3],
                           b[ni >> 1][(ni & 1) * 2], b[ni >> 1][(ni & 1) * 2 + 1]);
        }
        if (((c + 1) % NCA) == 0) {      // plane boundary: fold digits
            #pragma unroll
            for (int mi = 0; mi < 2; mi++)
                #pragma unroll
                for (int ni = 0; ni < 4; ni++)
                    #pragma unroll
                    for (int r = 0; r < 4; r++) {
                        facc[mi][ni][r] = facc[mi][ni][r] * 256.f + (float)iacc[mi][ni][r];
                        iacc[mi][ni][r] = 0;
                    }
        }
    }
#undef IPRE

    const int row0 = rowBase + wm * 32 + (lane >> 2);
    const int col0 = colBase + wn * 32 + (lane & 3) * 2;
    #pragma unroll
    for (int mi = 0; mi < 2; mi++) {
        #pragma unroll
        for (int ni = 0; ni < 4; ni++) {
            const int r = row0 + mi * 16;
            const int cc = col0 + ni * 8;
            float b0 = 0.f, b1 = 0.f;
            if (bias) { b0 = bias[cc]; b1 = bias[cc + 1]; }
            float2 v0 = { facc[mi][ni][0] * invSF + b0, facc[mi][ni][1] * invSF + b1 };
            float2 v1 = { facc[mi][ni][2] * invSF + b0, facc[mi][ni][3] * invSF + b1 };
            *(float2*)(C + (size_t)r * N + cc) = v0;
            *(float2*)(C + (size_t)(r + 8) * N + cc) = v1;
        }
    }
}

// ---- weight prep: w[K,N] fp32 -> s8 digit planes Wt[N][NP*K], msb first -----
__global__ void k_prep_w_s8(const float* __restrict__ w, int8_t* __restrict__ wt,
                            int K, int N, int NP, float SF)
{
    int idx = blockIdx.x * 256 + threadIdx.x;
    if (idx >= N * K) return;
    int n = idx / K, k = idx - n * K;
    float v = w[(size_t)k * N + n];
    long long wi = llrintf(v * SF);
    int8_t dig[4];
    for (int p = 0; p < NP; p++) {           // lsb-first digits
        int8_t d = (int8_t)(wi & 0xFF);
        dig[p] = d;
        wi = (wi - d) >> 8;
    }
    int8_t* base = wt + (size_t)n * NP * K + k;
    for (int q = 0; q < NP; q++)             // store msb plane first
        base[(size_t)q * K] = dig[NP - 1 - q];
}

// ------- IF on input + transpose to column-major fp32 spikes -----------------
__global__ void k_if_input_T(const float* __restrict__ x)
{
    __shared__ float sm[TT][32][33];
    const int d0 = blockIdx.x * 32, s0 = blockIdx.y * 32;
    const int tx = threadIdx.x, tyy = threadIdx.y;
    #pragma unroll
    for (int i = 0; i < 4; i++) {
        const int sl = tyy + i * 8;
        const int s = s0 + sl;
        float v = 0.f;
        #pragma unroll
        for (int t = 0; t < TT; t++) {
            v += x[(size_t)(t * SS + s) * DD + d0 + tx];
            float sp = (v >= 1.f) ? 1.f : 0.f;
            sm[t][sl][tx] = sp;
            v *= (1.f - sp);
        }
    }
    __syncthreads();
    #pragma unroll
    for (int i = 0; i < 4; i++) {
        const int d = d0 + tyy + i * 8;
        #pragma unroll
        for (int t = 0; t < TT; t++)
            g_tmpsT[(size_t)d * TS + t * SS + s0 + tx] = sm[t][tx][tyy + i * 8];
    }
}

// ---------------- fused BatchNorm (per-s over T,DIM) + IF --------------------
template<int MODE, int DIM, typename OBT>
__global__ void __launch_bounds__(256) k_bn_if(
    const float* __restrict__ y, const float* __restrict__ res,
    float* __restrict__ of, OBT* __restrict__ ob)
{
    constexpr int CPT = DIM / 256;
    const int s = blockIdx.x, tid = threadIdx.x;
    float vals[TT][CPT];
    float sum = 0.f, sq = 0.f;
    #pragma unroll
    for (int c = 0; c < CPT; c++) {
        int d = tid + c * 256;
        #pragma unroll
        for (int t = 0; t < TT; t++) {
            float val = y[(size_t)(t * SS + s) * DIM + d];
            vals[t][c] = val;
            sum += val; sq += val * val;
        }
    }
    __shared__ float s1[256], s2[256];
    s1[tid] = sum; s2[tid] = sq;
    __syncthreads();
    for (int o = 128; o > 0; o >>= 1) {
        if (tid < o) { s1[tid] += s1[tid + o]; s2[tid] += s2[tid + o]; }
        __syncthreads();
    }
    const float invn = 1.f / (float)(TT * DIM);
    float mean = s1[0] * invn;
    float inv  = rsqrtf(s2[0] * invn - mean * mean + EPSf);
    #pragma unroll
    for (int c = 0; c < CPT; c++) {
        int d = tid + c * 256;
        float v = 0.f;
        #pragma unroll
        for (int t = 0; t < TT; t++) {
            size_t idx = (size_t)(t * SS + s) * DIM + d;
            float nv = (vals[t][c] - mean) * inv;
            if (MODE == 0) {
                v += nv;
                float sp = (v >= 1.f) ? 1.f : 0.f;
                ob[idx] = (OBT)sp;
                v *= (1.f - sp);
            } else if (MODE == 1) {
                float hh = res[idx] + nv;
                of[idx] = hh;
                v += hh;
                float sp = (v >= 1.f) ? 1.f : 0.f;
                ob[idx] = (OBT)sp;
                v *= (1.f - sp);
            } else {
                of[idx] = res[idx] + nv;
            }
        }
    }
}

// ---------------- QK column-sum (deterministic 2-phase) + IF over T ----------
__global__ void k_qk_partial()
{
    int d = blockIdx.x * 256 + threadIdx.x;
    int t = blockIdx.z;
    int chunk = blockIdx.y;
    size_t base = (size_t)(t * SS + chunk * 128) * DD + d;
    float acc = 0.f;
    #pragma unroll 4
    for (int i = 0; i < 128; i++)
        acc += g_qs[base + (size_t)i * DD] * g_ks[base + (size_t)i * DD];
    g_qkp[(chunk * TT + t) * DD + d] = acc;
}

__global__ void k_qk_if()
{
    int d = blockIdx.x * 256 + threadIdx.x;
    float v = 0.f;
    #pragma unroll
    for (int t = 0; t < TT; t++) {
        float s = 0.f;
        #pragma unroll
        for (int c = 0; c < 8; c++) s += g_qkp[(c * TT + t) * DD + d];
        v += s;
        float sp = (v >= 1.f) ? 1.f : 0.f;
        g_qks[t * DD + d] = sp;
        v *= (1.f - sp);
    }
}

// -------- vm = V_spike * QK_spike, transposed to column-major fp32 -----------
__global__ void k_vmask_T()
{
    __shared__ float sm[TT][32][33];
    const int d0 = blockIdx.x * 32, s0 = blockIdx.y * 32;
    const int tx = threadIdx.x, tyy = threadIdx.y;
    #pragma unroll
    for (int i = 0; i < 4; i++) {
        const int sl = tyy + i * 8;
        const int s = s0 + sl;
        #pragma unroll
        for (int t = 0; t < TT; t++) {
            float m = g_qks[t * DD + d0 + tx];
            sm[t][sl][tx] = g_vs[(size_t)(t * SS + s) * DD + d0 + tx] * m;
        }
    }
    __syncthreads();
    #pragma unroll
    for (int i = 0; i < 4; i++) {
        const int d = d0 + tyy + i * 8;
        #pragma unroll
        for (int t = 0; t < TT; t++)
            g_vmT[(size_t)d * TS + t * SS + s0 + tx] = sm[t][tx][tyy + i * 8];
    }
}

// ---------------- launch ------------------------------------------------------
extern "C" void kernel_launch(void* const* d_in, const int* in_sizes, int n_in,
                              void* d_out, int out_size)
{
    const float* x  = (const float*)d_in[0];
    const float* wq = (const float*)d_in[1];
    const float* wk = (const float*)d_in[2];
    const float* wv = (const float*)d_in[3];
    const float* wo = (const float*)d_in[4];
    const float* w1 = (const float*)d_in[5];
    const float* b1 = (const float*)d_in[6];
    const float* w2 = (const float*)d_in[7];
    const float* b2 = (const float*)d_in[8];
    float* out = (float*)d_out;

    float *q, *k, *v, *go, *h, *g1, *g2, *qs, *ks, *vs, *tmpsT, *vmT;
    int8_t *fs, *g1s, *w1T, *w2T;
    cudaGetSymbolAddress((void**)&q, g_q);       cudaGetSymbolAddress((void**)&k, g_k);
    cudaGetSymbolAddress((void**)&v, g_v);       cudaGetSymbolAddress((void**)&go, g_go);
    cudaGetSymbolAddress((void**)&h, g_h);       cudaGetSymbolAddress((void**)&g1, g_g1);
    cudaGetSymbolAddress((void**)&g2, g_g2);
    cudaGetSymbolAddress((void**)&qs, g_qs);     cudaGetSymbolAddress((void**)&ks, g_ks);
    cudaGetSymbolAddress((void**)&vs, g_vs);
    cudaGetSymbolAddress((void**)&tmpsT, g_tmpsT);
    cudaGetSymbolAddress((void**)&vmT, g_vmT);
    cudaGetSymbolAddress((void**)&fs, g_fs);     cudaGetSymbolAddress((void**)&g1s, g_g1s);
    cudaGetSymbolAddress((void**)&w1T, g_w1T);   cudaGetSymbolAddress((void**)&w2T, g_w2T);

    cudaFuncSetAttribute(k_sgemm_f32, cudaFuncAttributeMaxDynamicSharedMemorySize, SGEMM_SMEM);
    cudaFuncSetAttribute(k_imma_gemm<DD, 4>, cudaFuncAttributeMaxDynamicSharedMemorySize, IMMA_SMEM);
    cudaFuncSetAttribute(k_imma_gemm<FFD, 2>, cudaFuncAttributeMaxDynamicSharedMemorySize, IMMA_SMEM);

    const float SF_UP = 8589934592.f;      // 2^33
    const float SF_DN = 262144.f;          // 2^18

    const dim3 gS(DD / 128, TS / 64);       // (6, 64) = 384 CTAs, single wave
    const dim3 gUp(FFD / 64, TS / 128);     // (48, 32) = 1536 CTAs
    const dim3 gDn(DD / 64, TS / 128);      // (12, 32) = 384 CTAs
    const dim3 gT(DD / 32, SS / 32);        // transpose grids
    const dim3 bT(32, 8);

    // 0) FFN weight prep (s8 digit planes)
    k_prep_w_s8<<<(DD * FFD + 255) / 256, 256>>>(w1, w1T, DD, FFD, 4, SF_UP);
    k_prep_w_s8<<<(DD * FFD + 255) / 256, 256>>>(w2, w2T, FFD, DD, 2, SF_DN);

    // 1) tmp = IF(x), column-major fp32 spikes
    k_if_input_T<<<gT, bT>>>(x);
    // 2) Q/K/V pre-BN GEMMs (bitwise ascending-k fp32 chain)
    k_sgemm_f32<<<gS, 256, SGEMM_SMEM>>>(tmpsT, wq, q, DD, DD);
    k_sgemm_f32<<<gS, 256, SGEMM_SMEM>>>(tmpsT, wk, k, DD, DD);
    k_sgemm_f32<<<gS, 256, SGEMM_SMEM>>>(tmpsT, wv, v, DD, DD);
    // 3) BN + IF -> fp32 spikes
    k_bn_if<0, DD, float><<<SS, 256>>>(q, nullptr, nullptr, qs);
    k_bn_if<0, DD, float><<<SS, 256>>>(k, nullptr, nullptr, ks);
    k_bn_if<0, DD, float><<<SS, 256>>>(v, nullptr, nullptr, vs);
    // 4) QK column-sums + talking-heads IF; masked-V transpose
    k_qk_partial<<<dim3(3, 8, 4), 256>>>();
    k_qk_if<<<3, 256>>>();
    k_vmask_T<<<gT, bT>>>();
    // 5) attn GEMM
    k_sgemm_f32<<<gS, 256, SGEMM_SMEM>>>(vmT, wo, go, DD, DD);
    // 6) h = x + BN(go); f = IF(h) -> s8 spikes
    k_bn_if<1, DD, int8_t><<<SS, 256>>>(go, x, h, fs);
    // 7) FFN up (IMMA s8, 4 digit planes, SF=2^33)
    k_imma_gemm<DD, 4><<<gUp, 256, IMMA_SMEM>>>(fs, w1T, b1, g1, FFD, 1.f / SF_UP);
    // 8) BN + IF -> s8 spikes
    k_bn_if<0, FFD, int8_t><<<SS, 256>>>(g1, nullptr, nullptr, g1s);
    // 9) FFN down (IMMA s8, 2 digit planes, SF=2^18; value-only path)
    k_imma_gemm<FFD, 2><<<gDn, 256, IMMA_SMEM>>>(g1s, w2T, b2, g2, DD, 1.f / SF_DN);
    // 10) out = h + BN(g2)
    k_bn_if<2, DD, float><<<SS, 256>>>(g2, h, out, nullptr);
}

// round 10
// speedup vs baseline: 2.2877x; 1.0329x over previous
#include <cuda_runtime.h>
#include <cuda_bf16.h>
#include <cstdint>

// Shapes (fixed)
#define TT  4
#define SS  1024
#define DD  768
#define FFD 3072
#define TS  4096          // TT*SS
#define EPSf 1e-5f
#define NQKV 2304         // 3*DD merged QKV output width

// ---------------- scratch (device globals; no allocs allowed) ----------------
__device__ float g_qkv[(size_t)TS*NQKV];   // merged QKV pre-BN
__device__ float g_go [TS*DD];
__device__ float g_h  [TS*DD];
__device__ float g_g1 [TS*FFD];
__device__ float g_g2 [TS*DD];
__device__ float g_qkp[8*TT*DD];
__device__ float g_qks[TT*DD];
// fp32 spikes (bitwise path)
__device__ float g_qs [TS*DD];
__device__ float g_ks [TS*DD];
__device__ float g_vs [TS*DD];
// column-major fp32 A operands for SGEMM: [K][TS]
__device__ __align__(128) float g_tmpsT[DD*TS];
__device__ __align__(128) float g_vmT  [DD*TS];
// concatenated QKV weights [K][2304]
__device__ __align__(128) float g_wqkv[(size_t)DD*NQKV];
// s8 spikes for IMMA FFN path
__device__ __align__(128) int8_t g_fs [TS*DD];
__device__ __align__(128) int8_t g_g1s[TS*FFD];
// s8 digit-plane weights: Wt[n][plane*K + k], msb plane first
__device__ __align__(128) int8_t g_w1T[(size_t)FFD*4*DD];
__device__ __align__(128) int8_t g_w2T[(size_t)DD*2*FFD];

// ---------------- PTX helpers ------------------------------------------------
__device__ __forceinline__ uint32_t smem_u32(const void* p) {
    uint32_t a;
    asm("{ .reg .u64 t; cvta.to.shared.u64 t, %1; cvt.u32.u64 %0, t; }" : "=r"(a) : "l"(p));
    return a;
}
__device__ __forceinline__ void cp16(uint32_t dst, const void* src) {
    asm volatile("cp.async.cg.shared.global [%0], [%1], 16;" :: "r"(dst), "l"(src));
}
__device__ __forceinline__ void cp_commit() {
    asm volatile("cp.async.commit_group;" ::: "memory");
}
template<int N> __device__ __forceinline__ void cp_wait() {
    asm volatile("cp.async.wait_group %0;" :: "n"(N) : "memory");
}
__device__ __forceinline__ void ldm_x4(uint32_t& r0, uint32_t& r1, uint32_t& r2, uint32_t& r3,
                                       uint32_t addr) {
    asm volatile("ldmatrix.sync.aligned.m8n8.x4.shared.b16 {%0,%1,%2,%3}, [%4];"
                 : "=r"(r0), "=r"(r1), "=r"(r2), "=r"(r3) : "r"(addr));
}
__device__ __forceinline__ void mma_s8(int* d, uint32_t a0, uint32_t a1, uint32_t a2,
                                       uint32_t a3, uint32_t b0, uint32_t b1) {
    asm volatile(
        "mma.sync.aligned.m16n8k32.row.col.s32.s8.s8.s32 "
        "{%0,%1,%2,%3}, {%4,%5,%6,%7}, {%8,%9}, {%0,%1,%2,%3};"
        : "+r"(d[0]), "+r"(d[1]), "+r"(d[2]), "+r"(d[3])
        : "r"(a0), "r"(a1), "r"(a2), "r"(a3), "r"(b0), "r"(b1));
}
// packed fp32x2; lane-wise fma.rn == scalar FFMA bitwise
__device__ __forceinline__ unsigned long long pk2(float lo, float hi) {
    unsigned long long r;
    asm("mov.b64 %0, {%1, %2};" : "=l"(r) : "f"(lo), "f"(hi));
    return r;
}
__device__ __forceinline__ void fma2(unsigned long long& d, unsigned long long a,
                                     unsigned long long b) {
    asm("fma.rn.f32x2 %0, %1, %2, %0;" : "+l"(d) : "l"(a), "l"(b));
}

// =============================================================================
// fp32 SGEMM, bitwise ascending-k FFMA chain per output, packed f32x2 math.
// C[4096,N] = A[4096,K] @ W[K,N], A column-major AT[K][4096].
// 64x128 tile, 128 threads, 8x8 microtile, BK=16, 3-stage cp.async.
// =============================================================================
#define A_F   (16*68)            // 1088 floats per A stage
#define B_F   (16*132)           // 2112 floats per B stage
#define STG_F (A_F + B_F)        // 3200 floats = 12800 B per stage
#define SGEMM_SMEM (3*STG_F*4)   // 38400 B

__global__ void __launch_bounds__(128, 4) k_sgemm_f32(
    const float* __restrict__ AT, const float* __restrict__ W,
    float* __restrict__ C, int N, int K)
{
    extern __shared__ float smem[];
    const int tid = threadIdx.x;
    const int ty = tid >> 4, tx = tid & 15;      // 8 row-groups x 16 col-groups
    const int rowBase = blockIdx.y * 64;
    const int colBase = blockIdx.x * 128;
    const int NC = K >> 4;
    const uint32_t sb = smem_u32(smem);
    const int kr = tid >> 3;     // k-row 0..15 (loader)
    const int lg = tid & 7;      // granule 0..7

#define PREFETCH(c) do {                                                        \
        const int st_ = (c) % 3;                                                \
        const uint32_t sa_  = sb + (st_ * STG_F + kr * 68 + lg * 8) * 4;        \
        const uint32_t sbB_ = sb + (st_ * STG_F + A_F + kr * 132 + lg * 16) * 4; \
        const float* as_ = AT + (size_t)((c) * 16 + kr) * TS + rowBase + lg * 8; \
        const float* bs_ = W + (size_t)((c) * 16 + kr) * N + colBase + lg * 16;  \
        cp16(sa_, as_);        cp16(sa_ + 16, as_ + 4);                         \
        cp16(sbB_, bs_);       cp16(sbB_ + 16, bs_ + 4);                        \
        cp16(sbB_ + 32, bs_ + 8); cp16(sbB_ + 48, bs_ + 12);                    \
        cp_commit();                                                            \
    } while (0)

    unsigned long long acc2[8][4];   // [row][col-pair], cols tx*8..tx*8+7
    #pragma unroll
    for (int i = 0; i < 8; i++)
        #pragma unroll
        for (int j = 0; j < 4; j++) acc2[i][j] = 0ull;

    PREFETCH(0);
    PREFETCH(1);

    for (int c = 0; c < NC; c++) {
        cp_wait<1>();
        __syncthreads();
        if (c + 2 < NC) PREFETCH(c + 2); else cp_commit();
        const float* As = smem + (c % 3) * STG_F;
        const float* Bs = As + A_F;
        #pragma unroll
        for (int kk = 0; kk < 16; kk++) {
            float4 a0 = *(const float4*)&As[kk * 68 + ty * 8];
            float4 a1 = *(const float4*)&As[kk * 68 + ty * 8 + 4];
            float4 b0 = *(const float4*)&Bs[kk * 132 + tx * 8];
            float4 b1 = *(const float4*)&Bs[kk * 132 + tx * 8 + 4];
            unsigned long long bp[4] = { pk2(b0.x, b0.y), pk2(b0.z, b0.w),
                                         pk2(b1.x, b1.y), pk2(b1.z, b1.w) };
            unsigned long long ad[8] = { pk2(a0.x, a0.x), pk2(a0.y, a0.y),
                                         pk2(a0.z, a0.z), pk2(a0.w, a0.w),
                                         pk2(a1.x, a1.x), pk2(a1.y, a1.y),
                                         pk2(a1.z, a1.z), pk2(a1.w, a1.w) };
            #pragma unroll
            for (int i = 0; i < 8; i++)
                #pragma unroll
                for (int j = 0; j < 4; j++)
                    fma2(acc2[i][j], ad[i], bp[j]);
        }
    }
#undef PREFETCH

    // epilogue: 8 rows x 8 contiguous cols per thread
    #pragma unroll
    for (int i = 0; i < 8; i++) {
        const int row = rowBase + ty * 8 + i;
        ulonglong2 u0 = { acc2[i][0], acc2[i][1] };
        ulonglong2 u1 = { acc2[i][2], acc2[i][3] };
        *(ulonglong2*)(C + (size_t)row * N + colBase + tx * 8) = u0;
        *(ulonglong2*)(C + (size_t)row * N + colBase + tx * 8 + 4) = u1;
    }
}

// =============================================================================
// IMMA s8 GEMM for FFN: C = (A @ digit-planes of W) folded, + bias.
// =============================================================================
#define ISTRIDE 80
#define IA_TILE (128*ISTRIDE)
#define IB_TILE (64*ISTRIDE)
#define ISTG    (IA_TILE + IB_TILE)
#define IMMA_SMEM (3*ISTG)

template<int KA, int NP>
__global__ void __launch_bounds__(256, 2) k_imma_gemm(
    const int8_t* __restrict__ A, const int8_t* __restrict__ Wt,
    const float* __restrict__ bias, float* __restrict__ C, int N, float invSF)
{
    constexpr int NCA = KA / 64;
    constexpr int NC = NCA * NP;
    extern __shared__ __align__(16) char smem_i[];
    const int tid = threadIdx.x, lane = tid & 31, wid = tid >> 5;
    const int wm = wid >> 1, wn = wid & 1;
    const int rowBase = blockIdx.y * 128, colBase = blockIdx.x * 64;
    const uint32_t sb = smem_u32(smem_i);

    const int lrA = tid >> 1, lcA = (tid & 1) * 32;
    const int8_t* Ag = A + (size_t)(rowBase + lrA) * KA + lcA;
    const uint32_t sdA = sb + lrA * ISTRIDE + lcA;
    const int lrB = tid >> 2, lcB = (tid & 3) * 16;
    const int8_t* Bg = Wt + (size_t)(colBase + lrB) * (NP * KA) + lcB;
    const uint32_t sdB = sb + IA_TILE + lrB * ISTRIDE + lcB;

#define IPRE(c) do {                                                           \
        const uint32_t so_ = ((c) % 3) * ISTG;                                 \
        const int8_t* as_ = Ag + ((c) % NCA) * 64;                             \
        const int8_t* bs_ = Bg + (size_t)(c) * 64;                             \
        cp16(sdA + so_, as_);      cp16(sdA + so_ + 16, as_ + 16);             \
        cp16(sdB + so_, bs_);                                                  \
        cp_commit();                                                           \
    } while (0)

    const uint32_t aBase = sb + (wm * 32 + (lane & 15)) * ISTRIDE + (lane >> 4) * 16;
    const int bn_local = (lane & 7) + ((lane >> 4) & 1) * 8;
    const uint32_t bBase = sb + IA_TILE + (wn * 32 + bn_local) * ISTRIDE + ((lane >> 3) & 1) * 16;

    int   iacc[2][4][4];
    float facc[2][4][4];
    #pragma unroll
    for (int i = 0; i < 2; i++)
        #pragma unroll
        for (int j = 0; j < 4; j++)
            #pragma unroll
            for (int r = 0; r < 4; r++) { iacc[i][j][r] = 0; facc[i][j][r] = 0.f; }

    IPRE(0);
    IPRE(1);

    for (int c = 0; c < NC; c++) {
        cp_wait<1>();
        __syncthreads();
        if (c + 2 < NC) IPRE(c + 2); else cp_commit();
        const uint32_t so = (c % 3) * ISTG;
        #pragma unroll
        for (int ks = 0; ks < 2; ks++) {
            uint32_t a[2][4], b[2][4];
            #pragma unroll
            for (int mi = 0; mi < 2; mi++)
                ldm_x4(a[mi][0], a[mi][1], a[mi][2], a[mi][3],
                       aBase + so + mi * 16 * ISTRIDE + ks * 32);
            #pragma unroll
            for (int nj = 0; nj < 2; nj++)
                ldm_x4(b[nj][0], b[nj][1], b[nj][2], b[nj][3],
                       bBase + so + nj * 16 * ISTRIDE + ks * 32);
            #pragma unroll
            for (int mi = 0; mi < 2; mi++)
                #pragma unroll
                for (int ni = 0; ni < 4; ni++)
                    mma_s8(iacc[mi][ni], a[mi][0], a[mi][1], a[mi][2], a[mi][3],
                           b[ni >> 1][(ni & 1) * 2], b[ni >> 1][(ni & 1) * 2 + 1]);
        }
        if (((c + 1) % NCA) == 0) {
            #pragma unroll
            for (int mi = 0; mi < 2; mi++)
                #pragma unroll
                for (int ni = 0; ni < 4; ni++)
                    #pragma unroll
                    for (int r = 0; r < 4; r++) {
                        facc[mi][ni][r] = facc[mi][ni][r] * 256.f + (float)iacc[mi][ni][r];
                        iacc[mi][ni][r] = 0;
                    }
        }
    }
#undef IPRE

    const int row0 = rowBase + wm * 32 + (lane >> 2);
    const int col0 = colBase + wn * 32 + (lane & 3) * 2;
    #pragma unroll
    for (int mi = 0; mi < 2; mi++) {
        #pragma unroll
        for (int ni = 0; ni < 4; ni++) {
            const int r = row0 + mi * 16;
            const int cc = col0 + ni * 8;
            float b0 = 0.f, b1 = 0.f;
            if (bias) { b0 = bias[cc]; b1 = bias[cc + 1]; }
            float2 v0 = { facc[mi][ni][0] * invSF + b0, facc[mi][ni][1] * invSF + b1 };
            float2 v1 = { facc[mi][ni][2] * invSF + b0, facc[mi][ni][3] * invSF + b1 };
            *(float2*)(C + (size_t)r * N + cc) = v0;
            *(float2*)(C + (size_t)(r + 8) * N + cc) = v1;
        }
    }
}

// ---- weight prep: w[K,N] fp32 -> s8 digit planes Wt[N][NP*K], msb first -----
__global__ void k_prep_w_s8(const float* __restrict__ w, int8_t* __restrict__ wt,
                            int K, int N, int NP, float SF)
{
    int idx = blockIdx.x * 256 + threadIdx.x;
    if (idx >= N * K) return;
    int n = idx / K, k = idx - n * K;
    float v = w[(size_t)k * N + n];
    long long wi = llrintf(v * SF);
    int8_t dig[4];
    for (int p = 0; p < NP; p++) {
        int8_t d = (int8_t)(wi & 0xFF);
        dig[p] = d;
        wi = (wi - d) >> 8;
    }
    int8_t* base = wt + (size_t)n * NP * K + k;
    for (int q = 0; q < NP; q++)
        base[(size_t)q * K] = dig[NP - 1 - q];
}

// ---- concat wq|wk|wv into [K][2304] ----------------------------------------
__global__ void k_cat_qkv(const float* __restrict__ wq, const float* __restrict__ wk,
                          const float* __restrict__ wv)
{
    int idx = blockIdx.x * 256 + threadIdx.x;     // over DD*NQKV
    int k = idx / NQKV, j = idx - k * NQKV;
    float v;
    if (j < DD)            v = wq[(size_t)k * DD + j];
    else if (j < 2 * DD)   v = wk[(size_t)k * DD + j - DD];
    else                   v = wv[(size_t)k * DD + j - 2 * DD];
    g_wqkv[(size_t)k * NQKV + j] = v;
}

// ------- IF on input + transpose to column-major fp32 spikes -----------------
__global__ void k_if_input_T(const float* __restrict__ x)
{
    __shared__ float sm[TT][32][33];
    const int d0 = blockIdx.x * 32, s0 = blockIdx.y * 32;
    const int tx = threadIdx.x, tyy = threadIdx.y;
    #pragma unroll
    for (int i = 0; i < 4; i++) {
        const int sl = tyy + i * 8;
        const int s = s0 + sl;
        float v = 0.f;
        #pragma unroll
        for (int t = 0; t < TT; t++) {
            v += x[(size_t)(t * SS + s) * DD + d0 + tx];
            float sp = (v >= 1.f) ? 1.f : 0.f;
            sm[t][sl][tx] = sp;
            v *= (1.f - sp);
        }
    }
    __syncthreads();
    #pragma unroll
    for (int i = 0; i < 4; i++) {
        const int d = d0 + tyy + i * 8;
        #pragma unroll
        for (int t = 0; t < TT; t++)
            g_tmpsT[(size_t)d * TS + t * SS + s0 + tx] = sm[t][tx][tyy + i * 8];
    }
}

// ---------------- fused BatchNorm (per-s over T,DIM) + IF --------------------
// y has row stride ldy (supports reading a slice of the merged QKV buffer)
template<int MODE, int DIM, typename OBT>
__global__ void __launch_bounds__(256) k_bn_if(
    const float* __restrict__ y, int ldy, const float* __restrict__ res,
    float* __restrict__ of, OBT* __restrict__ ob)
{
    constexpr int CPT = DIM / 256;
    const int s = blockIdx.x, tid = threadIdx.x;
    float vals[TT][CPT];
    float sum = 0.f, sq = 0.f;
    #pragma unroll
    for (int c = 0; c < CPT; c++) {
        int d = tid + c * 256;
        #pragma unroll
        for (int t = 0; t < TT; t++) {
            float val = y[(size_t)(t * SS + s) * ldy + d];
            vals[t][c] = val;
            sum += val; sq += val * val;
        }
    }
    __shared__ float s1[256], s2[256];
    s1[tid] = sum; s2[tid] = sq;
    __syncthreads();
    for (int o = 128; o > 0; o >>= 1) {
        if (tid < o) { s1[tid] += s1[tid + o]; s2[tid] += s2[tid + o]; }
        __syncthreads();
    }
    const float invn = 1.f / (float)(TT * DIM);
    float mean = s1[0] * invn;
    float inv  = rsqrtf(s2[0] * invn - mean * mean + EPSf);
    #pragma unroll
    for (int c = 0; c < CPT; c++) {
        int d = tid + c * 256;
        float v = 0.f;
        #pragma unroll
        for (int t = 0; t < TT; t++) {
            size_t idx = (size_t)(t * SS + s) * DIM + d;
            float nv = (vals[t][c] - mean) * inv;
            if (MODE == 0) {
                v += nv;
                float sp = (v >= 1.f) ? 1.f : 0.f;
                ob[idx] = (OBT)sp;
                v *= (1.f - sp);
            } else if (MODE == 1) {
                float hh = res[idx] + nv;
                of[idx] = hh;
                v += hh;
                float sp = (v >= 1.f) ? 1.f : 0.f;
                ob[idx] = (OBT)sp;
                v *= (1.f - sp);
            } else {
                of[idx] = res[idx] + nv;
            }
        }
    }
}

// ---------------- QK column-sum (deterministic 2-phase) + IF over T ----------
__global__ void k_qk_partial()
{
    int d = blockIdx.x * 256 + threadIdx.x;
    int t = blockIdx.z;
    int chunk = blockIdx.y;
    size_t base = (size_t)(t * SS + chunk * 128) * DD + d;
    float acc = 0.f;
    #pragma unroll 4
    for (int i = 0; i < 128; i++)
        acc += g_qs[base + (size_t)i * DD] * g_ks[base + (size_t)i * DD];
    g_qkp[(chunk * TT + t) * DD + d] = acc;
}

__global__ void k_qk_if()
{
    int d = blockIdx.x * 256 + threadIdx.x;
    float v = 0.f;
    #pragma unroll
    for (int t = 0; t < TT; t++) {
        float s = 0.f;
        #pragma unroll
        for (int c = 0; c < 8; c++) s += g_qkp[(c * TT + t) * DD + d];
        v += s;
        float sp = (v >= 1.f) ? 1.f : 0.f;
        g_qks[t * DD + d] = sp;
        v *= (1.f - sp);
    }
}

// -------- vm = V_spike * QK_spike, transposed to column-major fp32 -----------
__global__ void k_vmask_T()
{
    __shared__ float sm[TT][32][33];
    const int d0 = blockIdx.x * 32, s0 = blockIdx.y * 32;
    const int tx = threadIdx.x, tyy = threadIdx.y;
    #pragma unroll
    for (int i = 0; i < 4; i++) {
        const int sl = tyy + i * 8;
        const int s = s0 + sl;
        #pragma unroll
        for (int t = 0; t < TT; t++) {
            float m = g_qks[t * DD + d0 + tx];
            sm[t][sl][tx] = g_vs[(size_t)(t * SS + s) * DD + d0 + tx] * m;
        }
    }
    __syncthreads();
    #pragma unroll
    for (int i = 0; i < 4; i++) {
        const int d = d0 + tyy + i * 8;
        #pragma unroll
        for (int t = 0; t < TT; t++)
            g_vmT[(size_t)d * TS + t * SS + s0 + tx] = sm[t][tx][tyy + i * 8];
    }
}

// ---------------- launch ------------------------------------------------------
extern "C" void kernel_launch(void* const* d_in, const int* in_sizes, int n_in,
                              void* d_out, int out_size)
{
    const float* x  = (const float*)d_in[0];
    const float* wq = (const float*)d_in[1];
    const float* wk = (const float*)d_in[2];
    const float* wv = (const float*)d_in[3];
    const float* wo = (const float*)d_in[4];
    const float* w1 = (const float*)d_in[5];
    const float* b1 = (const float*)d_in[6];
    const float* w2 = (const float*)d_in[7];
    const float* b2 = (const float*)d_in[8];
    float* out = (float*)d_out;

    float *qkv, *go, *h, *g1, *g2, *qs, *ks, *vs, *tmpsT, *vmT, *wqkv;
    int8_t *fs, *g1s, *w1T, *w2T;
    cudaGetSymbolAddress((void**)&qkv, g_qkv);
    cudaGetSymbolAddress((void**)&go, g_go);     cudaGetSymbolAddress((void**)&h, g_h);
    cudaGetSymbolAddress((void**)&g1, g_g1);     cudaGetSymbolAddress((void**)&g2, g_g2);
    cudaGetSymbolAddress((void**)&qs, g_qs);     cudaGetSymbolAddress((void**)&ks, g_ks);
    cudaGetSymbolAddress((void**)&vs, g_vs);
    cudaGetSymbolAddress((void**)&tmpsT, g_tmpsT);
    cudaGetSymbolAddress((void**)&vmT, g_vmT);
    cudaGetSymbolAddress((void**)&wqkv, g_wqkv);
    cudaGetSymbolAddress((void**)&fs, g_fs);     cudaGetSymbolAddress((void**)&g1s, g_g1s);
    cudaGetSymbolAddress((void**)&w1T, g_w1T);   cudaGetSymbolAddress((void**)&w2T, g_w2T);

    cudaFuncSetAttribute(k_sgemm_f32, cudaFuncAttributeMaxDynamicSharedMemorySize, SGEMM_SMEM);
    cudaFuncSetAttribute(k_imma_gemm<DD, 4>, cudaFuncAttributeMaxDynamicSharedMemorySize, IMMA_SMEM);
    cudaFuncSetAttribute(k_imma_gemm<FFD, 2>, cudaFuncAttributeMaxDynamicSharedMemorySize, IMMA_SMEM);

    const float SF_UP = 8589934592.f;      // 2^33
    const float SF_DN = 262144.f;          // 2^18

    const dim3 gQKV(NQKV / 128, TS / 64);   // (18, 64) = 1152 CTAs
    const dim3 gAttn(DD / 128, TS / 64);    // (6, 64)  = 384 CTAs
    const dim3 gUp(FFD / 64, TS / 128);     // (48, 32)
    const dim3 gDn(DD / 64, TS / 128);      // (12, 32)
    const dim3 gT(DD / 32, SS / 32);
    const dim3 bT(32, 8);

    // 0) weight prep
    k_cat_qkv<<<(DD * NQKV + 255) / 256, 256>>>(wq, wk, wv);
    k_prep_w_s8<<<(DD * FFD + 255) / 256, 256>>>(w1, w1T, DD, FFD, 4, SF_UP);
    k_prep_w_s8<<<(DD * FFD + 255) / 256, 256>>>(w2, w2T, FFD, DD, 2, SF_DN);

    // 1) tmp = IF(x), column-major fp32 spikes
    k_if_input_T<<<gT, bT>>>(x);
    // 2) merged QKV pre-BN GEMM (bitwise ascending-k fp32 chain)
    k_sgemm_f32<<<gQKV, 128, SGEMM_SMEM>>>(tmpsT, wqkv, qkv, NQKV, DD);
    // 3) BN + IF -> fp32 spikes (strided reads from merged buffer)
    k_bn_if<0, DD, float><<<SS, 256>>>(qkv,            NQKV, nullptr, nullptr, qs);
    k_bn_if<0, DD, float><<<SS, 256>>>(qkv + DD,       NQKV, nullptr, nullptr, ks);
    k_bn_if<0, DD, float><<<SS, 256>>>(qkv + 2 * DD,   NQKV, nullptr, nullptr, vs);
    // 4) QK column-sums + talking-heads IF; masked-V transpose
    k_qk_partial<<<dim3(3, 8, 4), 256>>>();
    k_qk_if<<<3, 256>>>();
    k_vmask_T<<<gT, bT>>>();
    // 5) attn GEMM
    k_sgemm_f32<<<gAttn, 128, SGEMM_SMEM>>>(vmT, wo, go, DD, DD);
    // 6) h = x + BN(go); f = IF(h) -> s8 spikes
    k_bn_if<1, DD, int8_t><<<SS, 256>>>(go, DD, x, h, fs);
    // 7) FFN up (IMMA s8, 4 digit planes)
    k_imma_gemm<DD, 4><<<gUp, 256, IMMA_SMEM>>>(fs, w1T, b1, g1, FFD, 1.f / SF_UP);
    // 8) BN + IF -> s8 spikes
    k_bn_if<0, FFD, int8_t><<<SS, 256>>>(g1, FFD, nullptr, nullptr, g1s);
    // 9) FFN down (IMMA s8, 2 digit planes)
    k_imma_gemm<FFD, 2><<<gDn, 256, IMMA_SMEM>>>(g1s, w2T, b2, g2, DD, 1.f / SF_DN);
    // 10) out = h + BN(g2)
    k_bn_if<2, DD, float><<<SS, 256>>>(g2, DD, h, out, nullptr);
}

// round 11
// speedup vs baseline: 2.4451x; 1.0688x over previous
#include <cuda_runtime.h>
#include <cuda_bf16.h>
#include <cstdint>

// Shapes (fixed)
#define TT  4
#define SS  1024
#define DD  768
#define FFD 3072
#define TS  4096          // TT*SS
#define EPSf 1e-5f
#define NQKV 2304         // 3*DD merged QKV output width

// ---------------- scratch (device globals; no allocs allowed) ----------------
__device__ float g_qkv[(size_t)TS*NQKV];   // merged QKV pre-BN
__device__ float g_go [TS*DD];
__device__ float g_h  [TS*DD];
__device__ float g_g1 [TS*FFD];
__device__ float g_g2 [TS*DD];
__device__ float g_qkp[8*TT*DD];
__device__ float g_qks[TT*DD];
// fp32 spikes (bitwise path)
__device__ float g_qs [TS*DD];
__device__ float g_ks [TS*DD];
__device__ float g_vs [TS*DD];
// column-major fp32 A operand for QKV SGEMM: [K][TS]
__device__ __align__(128) float g_tmpsT[DD*TS];
// concatenated QKV weights [K][2304]
__device__ __align__(128) float g_wqkv[(size_t)DD*NQKV];
// s8 spikes for IMMA paths (row-major)
__device__ __align__(128) int8_t g_vms[TS*DD];     // V*QK mask spikes
__device__ __align__(128) int8_t g_fs [TS*DD];
__device__ __align__(128) int8_t g_g1s[TS*FFD];
// s8 digit-plane weights: Wt[n][plane*K + k], msb plane first
__device__ __align__(128) int8_t g_woT[(size_t)DD*4*DD];
__device__ __align__(128) int8_t g_w1T[(size_t)FFD*4*DD];
__device__ __align__(128) int8_t g_w2T[(size_t)DD*2*FFD];

// ---------------- PTX helpers ------------------------------------------------
__device__ __forceinline__ uint32_t smem_u32(const void* p) {
    uint32_t a;
    asm("{ .reg .u64 t; cvta.to.shared.u64 t, %1; cvt.u32.u64 %0, t; }" : "=r"(a) : "l"(p));
    return a;
}
__device__ __forceinline__ void cp16(uint32_t dst, const void* src) {
    asm volatile("cp.async.cg.shared.global [%0], [%1], 16;" :: "r"(dst), "l"(src));
}
__device__ __forceinline__ void cp_commit() {
    asm volatile("cp.async.commit_group;" ::: "memory");
}
template<int N> __device__ __forceinline__ void cp_wait() {
    asm volatile("cp.async.wait_group %0;" :: "n"(N) : "memory");
}
__device__ __forceinline__ void ldm_x4(uint32_t& r0, uint32_t& r1, uint32_t& r2, uint32_t& r3,
                                       uint32_t addr) {
    asm volatile("ldmatrix.sync.aligned.m8n8.x4.shared.b16 {%0,%1,%2,%3}, [%4];"
                 : "=r"(r0), "=r"(r1), "=r"(r2), "=r"(r3) : "r"(addr));
}
__device__ __forceinline__ void mma_s8(int* d, uint32_t a0, uint32_t a1, uint32_t a2,
                                       uint32_t a3, uint32_t b0, uint32_t b1) {
    asm volatile(
        "mma.sync.aligned.m16n8k32.row.col.s32.s8.s8.s32 "
        "{%0,%1,%2,%3}, {%4,%5,%6,%7}, {%8,%9}, {%0,%1,%2,%3};"
        : "+r"(d[0]), "+r"(d[1]), "+r"(d[2]), "+r"(d[3])
        : "r"(a0), "r"(a1), "r"(a2), "r"(a3), "r"(b0), "r"(b1));
}
// packed fp32x2; lane-wise fma.rn == scalar FFMA bitwise
__device__ __forceinline__ unsigned long long pk2(float lo, float hi) {
    unsigned long long r;
    asm("mov.b64 %0, {%1, %2};" : "=l"(r) : "f"(lo), "f"(hi));
    return r;
}
__device__ __forceinline__ void fma2(unsigned long long& d, unsigned long long a,
                                     unsigned long long b) {
    asm("fma.rn.f32x2 %0, %1, %2, %0;" : "+l"(d) : "l"(a), "l"(b));
}

// =============================================================================
// fp32 SGEMM, bitwise ascending-k FFMA chain per output, packed f32x2 math.
// (QKV path only: Q/K/V spike decisions require this exact accumulation.)
// C[4096,N] = A[4096,K] @ W[K,N], A column-major AT[K][4096].
// 64x128 tile, 128 threads, 8x8 microtile, BK=16, 3-stage cp.async.
// =============================================================================
#define A_F   (16*68)
#define B_F   (16*132)
#define STG_F (A_F + B_F)
#define SGEMM_SMEM (3*STG_F*4)

__global__ void __launch_bounds__(128, 4) k_sgemm_f32(
    const float* __restrict__ AT, const float* __restrict__ W,
    float* __restrict__ C, int N, int K)
{
    extern __shared__ float smem[];
    const int tid = threadIdx.x;
    const int ty = tid >> 4, tx = tid & 15;
    const int rowBase = blockIdx.y * 64;
    const int colBase = blockIdx.x * 128;
    const int NC = K >> 4;
    const uint32_t sb = smem_u32(smem);
    const int kr = tid >> 3;
    const int lg = tid & 7;

#define PREFETCH(c) do {                                                        \
        const int st_ = (c) % 3;                                                \
        const uint32_t sa_  = sb + (st_ * STG_F + kr * 68 + lg * 8) * 4;        \
        const uint32_t sbB_ = sb + (st_ * STG_F + A_F + kr * 132 + lg * 16) * 4; \
        const float* as_ = AT + (size_t)((c) * 16 + kr) * TS + rowBase + lg * 8; \
        const float* bs_ = W + (size_t)((c) * 16 + kr) * N + colBase + lg * 16;  \
        cp16(sa_, as_);        cp16(sa_ + 16, as_ + 4);                         \
        cp16(sbB_, bs_);       cp16(sbB_ + 16, bs_ + 4);                        \
        cp16(sbB_ + 32, bs_ + 8); cp16(sbB_ + 48, bs_ + 12);                    \
        cp_commit();                                                            \
    } while (0)

    unsigned long long acc2[8][4];
    #pragma unroll
    for (int i = 0; i < 8; i++)
        #pragma unroll
        for (int j = 0; j < 4; j++) acc2[i][j] = 0ull;

    PREFETCH(0);
    PREFETCH(1);

    for (int c = 0; c < NC; c++) {
        cp_wait<1>();
        __syncthreads();
        if (c + 2 < NC) PREFETCH(c + 2); else cp_commit();
        const float* As = smem + (c % 3) * STG_F;
        const float* Bs = As + A_F;
        #pragma unroll
        for (int kk = 0; kk < 16; kk++) {
            float4 a0 = *(const float4*)&As[kk * 68 + ty * 8];
            float4 a1 = *(const float4*)&As[kk * 68 + ty * 8 + 4];
            float4 b0 = *(const float4*)&Bs[kk * 132 + tx * 8];
            float4 b1 = *(const float4*)&Bs[kk * 132 + tx * 8 + 4];
            unsigned long long bp[4] = { pk2(b0.x, b0.y), pk2(b0.z, b0.w),
                                         pk2(b1.x, b1.y), pk2(b1.z, b1.w) };
            unsigned long long ad[8] = { pk2(a0.x, a0.x), pk2(a0.y, a0.y),
                                         pk2(a0.z, a0.z), pk2(a0.w, a0.w),
                                         pk2(a1.x, a1.x), pk2(a1.y, a1.y),
                                         pk2(a1.z, a1.z), pk2(a1.w, a1.w) };
            #pragma unroll
            for (int i = 0; i < 8; i++)
                #pragma unroll
                for (int j = 0; j < 4; j++)
                    fma2(acc2[i][j], ad[i], bp[j]);
        }
    }
#undef PREFETCH

    #pragma unroll
    for (int i = 0; i < 8; i++) {
        const int row = rowBase + ty * 8 + i;
        ulonglong2 u0 = { acc2[i][0], acc2[i][1] };
        ulonglong2 u1 = { acc2[i][2], acc2[i][3] };
        *(ulonglong2*)(C + (size_t)row * N + colBase + tx * 8) = u0;
        *(ulonglong2*)(C + (size_t)row * N + colBase + tx * 8 + 4) = u1;
    }
}

// =============================================================================
// IMMA s8 GEMM: C = (A @ digit-planes of W) folded, + bias.
// A: s8 binary spikes [4096, KA] row-major. Wt: s8 [N][NP*KA], msb plane first.
// Exact s32 per-plane accumulation; fold facc = facc*256 + iacc per plane.
// =============================================================================
#define ISTRIDE 80
#define IA_TILE (128*ISTRIDE)
#define IB_TILE (64*ISTRIDE)
#define ISTG    (IA_TILE + IB_TILE)
#define IMMA_SMEM (3*ISTG)

template<int KA, int NP>
__global__ void __launch_bounds__(256, 2) k_imma_gemm(
    const int8_t* __restrict__ A, const int8_t* __restrict__ Wt,
    const float* __restrict__ bias, float* __restrict__ C, int N, float invSF)
{
    constexpr int NCA = KA / 64;
    constexpr int NC = NCA * NP;
    extern __shared__ __align__(16) char smem_i[];
    const int tid = threadIdx.x, lane = tid & 31, wid = tid >> 5;
    const int wm = wid >> 1, wn = wid & 1;
    const int rowBase = blockIdx.y * 128, colBase = blockIdx.x * 64;
    const uint32_t sb = smem_u32(smem_i);

    const int lrA = tid >> 1, lcA = (tid & 1) * 32;
    const int8_t* Ag = A + (size_t)(rowBase + lrA) * KA + lcA;
    const uint32_t sdA = sb + lrA * ISTRIDE + lcA;
    const int lrB = tid >> 2, lcB = (tid & 3) * 16;
    const int8_t* Bg = Wt + (size_t)(colBase + lrB) * (NP * KA) + lcB;
    const uint32_t sdB = sb + IA_TILE + lrB * ISTRIDE + lcB;

#define IPRE(c) do {                                                           \
        const uint32_t so_ = ((c) % 3) * ISTG;                                 \
        const int8_t* as_ = Ag + ((c) % NCA) * 64;                             \
        const int8_t* bs_ = Bg + (size_t)(c) * 64;                             \
        cp16(sdA + so_, as_);      cp16(sdA + so_ + 16, as_ + 16);             \
        cp16(sdB + so_, bs_);                                                  \
        cp_commit();                                                           \
    } while (0)

    const uint32_t aBase = sb + (wm * 32 + (lane & 15)) * ISTRIDE + (lane >> 4) * 16;
    const int bn_local = (lane & 7) + ((lane >> 4) & 1) * 8;
    const uint32_t bBase = sb + IA_TILE + (wn * 32 + bn_local) * ISTRIDE + ((lane >> 3) & 1) * 16;

    int   iacc[2][4][4];
    float facc[2][4][4];
    #pragma unroll
    for (int i = 0; i < 2; i++)
        #pragma unroll
        for (int j = 0; j < 4; j++)
            #pragma unroll
            for (int r = 0; r < 4; r++) { iacc[i][j][r] = 0; facc[i][j][r] = 0.f; }

    IPRE(0);
    IPRE(1);

    for (int c = 0; c < NC; c++) {
        cp_wait<1>();
        __syncthreads();
        if (c + 2 < NC) IPRE(c + 2); else cp_commit();
        const uint32_t so = (c % 3) * ISTG;
        #pragma unroll
        for (int ks = 0; ks < 2; ks++) {
            uint32_t a[2][4], b[2][4];
            #pragma unroll
            for (int mi = 0; mi < 2; mi++)
                ldm_x4(a[mi][0], a[mi][1], a[mi][2], a[mi][3],
                       aBase + so + mi * 16 * ISTRIDE + ks * 32);
            #pragma unroll
            for (int nj = 0; nj < 2; nj++)
                ldm_x4(b[nj][0], b[nj][1], b[nj][2], b[nj][3],
                       bBase + so + nj * 16 * ISTRIDE + ks * 32);
            #pragma unroll
            for (int mi = 0; mi < 2; mi++)
                #pragma unroll
                for (int ni = 0; ni < 4; ni++)
                    mma_s8(iacc[mi][ni], a[mi][0], a[mi][1], a[mi][2], a[mi][3],
                           b[ni >> 1][(ni & 1) * 2], b[ni >> 1][(ni & 1) * 2 + 1]);
        }
        if (((c + 1) % NCA) == 0) {
            #pragma unroll
            for (int mi = 0; mi < 2; mi++)
                #pragma unroll
                for (int ni = 0; ni < 4; ni++)
                    #pragma unroll
                    for (int r = 0; r < 4; r++) {
                        facc[mi][ni][r] = facc[mi][ni][r] * 256.f + (float)iacc[mi][ni][r];
                        iacc[mi][ni][r] = 0;
                    }
        }
    }
#undef IPRE

    const int row0 = rowBase + wm * 32 + (lane >> 2);
    const int col0 = colBase + wn * 32 + (lane & 3) * 2;
    #pragma unroll
    for (int mi = 0; mi < 2; mi++) {
        #pragma unroll
        for (int ni = 0; ni < 4; ni++) {
            const int r = row0 + mi * 16;
            const int cc = col0 + ni * 8;
            float b0 = 0.f, b1 = 0.f;
            if (bias) { b0 = bias[cc]; b1 = bias[cc + 1]; }
            float2 v0 = { facc[mi][ni][0] * invSF + b0, facc[mi][ni][1] * invSF + b1 };
            float2 v1 = { facc[mi][ni][2] * invSF + b0, facc[mi][ni][3] * invSF + b1 };
            *(float2*)(C + (size_t)r * N + cc) = v0;
            *(float2*)(C + (size_t)(r + 8) * N + cc) = v1;
        }
    }
}

// ---- weight prep: w[K,N] fp32 -> s8 digit planes Wt[N][NP*K], msb first -----
__global__ void k_prep_w_s8(const float* __restrict__ w, int8_t* __restrict__ wt,
                            int K, int N, int NP, float SF)
{
    int idx = blockIdx.x * 256 + threadIdx.x;
    if (idx >= N * K) return;
    int n = idx / K, k = idx - n * K;
    float v = w[(size_t)k * N + n];
    long long wi = llrintf(v * SF);
    int8_t dig[4];
    for (int p = 0; p < NP; p++) {
        int8_t d = (int8_t)(wi & 0xFF);
        dig[p] = d;
        wi = (wi - d) >> 8;
    }
    int8_t* base = wt + (size_t)n * NP * K + k;
    for (int q = 0; q < NP; q++)
        base[(size_t)q * K] = dig[NP - 1 - q];
}

// ---- concat wq|wk|wv into [K][2304] ----------------------------------------
__global__ void k_cat_qkv(const float* __restrict__ wq, const float* __restrict__ wk,
                          const float* __restrict__ wv)
{
    int idx = blockIdx.x * 256 + threadIdx.x;
    int k = idx / NQKV, j = idx - k * NQKV;
    float v;
    if (j < DD)            v = wq[(size_t)k * DD + j];
    else if (j < 2 * DD)   v = wk[(size_t)k * DD + j - DD];
    else                   v = wv[(size_t)k * DD + j - 2 * DD];
    g_wqkv[(size_t)k * NQKV + j] = v;
}

// ------- IF on input + transpose to column-major fp32 spikes -----------------
__global__ void k_if_input_T(const float* __restrict__ x)
{
    __shared__ float sm[TT][32][33];
    const int d0 = blockIdx.x * 32, s0 = blockIdx.y * 32;
    const int tx = threadIdx.x, tyy = threadIdx.y;
    #pragma unroll
    for (int i = 0; i < 4; i++) {
        const int sl = tyy + i * 8;
        const int s = s0 + sl;
        float v = 0.f;
        #pragma unroll
        for (int t = 0; t < TT; t++) {
            v += x[(size_t)(t * SS + s) * DD + d0 + tx];
            float sp = (v >= 1.f) ? 1.f : 0.f;
            sm[t][sl][tx] = sp;
            v *= (1.f - sp);
        }
    }
    __syncthreads();
    #pragma unroll
    for (int i = 0; i < 4; i++) {
        const int d = d0 + tyy + i * 8;
        #pragma unroll
        for (int t = 0; t < TT; t++)
            g_tmpsT[(size_t)d * TS + t * SS + s0 + tx] = sm[t][tx][tyy + i * 8];
    }
}

// ---------------- fused BatchNorm (per-s over T,DIM) + IF --------------------
// y has row stride ldy (supports reading a slice of the merged QKV buffer)
template<int MODE, int DIM, typename OBT>
__global__ void __launch_bounds__(256) k_bn_if(
    const float* __restrict__ y, int ldy, const float* __restrict__ res,
    float* __restrict__ of, OBT* __restrict__ ob)
{
    constexpr int CPT = DIM / 256;
    const int s = blockIdx.x, tid = threadIdx.x;
    float vals[TT][CPT];
    float sum = 0.f, sq = 0.f;
    #pragma unroll
    for (int c = 0; c < CPT; c++) {
        int d = tid + c * 256;
        #pragma unroll
        for (int t = 0; t < TT; t++) {
            float val = y[(size_t)(t * SS + s) * ldy + d];
            vals[t][c] = val;
            sum += val; sq += val * val;
        }
    }
    __shared__ float s1[256], s2[256];
    s1[tid] = sum; s2[tid] = sq;
    __syncthreads();
    for (int o = 128; o > 0; o >>= 1) {
        if (tid < o) { s1[tid] += s1[tid + o]; s2[tid] += s2[tid + o]; }
        __syncthreads();
    }
    const float invn = 1.f / (float)(TT * DIM);
    float mean = s1[0] * invn;
    float inv  = rsqrtf(s2[0] * invn - mean * mean + EPSf);
    #pragma unroll
    for (int c = 0; c < CPT; c++) {
        int d = tid + c * 256;
        float v = 0.f;
        #pragma unroll
        for (int t = 0; t < TT; t++) {
            size_t idx = (size_t)(t * SS + s) * DIM + d;
            float nv = (vals[t][c] - mean) * inv;
            if (MODE == 0) {
                v += nv;
                float sp = (v >= 1.f) ? 1.f : 0.f;
                ob[idx] = (OBT)sp;
                v *= (1.f - sp);
            } else if (MODE == 1) {
                float hh = res[idx] + nv;
                of[idx] = hh;
                v += hh;
                float sp = (v >= 1.f) ? 1.f : 0.f;
                ob[idx] = (OBT)sp;
                v *= (1.f - sp);
            } else {
                of[idx] = res[idx] + nv;
            }
        }
    }
}

// ---------------- QK column-sum (deterministic 2-phase) + IF over T ----------
__global__ void k_qk_partial()
{
    int d = blockIdx.x * 256 + threadIdx.x;
    int t = blockIdx.z;
    int chunk = blockIdx.y;
    size_t base = (size_t)(t * SS + chunk * 128) * DD + d;
    float acc = 0.f;
    #pragma unroll 4
    for (int i = 0; i < 128; i++)
        acc += g_qs[base + (size_t)i * DD] * g_ks[base + (size_t)i * DD];
    g_qkp[(chunk * TT + t) * DD + d] = acc;
}

__global__ void k_qk_if()
{
    int d = blockIdx.x * 256 + threadIdx.x;
    float v = 0.f;
    #pragma unroll
    for (int t = 0; t < TT; t++) {
        float s = 0.f;
        #pragma unroll
        for (int c = 0; c < 8; c++) s += g_qkp[(c * TT + t) * DD + d];
        v += s;
        float sp = (v >= 1.f) ? 1.f : 0.f;
        g_qks[t * DD + d] = sp;
        v *= (1.f - sp);
    }
}

// -------- vm = V_spike * QK_spike -> s8 row-major (IMMA A operand) -----------
__global__ void k_vmask_s8()
{
    int idx = blockIdx.x * 256 + threadIdx.x;   // over TS*DD
    int t = idx / (SS * DD);
    int d = idx % DD;
    g_vms[idx] = (int8_t)(g_vs[idx] * g_qks[t * DD + d]);
}

// ---------------- launch ------------------------------------------------------
extern "C" void kernel_launch(void* const* d_in, const int* in_sizes, int n_in,
                              void* d_out, int out_size)
{
    const float* x  = (const float*)d_in[0];
    const float* wq = (const float*)d_in[1];
    const float* wk = (const float*)d_in[2];
    const float* wv = (const float*)d_in[3];
    const float* wo = (const float*)d_in[4];
    const float* w1 = (const float*)d_in[5];
    const float* b1 = (const float*)d_in[6];
    const float* w2 = (const float*)d_in[7];
    const float* b2 = (const float*)d_in[8];
    float* out = (float*)d_out;

    float *qkv, *go, *h, *g1, *g2, *qs, *ks, *vs, *tmpsT, *wqkv;
    int8_t *vms, *fs, *g1s, *woT, *w1T, *w2T;
    cudaGetSymbolAddress((void**)&qkv, g_qkv);
    cudaGetSymbolAddress((void**)&go, g_go);     cudaGetSymbolAddress((void**)&h, g_h);
    cudaGetSymbolAddress((void**)&g1, g_g1);     cudaGetSymbolAddress((void**)&g2, g_g2);
    cudaGetSymbolAddress((void**)&qs, g_qs);     cudaGetSymbolAddress((void**)&ks, g_ks);
    cudaGetSymbolAddress((void**)&vs, g_vs);
    cudaGetSymbolAddress((void**)&tmpsT, g_tmpsT);
    cudaGetSymbolAddress((void**)&wqkv, g_wqkv);
    cudaGetSymbolAddress((void**)&vms, g_vms);
    cudaGetSymbolAddress((void**)&fs, g_fs);     cudaGetSymbolAddress((void**)&g1s, g_g1s);
    cudaGetSymbolAddress((void**)&woT, g_woT);
    cudaGetSymbolAddress((void**)&w1T, g_w1T);   cudaGetSymbolAddress((void**)&w2T, g_w2T);

    cudaFuncSetAttribute(k_sgemm_f32, cudaFuncAttributeMaxDynamicSharedMemorySize, SGEMM_SMEM);
    cudaFuncSetAttribute(k_imma_gemm<DD, 4>, cudaFuncAttributeMaxDynamicSharedMemorySize, IMMA_SMEM);
    cudaFuncSetAttribute(k_imma_gemm<FFD, 2>, cudaFuncAttributeMaxDynamicSharedMemorySize, IMMA_SMEM);

    const float SF_UP = 8589934592.f;      // 2^33
    const float SF_DN = 262144.f;          // 2^18

    const dim3 gQKV(NQKV / 128, TS / 64);   // (18, 64) = 1152 CTAs
    const dim3 gAttn(DD / 64, TS / 128);    // (12, 32) = 384 CTAs (IMMA)
    const dim3 gUp(FFD / 64, TS / 128);     // (48, 32)
    const dim3 gDn(DD / 64, TS / 128);      // (12, 32)
    const dim3 gT(DD / 32, SS / 32);
    const dim3 bT(32, 8);

    // 0) weight prep
    k_cat_qkv<<<(DD * NQKV + 255) / 256, 256>>>(wq, wk, wv);
    k_prep_w_s8<<<(DD * DD + 255) / 256, 256>>>(wo, woT, DD, DD, 4, SF_UP);
    k_prep_w_s8<<<(DD * FFD + 255) / 256, 256>>>(w1, w1T, DD, FFD, 4, SF_UP);
    k_prep_w_s8<<<(DD * FFD + 255) / 256, 256>>>(w2, w2T, FFD, DD, 2, SF_DN);

    // 1) tmp = IF(x), column-major fp32 spikes
    k_if_input_T<<<gT, bT>>>(x);
    // 2) merged QKV pre-BN GEMM (bitwise ascending-k fp32 chain)
    k_sgemm_f32<<<gQKV, 128, SGEMM_SMEM>>>(tmpsT, wqkv, qkv, NQKV, DD);
    // 3) BN + IF -> fp32 spikes (strided reads from merged buffer)
    k_bn_if<0, DD, float><<<SS, 256>>>(qkv,            NQKV, nullptr, nullptr, qs);
    k_bn_if<0, DD, float><<<SS, 256>>>(qkv + DD,       NQKV, nullptr, nullptr, ks);
    k_bn_if<0, DD, float><<<SS, 256>>>(qkv + 2 * DD,   NQKV, nullptr, nullptr, vs);
    // 4) QK column-sums + talking-heads IF; masked-V spikes (row-major s8)
    k_qk_partial<<<dim3(3, 8, 4), 256>>>();
    k_qk_if<<<3, 256>>>();
    k_vmask_s8<<<TS * DD / 256, 256>>>();
    // 5) attn GEMM via exact-integer IMMA (downstream has no QK-style amplifier)
    k_imma_gemm<DD, 4><<<gAttn, 256, IMMA_SMEM>>>(vms, woT, nullptr, go, DD, 1.f / SF_UP);
    // 6) h = x + BN(go); f = IF(h) -> s8 spikes
    k_bn_if<1, DD, int8_t><<<SS, 256>>>(go, DD, x, h, fs);
    // 7) FFN up (IMMA s8, 4 digit planes)
    k_imma_gemm<DD, 4><<<gUp, 256, IMMA_SMEM>>>(fs, w1T, b1, g1, FFD, 1.f / SF_UP);
    // 8) BN + IF -> s8 spikes
    k_bn_if<0, FFD, int8_t><<<SS, 256>>>(g1, FFD, nullptr, nullptr, g1s);
    // 9) FFN down (IMMA s8, 2 digit planes)
    k_imma_gemm<FFD, 2><<<gDn, 256, IMMA_SMEM>>>(g1s, w2T, b2, g2, DD, 1.f / SF_DN);
    // 10) out = h + BN(g2)
    k_bn_if<2, DD, float><<<SS, 256>>>(g2, DD, h, out, nullptr);
}

// round 12
// speedup vs baseline: 3.5317x; 1.4444x over previous
#include <cuda_runtime.h>
#include <cstdint>

// Shapes (fixed)
#define TT  4
#define SS  1024
#define DD  768
#define FFD 3072
#define TS  4096          // TT*SS
#define EPSf 1e-5f
#define NQKV 2304         // 3*DD merged QKV output width

// ---------------- scratch (device globals; no allocs allowed) ----------------
__device__ float g_qkv[(size_t)TS*NQKV];   // merged QKV pre-BN
__device__ float g_go [TS*DD];
__device__ float g_h  [TS*DD];
__device__ float g_g1 [TS*FFD];
__device__ float g_g2 [TS*DD];
__device__ float g_qkp[8*TT*DD];
__device__ float g_qks[TT*DD];
// fp32 spikes (QK integer path)
__device__ float g_qs [TS*DD];
__device__ float g_ks [TS*DD];
__device__ float g_vs [TS*DD];
// s8 spikes (IMMA A operands, row-major)
__device__ __align__(128) int8_t g_tmps[TS*DD];
__device__ __align__(128) int8_t g_vms [TS*DD];
__device__ __align__(128) int8_t g_fs  [TS*DD];
__device__ __align__(128) int8_t g_g1s [TS*FFD];
// s8 digit-plane weights: Wt[n][plane*K + k], msb plane first
__device__ __align__(128) int8_t g_wqkvT[(size_t)NQKV*3*DD];
__device__ __align__(128) int8_t g_woT  [(size_t)DD*3*DD];
__device__ __align__(128) int8_t g_w1T  [(size_t)FFD*3*DD];
__device__ __align__(128) int8_t g_w2T  [(size_t)DD*2*FFD];

// ---------------- PTX helpers ------------------------------------------------
__device__ __forceinline__ uint32_t smem_u32(const void* p) {
    uint32_t a;
    asm("{ .reg .u64 t; cvta.to.shared.u64 t, %1; cvt.u32.u64 %0, t; }" : "=r"(a) : "l"(p));
    return a;
}
__device__ __forceinline__ void cp16(uint32_t dst, const void* src) {
    asm volatile("cp.async.cg.shared.global [%0], [%1], 16;" :: "r"(dst), "l"(src));
}
__device__ __forceinline__ void cp_commit() {
    asm volatile("cp.async.commit_group;" ::: "memory");
}
template<int N> __device__ __forceinline__ void cp_wait() {
    asm volatile("cp.async.wait_group %0;" :: "n"(N) : "memory");
}
__device__ __forceinline__ void ldm_x4(uint32_t& r0, uint32_t& r1, uint32_t& r2, uint32_t& r3,
                                       uint32_t addr) {
    asm volatile("ldmatrix.sync.aligned.m8n8.x4.shared.b16 {%0,%1,%2,%3}, [%4];"
                 : "=r"(r0), "=r"(r1), "=r"(r2), "=r"(r3) : "r"(addr));
}
__device__ __forceinline__ void mma_s8(int* d, uint32_t a0, uint32_t a1, uint32_t a2,
                                       uint32_t a3, uint32_t b0, uint32_t b1) {
    asm volatile(
        "mma.sync.aligned.m16n8k32.row.col.s32.s8.s8.s32 "
        "{%0,%1,%2,%3}, {%4,%5,%6,%7}, {%8,%9}, {%0,%1,%2,%3};"
        : "+r"(d[0]), "+r"(d[1]), "+r"(d[2]), "+r"(d[3])
        : "r"(a0), "r"(a1), "r"(a2), "r"(a3), "r"(b0), "r"(b1));
}

// =============================================================================
// IMMA s8 GEMM: C = (A @ digit-planes of W), exact-integer fold, + bias.
// A: s8 binary spikes [4096, KA] row-major. Wt: s8 [N][NP*KA], msb plane first.
// Per-plane s32 mma accumulation is exact; plane fold ifold = ifold*256 + iacc
// is exact in s32 (|w_int| column sums < 2^31 by construction of SF).
// Epilogue converts via double (ifold < 2^53 exact) -> one fp32 rounding.
// CTA tile 128x64, warp 32x32, BK=64 s8, 3-stage cp.async.
// =============================================================================
#define ISTRIDE 80
#define IA_TILE (128*ISTRIDE)
#define IB_TILE (64*ISTRIDE)
#define ISTG    (IA_TILE + IB_TILE)
#define IMMA_SMEM (3*ISTG)

template<int KA, int NP>
__global__ void __launch_bounds__(256, 2) k_imma_gemm(
    const int8_t* __restrict__ A, const int8_t* __restrict__ Wt,
    const float* __restrict__ bias, float* __restrict__ C, int N, double invSF)
{
    constexpr int NCA = KA / 64;
    constexpr int NC = NCA * NP;
    extern __shared__ __align__(16) char smem_i[];
    const int tid = threadIdx.x, lane = tid & 31, wid = tid >> 5;
    const int wm = wid >> 1, wn = wid & 1;
    const int rowBase = blockIdx.y * 128, colBase = blockIdx.x * 64;
    const uint32_t sb = smem_u32(smem_i);

    const int lrA = tid >> 1, lcA = (tid & 1) * 32;
    const int8_t* Ag = A + (size_t)(rowBase + lrA) * KA + lcA;
    const uint32_t sdA = sb + lrA * ISTRIDE + lcA;
    const int lrB = tid >> 2, lcB = (tid & 3) * 16;
    const int8_t* Bg = Wt + (size_t)(colBase + lrB) * (NP * KA) + lcB;
    const uint32_t sdB = sb + IA_TILE + lrB * ISTRIDE + lcB;

#define IPRE(c) do {                                                           \
        const uint32_t so_ = ((c) % 3) * ISTG;                                 \
        const int8_t* as_ = Ag + ((c) % NCA) * 64;                             \
        const int8_t* bs_ = Bg + (size_t)(c) * 64;                             \
        cp16(sdA + so_, as_);      cp16(sdA + so_ + 16, as_ + 16);             \
        cp16(sdB + so_, bs_);                                                  \
        cp_commit();                                                           \
    } while (0)

    const uint32_t aBase = sb + (wm * 32 + (lane & 15)) * ISTRIDE + (lane >> 4) * 16;
    const int bn_local = (lane & 7) + ((lane >> 4) & 1) * 8;
    const uint32_t bBase = sb + IA_TILE + (wn * 32 + bn_local) * ISTRIDE + ((lane >> 3) & 1) * 16;

    int iacc [2][4][4];    // current digit plane (exact)
    int ifold[2][4][4];    // folded planes so far (exact)
    #pragma unroll
    for (int i = 0; i < 2; i++)
        #pragma unroll
        for (int j = 0; j < 4; j++)
            #pragma unroll
            for (int r = 0; r < 4; r++) { iacc[i][j][r] = 0; ifold[i][j][r] = 0; }

    IPRE(0);
    IPRE(1);

    for (int c = 0; c < NC; c++) {
        cp_wait<1>();
        __syncthreads();
        if (c + 2 < NC) IPRE(c + 2); else cp_commit();
        const uint32_t so = (c % 3) * ISTG;
        #pragma unroll
        for (int ks = 0; ks < 2; ks++) {
            uint32_t a[2][4], b[2][4];
            #pragma unroll
            for (int mi = 0; mi < 2; mi++)
                ldm_x4(a[mi][0], a[mi][1], a[mi][2], a[mi][3],
                       aBase + so + mi * 16 * ISTRIDE + ks * 32);
            #pragma unroll
            for (int nj = 0; nj < 2; nj++)
                ldm_x4(b[nj][0], b[nj][1], b[nj][2], b[nj][3],
                       bBase + so + nj * 16 * ISTRIDE + ks * 32);
            #pragma unroll
            for (int mi = 0; mi < 2; mi++)
                #pragma unroll
                for (int ni = 0; ni < 4; ni++)
                    mma_s8(iacc[mi][ni], a[mi][0], a[mi][1], a[mi][2], a[mi][3],
                           b[ni >> 1][(ni & 1) * 2], b[ni >> 1][(ni & 1) * 2 + 1]);
        }
        if (((c + 1) % NCA) == 0) {      // plane boundary: exact integer fold
            #pragma unroll
            for (int mi = 0; mi < 2; mi++)
                #pragma unroll
                for (int ni = 0; ni < 4; ni++)
                    #pragma unroll
                    for (int r = 0; r < 4; r++) {
                        ifold[mi][ni][r] = ifold[mi][ni][r] * 256 + iacc[mi][ni][r];
                        iacc[mi][ni][r] = 0;
                    }
        }
    }
#undef IPRE

    const int row0 = rowBase + wm * 32 + (lane >> 2);
    const int col0 = colBase + wn * 32 + (lane & 3) * 2;
    #pragma unroll
    for (int mi = 0; mi < 2; mi++) {
        #pragma unroll
        for (int ni = 0; ni < 4; ni++) {
            const int r = row0 + mi * 16;
            const int cc = col0 + ni * 8;
            float b0 = 0.f, b1 = 0.f;
            if (bias) { b0 = bias[cc]; b1 = bias[cc + 1]; }
            float2 v0 = { (float)((double)ifold[mi][ni][0] * invSF) + b0,
                          (float)((double)ifold[mi][ni][1] * invSF) + b1 };
            float2 v1 = { (float)((double)ifold[mi][ni][2] * invSF) + b0,
                          (float)((double)ifold[mi][ni][3] * invSF) + b1 };
            *(float2*)(C + (size_t)r * N + cc) = v0;
            *(float2*)(C + (size_t)(r + 8) * N + cc) = v1;
        }
    }
}

// ---- weight prep: w[K,N] fp32 -> s8 digit planes Wt[N][NP*K], msb first -----
__global__ void k_prep_w_s8(const float* __restrict__ w, int8_t* __restrict__ wt,
                            int K, int N, int NP, float SF)
{
    int idx = blockIdx.x * 256 + threadIdx.x;
    if (idx >= N * K) return;
    int n = idx / K, k = idx - n * K;
    float v = w[(size_t)k * N + n];
    long long wi = llrintf(v * SF);
    int8_t dig[4];
    for (int p = 0; p < NP; p++) {
        int8_t d = (int8_t)(wi & 0xFF);
        dig[p] = d;
        wi = (wi - d) >> 8;
    }
    int8_t* base = wt + (size_t)n * NP * K + k;
    for (int q = 0; q < NP; q++)
        base[(size_t)q * K] = dig[NP - 1 - q];
}

// ------- IF on input -> s8 row-major binary spikes ---------------------------
__global__ void k_if_input(const float* __restrict__ x)
{
    int idx = blockIdx.x * 256 + threadIdx.x;   // over SS*DD
    float v = 0.f;
    #pragma unroll
    for (int t = 0; t < TT; t++) {
        v += x[(size_t)t * SS * DD + idx];
        float sp = (v >= 1.f) ? 1.f : 0.f;
        g_tmps[(size_t)t * SS * DD + idx] = (int8_t)sp;
        v *= (1.f - sp);
    }
}

// ---------------- fused BatchNorm (per-s over T,DIM) + IF --------------------
// y has row stride ldy (supports reading a slice of the merged QKV buffer)
template<int MODE, int DIM, typename OBT>
__global__ void __launch_bounds__(256) k_bn_if(
    const float* __restrict__ y, int ldy, const float* __restrict__ res,
    float* __restrict__ of, OBT* __restrict__ ob)
{
    constexpr int CPT = DIM / 256;
    const int s = blockIdx.x, tid = threadIdx.x;
    float vals[TT][CPT];
    float sum = 0.f, sq = 0.f;
    #pragma unroll
    for (int c = 0; c < CPT; c++) {
        int d = tid + c * 256;
        #pragma unroll
        for (int t = 0; t < TT; t++) {
            float val = y[(size_t)(t * SS + s) * ldy + d];
            vals[t][c] = val;
            sum += val; sq += val * val;
        }
    }
    __shared__ float s1[256], s2[256];
    s1[tid] = sum; s2[tid] = sq;
    __syncthreads();
    for (int o = 128; o > 0; o >>= 1) {
        if (tid < o) { s1[tid] += s1[tid + o]; s2[tid] += s2[tid + o]; }
        __syncthreads();
    }
    const float invn = 1.f / (float)(TT * DIM);
    float mean = s1[0] * invn;
    float inv  = rsqrtf(s2[0] * invn - mean * mean + EPSf);
    #pragma unroll
    for (int c = 0; c < CPT; c++) {
        int d = tid + c * 256;
        float v = 0.f;
        #pragma unroll
        for (int t = 0; t < TT; t++) {
            size_t idx = (size_t)(t * SS + s) * DIM + d;
            float nv = (vals[t][c] - mean) * inv;
            if (MODE == 0) {
                v += nv;
                float sp = (v >= 1.f) ? 1.f : 0.f;
                ob[idx] = (OBT)sp;
                v *= (1.f - sp);
            } else if (MODE == 1) {
                float hh = res[idx] + nv;
                of[idx] = hh;
                v += hh;
                float sp = (v >= 1.f) ? 1.f : 0.f;
                ob[idx] = (OBT)sp;
                v *= (1.f - sp);
            } else {
                of[idx] = res[idx] + nv;
            }
        }
    }
}

// ---------------- QK column-sum (deterministic 2-phase) + IF over T ----------
__global__ void k_qk_partial()
{
    int d = blockIdx.x * 256 + threadIdx.x;
    int t = blockIdx.z;
    int chunk = blockIdx.y;
    size_t base = (size_t)(t * SS + chunk * 128) * DD + d;
    float acc = 0.f;
    #pragma unroll 4
    for (int i = 0; i < 128; i++)
        acc += g_qs[base + (size_t)i * DD] * g_ks[base + (size_t)i * DD];
    g_qkp[(chunk * TT + t) * DD + d] = acc;
}

__global__ void k_qk_if()
{
    int d = blockIdx.x * 256 + threadIdx.x;
    float v = 0.f;
    #pragma unroll
    for (int t = 0; t < TT; t++) {
        float s = 0.f;
        #pragma unroll
        for (int c = 0; c < 8; c++) s += g_qkp[(c * TT + t) * DD + d];
        v += s;
        float sp = (v >= 1.f) ? 1.f : 0.f;
        g_qks[t * DD + d] = sp;
        v *= (1.f - sp);
    }
}

// -------- vm = V_spike * QK_spike -> s8 row-major (IMMA A operand) -----------
__global__ void k_vmask_s8()
{
    int idx = blockIdx.x * 256 + threadIdx.x;   // over TS*DD
    int t = idx / (SS * DD);
    int d = idx % DD;
    g_vms[idx] = (int8_t)(g_vs[idx] * g_qks[t * DD + d]);
}

// ---------------- launch ------------------------------------------------------
extern "C" void kernel_launch(void* const* d_in, const int* in_sizes, int n_in,
                              void* d_out, int out_size)
{
    const float* x  = (const float*)d_in[0];
    const float* wq = (const float*)d_in[1];
    const float* wk = (const float*)d_in[2];
    const float* wv = (const float*)d_in[3];
    const float* wo = (const float*)d_in[4];
    const float* w1 = (const float*)d_in[5];
    const float* b1 = (const float*)d_in[6];
    const float* w2 = (const float*)d_in[7];
    const float* b2 = (const float*)d_in[8];
    float* out = (float*)d_out;

    float *qkv, *go, *h, *g1, *g2, *qs, *ks, *vs;
    int8_t *tmps, *vms, *fs, *g1s, *wqkvT, *woT, *w1T, *w2T;
    cudaGetSymbolAddress((void**)&qkv, g_qkv);
    cudaGetSymbolAddress((void**)&go, g_go);     cudaGetSymbolAddress((void**)&h, g_h);
    cudaGetSymbolAddress((void**)&g1, g_g1);     cudaGetSymbolAddress((void**)&g2, g_g2);
    cudaGetSymbolAddress((void**)&qs, g_qs);     cudaGetSymbolAddress((void**)&ks, g_ks);
    cudaGetSymbolAddress((void**)&vs, g_vs);
    cudaGetSymbolAddress((void**)&tmps, g_tmps);
    cudaGetSymbolAddress((void**)&vms, g_vms);
    cudaGetSymbolAddress((void**)&fs, g_fs);     cudaGetSymbolAddress((void**)&g1s, g_g1s);
    cudaGetSymbolAddress((void**)&wqkvT, g_wqkvT);
    cudaGetSymbolAddress((void**)&woT, g_woT);
    cudaGetSymbolAddress((void**)&w1T, g_w1T);   cudaGetSymbolAddress((void**)&w2T, g_w2T);

    cudaFuncSetAttribute(k_imma_gemm<DD, 3>, cudaFuncAttributeMaxDynamicSharedMemorySize, IMMA_SMEM);
    cudaFuncSetAttribute(k_imma_gemm<FFD, 2>, cudaFuncAttributeMaxDynamicSharedMemorySize, IMMA_SMEM);

    const float  SF3  = 16777216.f;        // 2^24 (3 digit planes)
    const double IS3  = 1.0 / 16777216.0;
    const float  SF2  = 262144.f;          // 2^18 (2 digit planes)
    const double IS2  = 1.0 / 262144.0;

    const dim3 gQKV(NQKV / 64, TS / 128);   // (36, 32) = 1152 CTAs
    const dim3 gAttn(DD / 64, TS / 128);    // (12, 32)
    const dim3 gUp(FFD / 64, TS / 128);     // (48, 32)
    const dim3 gDn(DD / 64, TS / 128);      // (12, 32)

    // 0) weight prep: s8 digit planes (QKV planes stored as 3 row-blocks)
    k_prep_w_s8<<<(DD * DD + 255) / 256, 256>>>(wq, wqkvT,                       DD, DD, 3, SF3);
    k_prep_w_s8<<<(DD * DD + 255) / 256, 256>>>(wk, wqkvT + (size_t)DD * 3 * DD, DD, DD, 3, SF3);
    k_prep_w_s8<<<(DD * DD + 255) / 256, 256>>>(wv, wqkvT + (size_t)2 * DD * 3 * DD, DD, DD, 3, SF3);
    k_prep_w_s8<<<(DD * DD + 255) / 256, 256>>>(wo, woT, DD, DD, 3, SF3);
    k_prep_w_s8<<<(DD * FFD + 255) / 256, 256>>>(w1, w1T, DD, FFD, 3, SF3);
    k_prep_w_s8<<<(DD * FFD + 255) / 256, 256>>>(w2, w2T, FFD, DD, 2, SF2);

    // 1) tmp = IF(x) -> s8 row-major spikes
    k_if_input<<<SS * DD / 256, 256>>>(x);
    // 2) merged QKV pre-BN GEMM (exact-integer IMMA)
    k_imma_gemm<DD, 3><<<gQKV, 256, IMMA_SMEM>>>(tmps, wqkvT, nullptr, qkv, NQKV, IS3);
    // 3) BN + IF -> fp32 spikes (strided reads from merged buffer)
    k_bn_if<0, DD, float><<<SS, 256>>>(qkv,          NQKV, nullptr, nullptr, qs);
    k_bn_if<0, DD, float><<<SS, 256>>>(qkv + DD,     NQKV, nullptr, nullptr, ks);
    k_bn_if<0, DD, float><<<SS, 256>>>(qkv + 2 * DD, NQKV, nullptr, nullptr, vs);
    // 4) QK column-sums (exact integers) + talking-heads IF; masked-V s8
    k_qk_partial<<<dim3(3, 8, 4), 256>>>();
    k_qk_if<<<3, 256>>>();
    k_vmask_s8<<<TS * DD / 256, 256>>>();
    // 5) attn GEMM (exact-integer IMMA)
    k_imma_gemm<DD, 3><<<gAttn, 256, IMMA_SMEM>>>(vms, woT, nullptr, go, DD, IS3);
    // 6) h = x + BN(go); f = IF(h) -> s8 spikes
    k_bn_if<1, DD, int8_t><<<SS, 256>>>(go, DD, x, h, fs);
    // 7) FFN up (exact-integer IMMA, 3 planes)
    k_imma_gemm<DD, 3><<<gUp, 256, IMMA_SMEM>>>(fs, w1T, b1, g1, FFD, IS3);
    // 8) BN + IF -> s8 spikes
    k_bn_if<0, FFD, int8_t><<<SS, 256>>>(g1, FFD, nullptr, nullptr, g1s);
    // 9) FFN down (exact-integer IMMA, 2 planes)
    k_imma_gemm<FFD, 2><<<gDn, 256, IMMA_SMEM>>>(g1s, w2T, b2, g2, DD, IS2);
    // 10) out = h + BN(g2)
    k_bn_if<2, DD, float><<<SS, 256>>>(g2, DD, h, out, nullptr);
}

// round 13
// speedup vs baseline: 3.6554x; 1.0350x over previous
#include <cuda_runtime.h>
#include <cstdint>

// Shapes (fixed)
#define TT  4
#define SS  1024
#define DD  768
#define FFD 3072
#define TS  4096          // TT*SS
#define EPSf 1e-5f
#define NQKV 2304         // 3*DD merged QKV output width

// ---------------- scratch (device globals; no allocs allowed) ----------------
__device__ float g_qkv[(size_t)TS*NQKV];   // merged QKV pre-BN
__device__ float g_go [TS*DD];
__device__ float g_h  [TS*DD];
__device__ float g_g1 [TS*FFD];
__device__ float g_g2 [TS*DD];
__device__ int   g_qkp[8*TT*DD];           // integer partial QK sums
__device__ int8_t g_qks[TT*DD];            // talking-heads spikes
// s8 spikes
__device__ __align__(128) int8_t g_qs  [TS*DD];
__device__ __align__(128) int8_t g_ks  [TS*DD];
__device__ __align__(128) int8_t g_vs  [TS*DD];
__device__ __align__(128) int8_t g_tmps[TS*DD];
__device__ __align__(128) int8_t g_vms [TS*DD];
__device__ __align__(128) int8_t g_fs  [TS*DD];
__device__ __align__(128) int8_t g_g1s [TS*FFD];
// s8 digit-plane weights: Wt[n][plane*K + k], msb plane first
__device__ __align__(128) int8_t g_wqkvT[(size_t)NQKV*3*DD];
__device__ __align__(128) int8_t g_woT  [(size_t)DD*3*DD];
__device__ __align__(128) int8_t g_w1T  [(size_t)FFD*3*DD];
__device__ __align__(128) int8_t g_w2T  [(size_t)DD*2*FFD];

// ---------------- PTX helpers ------------------------------------------------
__device__ __forceinline__ uint32_t smem_u32(const void* p) {
    uint32_t a;
    asm("{ .reg .u64 t; cvta.to.shared.u64 t, %1; cvt.u32.u64 %0, t; }" : "=r"(a) : "l"(p));
    return a;
}
__device__ __forceinline__ void cp16(uint32_t dst, const void* src) {
    asm volatile("cp.async.cg.shared.global [%0], [%1], 16;" :: "r"(dst), "l"(src));
}
__device__ __forceinline__ void cp_commit() {
    asm volatile("cp.async.commit_group;" ::: "memory");
}
template<int N> __device__ __forceinline__ void cp_wait() {
    asm volatile("cp.async.wait_group %0;" :: "n"(N) : "memory");
}
__device__ __forceinline__ void ldm_x4(uint32_t& r0, uint32_t& r1, uint32_t& r2, uint32_t& r3,
                                       uint32_t addr) {
    asm volatile("ldmatrix.sync.aligned.m8n8.x4.shared.b16 {%0,%1,%2,%3}, [%4];"
                 : "=r"(r0), "=r"(r1), "=r"(r2), "=r"(r3) : "r"(addr));
}
__device__ __forceinline__ void mma_s8(int* d, uint32_t a0, uint32_t a1, uint32_t a2,
                                       uint32_t a3, uint32_t b0, uint32_t b1) {
    asm volatile(
        "mma.sync.aligned.m16n8k32.row.col.s32.s8.s8.s32 "
        "{%0,%1,%2,%3}, {%4,%5,%6,%7}, {%8,%9}, {%0,%1,%2,%3};"
        : "+r"(d[0]), "+r"(d[1]), "+r"(d[2]), "+r"(d[3])
        : "r"(a0), "r"(a1), "r"(a2), "r"(a3), "r"(b0), "r"(b1));
}

// =============================================================================
// IMMA s8 GEMM: C = (A @ digit-planes of W), exact-integer fold, + bias.
// A: s8 binary spikes [4096, KA] row-major. Wt: s8 [N][NP*KA], msb plane first.
// CTA tile 128x64, warp 32x32, BK=64 s8, 3-stage cp.async.
// =============================================================================
#define ISTRIDE 80
#define IA_TILE (128*ISTRIDE)
#define IB_TILE (64*ISTRIDE)
#define ISTG    (IA_TILE + IB_TILE)
#define IMMA_SMEM (3*ISTG)

template<int KA, int NP>
__global__ void __launch_bounds__(256, 2) k_imma_gemm(
    const int8_t* __restrict__ A, const int8_t* __restrict__ Wt,
    const float* __restrict__ bias, float* __restrict__ C, int N, double invSF)
{
    constexpr int NCA = KA / 64;
    constexpr int NC = NCA * NP;
    extern __shared__ __align__(16) char smem_i[];
    const int tid = threadIdx.x, lane = tid & 31, wid = tid >> 5;
    const int wm = wid >> 1, wn = wid & 1;
    const int rowBase = blockIdx.y * 128, colBase = blockIdx.x * 64;
    const uint32_t sb = smem_u32(smem_i);

    const int lrA = tid >> 1, lcA = (tid & 1) * 32;
    const int8_t* Ag = A + (size_t)(rowBase + lrA) * KA + lcA;
    const uint32_t sdA = sb + lrA * ISTRIDE + lcA;
    const int lrB = tid >> 2, lcB = (tid & 3) * 16;
    const int8_t* Bg = Wt + (size_t)(colBase + lrB) * (NP * KA) + lcB;
    const uint32_t sdB = sb + IA_TILE + lrB * ISTRIDE + lcB;

#define IPRE(c) do {                                                           \
        const uint32_t so_ = ((c) % 3) * ISTG;                                 \
        const int8_t* as_ = Ag + ((c) % NCA) * 64;                             \
        const int8_t* bs_ = Bg + (size_t)(c) * 64;                             \
        cp16(sdA + so_, as_);      cp16(sdA + so_ + 16, as_ + 16);             \
        cp16(sdB + so_, bs_);                                                  \
        cp_commit();                                                           \
    } while (0)

    const uint32_t aBase = sb + (wm * 32 + (lane & 15)) * ISTRIDE + (lane >> 4) * 16;
    const int bn_local = (lane & 7) + ((lane >> 4) & 1) * 8;
    const uint32_t bBase = sb + IA_TILE + (wn * 32 + bn_local) * ISTRIDE + ((lane >> 3) & 1) * 16;

    int iacc [2][4][4];
    int ifold[2][4][4];
    #pragma unroll
    for (int i = 0; i < 2; i++)
        #pragma unroll
        for (int j = 0; j < 4; j++)
            #pragma unroll
            for (int r = 0; r < 4; r++) { iacc[i][j][r] = 0; ifold[i][j][r] = 0; }

    IPRE(0);
    IPRE(1);

    for (int c = 0; c < NC; c++) {
        cp_wait<1>();
        __syncthreads();
        if (c + 2 < NC) IPRE(c + 2); else cp_commit();
        const uint32_t so = (c % 3) * ISTG;
        #pragma unroll
        for (int ks = 0; ks < 2; ks++) {
            uint32_t a[2][4], b[2][4];
            #pragma unroll
            for (int mi = 0; mi < 2; mi++)
                ldm_x4(a[mi][0], a[mi][1], a[mi][2], a[mi][3],
                       aBase + so + mi * 16 * ISTRIDE + ks * 32);
            #pragma unroll
            for (int nj = 0; nj < 2; nj++)
                ldm_x4(b[nj][0], b[nj][1], b[nj][2], b[nj][3],
                       bBase + so + nj * 16 * ISTRIDE + ks * 32);
            #pragma unroll
            for (int mi = 0; mi < 2; mi++)
                #pragma unroll
                for (int ni = 0; ni < 4; ni++)
                    mma_s8(iacc[mi][ni], a[mi][0], a[mi][1], a[mi][2], a[mi][3],
                           b[ni >> 1][(ni & 1) * 2], b[ni >> 1][(ni & 1) * 2 + 1]);
        }
        if (((c + 1) % NCA) == 0) {      // plane boundary: exact integer fold
            #pragma unroll
            for (int mi = 0; mi < 2; mi++)
                #pragma unroll
                for (int ni = 0; ni < 4; ni++)
                    #pragma unroll
                    for (int r = 0; r < 4; r++) {
                        ifold[mi][ni][r] = ifold[mi][ni][r] * 256 + iacc[mi][ni][r];
                        iacc[mi][ni][r] = 0;
                    }
        }
    }
#undef IPRE

    const int row0 = rowBase + wm * 32 + (lane >> 2);
    const int col0 = colBase + wn * 32 + (lane & 3) * 2;
    #pragma unroll
    for (int mi = 0; mi < 2; mi++) {
        #pragma unroll
        for (int ni = 0; ni < 4; ni++) {
            const int r = row0 + mi * 16;
            const int cc = col0 + ni * 8;
            float b0 = 0.f, b1 = 0.f;
            if (bias) { b0 = bias[cc]; b1 = bias[cc + 1]; }
            float2 v0 = { (float)((double)ifold[mi][ni][0] * invSF) + b0,
                          (float)((double)ifold[mi][ni][1] * invSF) + b1 };
            float2 v1 = { (float)((double)ifold[mi][ni][2] * invSF) + b0,
                          (float)((double)ifold[mi][ni][3] * invSF) + b1 };
            *(float2*)(C + (size_t)r * N + cc) = v0;
            *(float2*)(C + (size_t)(r + 8) * N + cc) = v1;
        }
    }
}

// ---- weight prep (coalesced, smem-tiled transpose): w[K,N] -> Wt[N][NP*K] ---
// grid (K/32, N/32), block (32, 8). Phase 1: coalesced fp32 reads across n.
// Phase 2: 32B s8 runs across k per (n, plane).
__global__ void k_prep_w_s8_t(const float* __restrict__ w, int8_t* __restrict__ wt,
                              int K, int N, int NP, float SF)
{
    __shared__ int8_t sm[3][32][33];
    const int k0 = blockIdx.x * 32, n0 = blockIdx.y * 32;
    const int tx = threadIdx.x, ty = threadIdx.y;
    #pragma unroll
    for (int i = 0; i < 4; i++) {
        const int kl = ty + i * 8;
        float v = w[(size_t)(k0 + kl) * N + n0 + tx];
        long long wi = llrintf(v * SF);
        for (int p = 0; p < NP; p++) {         // lsb-first digits
            int8_t d = (int8_t)(wi & 0xFF);
            wi = (wi - d) >> 8;
            sm[NP - 1 - p][kl][tx] = d;        // store msb plane at index 0
        }
    }
    __syncthreads();
    #pragma unroll
    for (int i = 0; i < 4; i++) {
        const int nl = ty + i * 8;
        int8_t* base = wt + (size_t)(n0 + nl) * NP * K + k0 + tx;
        for (int q = 0; q < NP; q++)
            base[(size_t)q * K] = sm[q][tx][nl];
    }
}

// ------- IF on input -> s8 row-major binary spikes ---------------------------
__global__ void k_if_input(const float* __restrict__ x)
{
    int idx = blockIdx.x * 256 + threadIdx.x;   // over SS*DD
    float v = 0.f;
    #pragma unroll
    for (int t = 0; t < TT; t++) {
        v += x[(size_t)t * SS * DD + idx];
        float sp = (v >= 1.f) ? 1.f : 0.f;
        g_tmps[(size_t)t * SS * DD + idx] = (int8_t)sp;
        v *= (1.f - sp);
    }
}

// ---------------- fused BatchNorm (per-s over T,DIM) + IF --------------------
// MODE 0: ob = IF(BN(y));  MODE 1: of = h = res+BN(y), ob = IF(h);
// MODE 2: of = res + BN(y).  y row stride ldy.
template<int MODE, int DIM, typename OBT>
__global__ void __launch_bounds__(256) k_bn_if(
    const float* __restrict__ y, int ldy, const float* __restrict__ res,
    float* __restrict__ of, OBT* __restrict__ ob)
{
    constexpr int CPT = DIM / 256;
    const int s = blockIdx.x, tid = threadIdx.x;
    float vals[TT][CPT];
    float sum = 0.f, sq = 0.f;
    #pragma unroll
    for (int c = 0; c < CPT; c++) {
        int d = tid + c * 256;
        #pragma unroll
        for (int t = 0; t < TT; t++) {
            float val = y[(size_t)(t * SS + s) * ldy + d];
            vals[t][c] = val;
            sum += val; sq += val * val;
        }
    }
    __shared__ float s1[256], s2[256];
    s1[tid] = sum; s2[tid] = sq;
    __syncthreads();
    for (int o = 128; o > 0; o >>= 1) {
        if (tid < o) { s1[tid] += s1[tid + o]; s2[tid] += s2[tid + o]; }
        __syncthreads();
    }
    const float invn = 1.f / (float)(TT * DIM);
    float mean = s1[0] * invn;
    float inv  = rsqrtf(s2[0] * invn - mean * mean + EPSf);
    #pragma unroll
    for (int c = 0; c < CPT; c++) {
        int d = tid + c * 256;
        float v = 0.f;
        #pragma unroll
        for (int t = 0; t < TT; t++) {
            size_t idx = (size_t)(t * SS + s) * DIM + d;
            float nv = (vals[t][c] - mean) * inv;
            if (MODE == 0) {
                v += nv;
                float sp = (v >= 1.f) ? 1.f : 0.f;
                ob[idx] = (OBT)sp;
                v *= (1.f - sp);
            } else if (MODE == 1) {
                float hh = res[idx] + nv;
                of[idx] = hh;
                v += hh;
                float sp = (v >= 1.f) ? 1.f : 0.f;
                ob[idx] = (OBT)sp;
                v *= (1.f - sp);
            } else {
                of[idx] = res[idx] + nv;
            }
        }
    }
}

// ---- fused QKV BN+IF: grid (SS, 3), slice picks Q/K/V -> s8 spikes ----------
__global__ void __launch_bounds__(256) k_bn_if_qkv(
    const float* __restrict__ qkv, int8_t* __restrict__ qs,
    int8_t* __restrict__ ks, int8_t* __restrict__ vs)
{
    constexpr int CPT = DD / 256;
    const int s = blockIdx.x, tid = threadIdx.x;
    const int slice = blockIdx.y;
    const float* y = qkv + slice * DD;
    int8_t* ob = (slice == 0) ? qs : (slice == 1) ? ks : vs;
    float vals[TT][CPT];
    float sum = 0.f, sq = 0.f;
    #pragma unroll
    for (int c = 0; c < CPT; c++) {
        int d = tid + c * 256;
        #pragma unroll
        for (int t = 0; t < TT; t++) {
            float val = y[(size_t)(t * SS + s) * NQKV + d];
            vals[t][c] = val;
            sum += val; sq += val * val;
        }
    }
    __shared__ float s1[256], s2[256];
    s1[tid] = sum; s2[tid] = sq;
    __syncthreads();
    for (int o = 128; o > 0; o >>= 1) {
        if (tid < o) { s1[tid] += s1[tid + o]; s2[tid] += s2[tid + o]; }
        __syncthreads();
    }
    const float invn = 1.f / (float)(TT * DD);
    float mean = s1[0] * invn;
    float inv  = rsqrtf(s2[0] * invn - mean * mean + EPSf);
    #pragma unroll
    for (int c = 0; c < CPT; c++) {
        int d = tid + c * 256;
        float v = 0.f;
        #pragma unroll
        for (int t = 0; t < TT; t++) {
            size_t idx = (size_t)(t * SS + s) * DD + d;
            float nv = (vals[t][c] - mean) * inv;
            v += nv;
            float sp = (v >= 1.f) ? 1.f : 0.f;
            ob[idx] = (int8_t)sp;
            v *= (1.f - sp);
        }
    }
}

// ---------------- QK column-sum (exact integers) + IF over T -----------------
__global__ void k_qk_partial()
{
    int d = blockIdx.x * 256 + threadIdx.x;
    int t = blockIdx.z;
    int chunk = blockIdx.y;
    size_t base = (size_t)(t * SS + chunk * 128) * DD + d;
    int acc = 0;
    #pragma unroll 4
    for (int i = 0; i < 128; i++)
        acc += (int)g_qs[base + (size_t)i * DD] * (int)g_ks[base + (size_t)i * DD];
    g_qkp[(chunk * TT + t) * DD + d] = acc;
}

__global__ void k_qk_if()
{
    int d = blockIdx.x * 256 + threadIdx.x;
    int v = 0;
    #pragma unroll
    for (int t = 0; t < TT; t++) {
        int s = 0;
        #pragma unroll
        for (int c = 0; c < 8; c++) s += g_qkp[(c * TT + t) * DD + d];
        v += s;
        int sp = (v >= 1) ? 1 : 0;
        g_qks[t * DD + d] = (int8_t)sp;
        v *= (1 - sp);
    }
}

// -------- vm = V_spike * QK_spike -> s8 row-major ----------------------------
__global__ void k_vmask_s8()
{
    int idx = blockIdx.x * 256 + threadIdx.x;   // over TS*DD
    int t = idx / (SS * DD);
    int d = idx % DD;
    g_vms[idx] = (int8_t)(g_vs[idx] & g_qks[t * DD + d]);
}

// ---------------- launch ------------------------------------------------------
extern "C" void kernel_launch(void* const* d_in, const int* in_sizes, int n_in,
                              void* d_out, int out_size)
{
    const float* x  = (const float*)d_in[0];
    const float* wq = (const float*)d_in[1];
    const float* wk = (const float*)d_in[2];
    const float* wv = (const float*)d_in[3];
    const float* wo = (const float*)d_in[4];
    const float* w1 = (const float*)d_in[5];
    const float* b1 = (const float*)d_in[6];
    const float* w2 = (const float*)d_in[7];
    const float* b2 = (const float*)d_in[8];
    float* out = (float*)d_out;

    float *qkv, *go, *h, *g1, *g2;
    int8_t *qs, *ks, *vs, *tmps, *vms, *fs, *g1s, *wqkvT, *woT, *w1T, *w2T;
    cudaGetSymbolAddress((void**)&qkv, g_qkv);
    cudaGetSymbolAddress((void**)&go, g_go);     cudaGetSymbolAddress((void**)&h, g_h);
    cudaGetSymbolAddress((void**)&g1, g_g1);     cudaGetSymbolAddress((void**)&g2, g_g2);
    cudaGetSymbolAddress((void**)&qs, g_qs);     cudaGetSymbolAddress((void**)&ks, g_ks);
    cudaGetSymbolAddress((void**)&vs, g_vs);
    cudaGetSymbolAddress((void**)&tmps, g_tmps);
    cudaGetSymbolAddress((void**)&vms, g_vms);
    cudaGetSymbolAddress((void**)&fs, g_fs);     cudaGetSymbolAddress((void**)&g1s, g_g1s);
    cudaGetSymbolAddress((void**)&wqkvT, g_wqkvT);
    cudaGetSymbolAddress((void**)&woT, g_woT);
    cudaGetSymbolAddress((void**)&w1T, g_w1T);   cudaGetSymbolAddress((void**)&w2T, g_w2T);

    cudaFuncSetAttribute(k_imma_gemm<DD, 3>, cudaFuncAttributeMaxDynamicSharedMemorySize, IMMA_SMEM);
    cudaFuncSetAttribute(k_imma_gemm<FFD, 2>, cudaFuncAttributeMaxDynamicSharedMemorySize, IMMA_SMEM);

    const float  SF3  = 16777216.f;        // 2^24 (3 digit planes)
    const double IS3  = 1.0 / 16777216.0;
    const float  SF2  = 262144.f;          // 2^18 (2 digit planes)
    const double IS2  = 1.0 / 262144.0;

    const dim3 gQKV(NQKV / 64, TS / 128);   // (36, 32) = 1152 CTAs
    const dim3 gAttn(DD / 64, TS / 128);    // (12, 32)
    const dim3 gUp(FFD / 64, TS / 128);     // (48, 32)
    const dim3 gDn(DD / 64, TS / 128);      // (12, 32)
    const dim3 bP(32, 8);

    // 0) weight prep: s8 digit planes (tiled transpose, coalesced)
    k_prep_w_s8_t<<<dim3(DD / 32, DD / 32), bP>>>(wq, wqkvT,                           DD, DD, 3, SF3);
    k_prep_w_s8_t<<<dim3(DD / 32, DD / 32), bP>>>(wk, wqkvT + (size_t)DD * 3 * DD,     DD, DD, 3, SF3);
    k_prep_w_s8_t<<<dim3(DD / 32, DD / 32), bP>>>(wv, wqkvT + (size_t)2 * DD * 3 * DD, DD, DD, 3, SF3);
    k_prep_w_s8_t<<<dim3(DD / 32, DD / 32), bP>>>(wo, woT, DD, DD, 3, SF3);
    k_prep_w_s8_t<<<dim3(DD / 32, FFD / 32), bP>>>(w1, w1T, DD, FFD, 3, SF3);
    k_prep_w_s8_t<<<dim3(FFD / 32, DD / 32), bP>>>(w2, w2T, FFD, DD, 2, SF2);

    // 1) tmp = IF(x) -> s8 row-major spikes
    k_if_input<<<SS * DD / 256, 256>>>(x);
    // 2) merged QKV pre-BN GEMM (exact-integer IMMA)
    k_imma_gemm<DD, 3><<<gQKV, 256, IMMA_SMEM>>>(tmps, wqkvT, nullptr, qkv, NQKV, IS3);
    // 3) fused BN + IF for Q/K/V -> s8 spikes
    k_bn_if_qkv<<<dim3(SS, 3), 256>>>(qkv, qs, ks, vs);
    // 4) QK integer column-sums + talking-heads IF; masked-V s8
    k_qk_partial<<<dim3(3, 8, 4), 256>>>();
    k_qk_if<<<3, 256>>>();
    k_vmask_s8<<<TS * DD / 256, 256>>>();
    // 5) attn GEMM (exact-integer IMMA)
    k_imma_gemm<DD, 3><<<gAttn, 256, IMMA_SMEM>>>(vms, woT, nullptr, go, DD, IS3);
    // 6) h = x + BN(go); f = IF(h) -> s8 spikes
    k_bn_if<1, DD, int8_t><<<SS, 256>>>(go, DD, x, h, fs);
    // 7) FFN up (exact-integer IMMA, 3 planes)
    k_imma_gemm<DD, 3><<<gUp, 256, IMMA_SMEM>>>(fs, w1T, b1, g1, FFD, IS3);
    // 8) BN + IF -> s8 spikes
    k_bn_if<0, FFD, int8_t><<<SS, 256>>>(g1, FFD, nullptr, nullptr, g1s);
    // 9) FFN down (exact-integer IMMA, 2 planes)
    k_imma_gemm<FFD, 2><<<gDn, 256, IMMA_SMEM>>>(g1s, w2T, b2, g2, DD, IS2);
    // 10) out = h + BN(g2)
    k_bn_if<2, DD, float><<<SS, 256>>>(g2, DD, h, out, nullptr);
}